// round 4
// baseline (speedup 1.0000x reference)
#include <cuda_runtime.h>
#include <math.h>
#include <cstdint>

// Problem constants
#define B_ 16
#define CDIM 256
#define H_ 128
#define W_ 128
#define NTOK 262144   // B*H*W tokens

// Scratch (device globals)
__device__ float g_tok[67108864];    // [NTOK, 256]
__device__ float g_y[67108864];      // [NTOK, 256]
__device__ float g_qkv[201326592];   // [NTOK, 768]
__device__ float g_o[67108864];      // [NTOK, 256]
__device__ float g_hid[268435456];   // [NTOK, 1024]

__device__ __forceinline__ uint32_t f32_tf32(float v) {
    uint32_t u;
    asm("cvt.rna.tf32.f32 %0, %1;" : "=r"(u) : "f"(v));
    return u;
}

__device__ __forceinline__ float gelu_exact(float v) {
    return 0.5f * v * (1.0f + erff(v * 0.70710678118654752f));
}

// ===========================================================================
// TF32 mma.sync GEMM, double-buffered software pipeline.
// Out[M,N] = A[M,K] * W[N,K]^T + bias (+ epilogue)
// CTA tile 128x128, K-chunk 32, 8 warps (warp tile 64x32).
// SMEM (dynamic 64KB): As[2][128*32], Bs[2][128*32], XOR swizzle.
// EPI: 0=bias, 1=bias+residual, 2=bias+GELU
// ===========================================================================
template <int EPI>
__global__ void __launch_bounds__(256) mma_gemm(const float* __restrict__ A,
                                                const float* __restrict__ W,
                                                const float* __restrict__ bias,
                                                const float* __restrict__ R,
                                                float* __restrict__ Out,
                                                int N, int K) {
    extern __shared__ uint32_t sm[];
    uint32_t* As = sm;              // [2][4096]
    uint32_t* Bs = sm + 8192;       // [2][4096]

    const int tid = threadIdx.x;
    const int wid = tid >> 5;
    const int lane = tid & 31;
    const long long m0 = (long long)blockIdx.x * 128;
    const int n0 = blockIdx.y * 128;

    const int wm = (wid >> 2) * 64;
    const int wn = (wid & 3) * 32;
    const int lm = lane >> 2;
    const int lk = lane & 3;

    // global load mapping: row gr = tid>>1, 16 cols starting at (tid&1)*16
    const int gr = tid >> 1;
    const int gc = (tid & 1) * 16;
    const int swr = (gr & 7) * 4;

    const float* arow = A + (m0 + gr) * (long long)K + gc;
    const float* brow = W + (long long)(n0 + gr) * K + gc;
    const int sbase = gr * 32;  // smem row base (u32 units)

    float d[4][4][4];
#pragma unroll
    for (int i = 0; i < 4; i++)
#pragma unroll
        for (int j = 0; j < 4; j++)
#pragma unroll
            for (int q = 0; q < 4; q++) d[i][j][q] = 0.0f;

    // ---- prologue: chunk 0 -> buffer 0 ----
    {
#pragma unroll
        for (int j = 0; j < 4; j++) {
            float4 va = *(const float4*)(arow + j * 4);
            float4 vb = *(const float4*)(brow + j * 4);
            uint4 ta, tb;
            ta.x = f32_tf32(va.x); ta.y = f32_tf32(va.y);
            ta.z = f32_tf32(va.z); ta.w = f32_tf32(va.w);
            tb.x = f32_tf32(vb.x); tb.y = f32_tf32(vb.y);
            tb.z = f32_tf32(vb.z); tb.w = f32_tf32(vb.w);
            const int c = (gc + j * 4) ^ swr;
            *(uint4*)&As[sbase + c] = ta;
            *(uint4*)&Bs[sbase + c] = tb;
        }
    }
    __syncthreads();

    const int KT = K >> 5;
    for (int kt = 0; kt < KT; kt++) {
        const int cur = (kt & 1) * 4096;
        float4 na[4], nb[4];
        const bool more = (kt + 1 < KT);
        if (more) {
            const int ko = (kt + 1) * 32;
#pragma unroll
            for (int j = 0; j < 4; j++) {
                na[j] = *(const float4*)(arow + ko + j * 4);
                nb[j] = *(const float4*)(brow + ko + j * 4);
            }
        }

        // ---- compute from current buffer ----
#pragma unroll
        for (int kk = 0; kk < 32; kk += 8) {
            uint32_t a[4][4];
#pragma unroll
            for (int mf = 0; mf < 4; mf++) {
                const int m = wm + mf * 16 + lm;
                const int sw = (m & 7) * 4;
                const int c0 = (kk + lk) ^ sw;
                const int c1 = (kk + 4 + lk) ^ sw;
                a[mf][0] = As[cur + m * 32 + c0];
                a[mf][1] = As[cur + (m + 8) * 32 + c0];
                a[mf][2] = As[cur + m * 32 + c1];
                a[mf][3] = As[cur + (m + 8) * 32 + c1];
            }
            uint32_t b[4][2];
#pragma unroll
            for (int nf = 0; nf < 4; nf++) {
                const int n = wn + nf * 8 + lm;
                const int sw = (n & 7) * 4;
                b[nf][0] = Bs[cur + n * 32 + ((kk + lk) ^ sw)];
                b[nf][1] = Bs[cur + n * 32 + ((kk + 4 + lk) ^ sw)];
            }
#pragma unroll
            for (int mf = 0; mf < 4; mf++)
#pragma unroll
                for (int nf = 0; nf < 4; nf++) {
                    asm volatile(
                        "mma.sync.aligned.m16n8k8.row.col.f32.tf32.tf32.f32 "
                        "{%0,%1,%2,%3}, {%4,%5,%6,%7}, {%8,%9}, {%0,%1,%2,%3};"
                        : "+f"(d[mf][nf][0]), "+f"(d[mf][nf][1]),
                          "+f"(d[mf][nf][2]), "+f"(d[mf][nf][3])
                        : "r"(a[mf][0]), "r"(a[mf][1]), "r"(a[mf][2]), "r"(a[mf][3]),
                          "r"(b[nf][0]), "r"(b[nf][1]));
                }
        }

        // ---- store next chunk into other buffer ----
        if (more) {
            const int nxt = ((kt + 1) & 1) * 4096;
#pragma unroll
            for (int j = 0; j < 4; j++) {
                uint4 ta, tb;
                ta.x = f32_tf32(na[j].x); ta.y = f32_tf32(na[j].y);
                ta.z = f32_tf32(na[j].z); ta.w = f32_tf32(na[j].w);
                tb.x = f32_tf32(nb[j].x); tb.y = f32_tf32(nb[j].y);
                tb.z = f32_tf32(nb[j].z); tb.w = f32_tf32(nb[j].w);
                const int c = (gc + j * 4) ^ swr;
                *(uint4*)&As[nxt + sbase + c] = ta;
                *(uint4*)&Bs[nxt + sbase + c] = tb;
            }
        }
        __syncthreads();
    }

    // ---- epilogue ----
#pragma unroll
    for (int nf = 0; nf < 4; nf++) {
        const int gcol = n0 + wn + nf * 8 + 2 * lk;
        const float2 bv = *(const float2*)&bias[gcol];
#pragma unroll
        for (int mf = 0; mf < 4; mf++) {
            const long long row = m0 + wm + mf * 16 + lm;
            float2 v0, v1;
            v0.x = d[mf][nf][0] + bv.x;
            v0.y = d[mf][nf][1] + bv.y;
            v1.x = d[mf][nf][2] + bv.x;
            v1.y = d[mf][nf][3] + bv.y;
            if (EPI == 1) {
                float2 r0 = *(const float2*)&R[row * (long long)N + gcol];
                float2 r1 = *(const float2*)&R[(row + 8) * (long long)N + gcol];
                v0.x += r0.x; v0.y += r0.y;
                v1.x += r1.x; v1.y += r1.y;
            } else if (EPI == 2) {
                v0.x = gelu_exact(v0.x); v0.y = gelu_exact(v0.y);
                v1.x = gelu_exact(v1.x); v1.y = gelu_exact(v1.y);
            }
            *(float2*)&Out[row * (long long)N + gcol] = v0;
            *(float2*)&Out[(row + 8) * (long long)N + gcol] = v1;
        }
    }
}

// ===========================================================================
// Gather / Scatter / LayerNorm
// ===========================================================================
__global__ void __launch_bounds__(256) gather_kernel(const float* __restrict__ x,
                                                     float* __restrict__ tok) {
    __shared__ float tile[32][33];
    const int w0 = blockIdx.x * 32;
    const int c0 = blockIdx.y * 32;
    const int bh = blockIdx.z;
    const int b = bh >> 7, h = bh & 127;
    const int tx = threadIdx.x, ty = threadIdx.y;

    const float* xp = x + ((long long)(b * CDIM + c0)) * (H_ * W_) + h * W_ + w0;
#pragma unroll
    for (int i = 0; i < 4; i++) {
        int c = ty * 4 + i;
        tile[c][tx] = xp[(long long)c * (H_ * W_) + tx];
    }
    __syncthreads();

    const int wy = h >> 3, iy = h & 7;
#pragma unroll
    for (int i = 0; i < 4; i++) {
        int wloc = ty * 4 + i;
        int w = w0 + wloc;
        int wx = w >> 3, ix = w & 7;
        long long r = (((long long)(b * 16 + wy)) * 16 + wx) * 64 + iy * 8 + ix;
        tok[r * CDIM + c0 + tx] = tile[tx][wloc];
    }
}

__global__ void __launch_bounds__(256) scatter_kernel(const float* __restrict__ tok,
                                                      float* __restrict__ x) {
    __shared__ float tile[32][33];
    const int w0 = blockIdx.x * 32;
    const int c0 = blockIdx.y * 32;
    const int bh = blockIdx.z;
    const int b = bh >> 7, h = bh & 127;
    const int tx = threadIdx.x, ty = threadIdx.y;
    const int wy = h >> 3, iy = h & 7;

#pragma unroll
    for (int i = 0; i < 4; i++) {
        int wloc = ty * 4 + i;
        int w = w0 + wloc;
        int wx = w >> 3, ix = w & 7;
        long long r = (((long long)(b * 16 + wy)) * 16 + wx) * 64 + iy * 8 + ix;
        tile[tx][wloc] = tok[r * CDIM + c0 + tx];
    }
    __syncthreads();

    float* xp = x + ((long long)(b * CDIM + c0)) * (H_ * W_) + h * W_ + w0;
#pragma unroll
    for (int i = 0; i < 4; i++) {
        int c = ty * 4 + i;
        xp[(long long)c * (H_ * W_) + tx] = tile[c][tx];
    }
}

__global__ void __launch_bounds__(256) ln_kernel(const float* __restrict__ A,
                                                 const float* __restrict__ g,
                                                 const float* __restrict__ b,
                                                 float* __restrict__ Y) {
    const long long row = (long long)blockIdx.x * 8 + (threadIdx.x >> 5);
    const int lane = threadIdx.x & 31;
    const float4* ap = (const float4*)(A + row * CDIM);
    float4 v0 = ap[lane];
    float4 v1 = ap[lane + 32];

    float s = v0.x + v0.y + v0.z + v0.w + v1.x + v1.y + v1.z + v1.w;
#pragma unroll
    for (int o = 16; o; o >>= 1) s += __shfl_xor_sync(0xFFFFFFFFu, s, o);
    const float mu = s * (1.0f / 256.0f);

    float q = (v0.x - mu) * (v0.x - mu) + (v0.y - mu) * (v0.y - mu)
            + (v0.z - mu) * (v0.z - mu) + (v0.w - mu) * (v0.w - mu)
            + (v1.x - mu) * (v1.x - mu) + (v1.y - mu) * (v1.y - mu)
            + (v1.z - mu) * (v1.z - mu) + (v1.w - mu) * (v1.w - mu);
#pragma unroll
    for (int o = 16; o; o >>= 1) q += __shfl_xor_sync(0xFFFFFFFFu, q, o);
    const float rinv = rsqrtf(q * (1.0f / 256.0f) + 1e-5f);

    const float4* gp = (const float4*)g;
    const float4* bp = (const float4*)b;
    float4 g0 = gp[lane], g1 = gp[lane + 32];
    float4 b0 = bp[lane], b1 = bp[lane + 32];
    float4 y0, y1;
    y0.x = (v0.x - mu) * rinv * g0.x + b0.x;
    y0.y = (v0.y - mu) * rinv * g0.y + b0.y;
    y0.z = (v0.z - mu) * rinv * g0.z + b0.z;
    y0.w = (v0.w - mu) * rinv * g0.w + b0.w;
    y1.x = (v1.x - mu) * rinv * g1.x + b1.x;
    y1.y = (v1.y - mu) * rinv * g1.y + b1.y;
    y1.z = (v1.z - mu) * rinv * g1.z + b1.z;
    y1.w = (v1.w - mu) * rinv * g1.w + b1.w;
    float4* yp = (float4*)(Y + row * CDIM);
    yp[lane] = y0;
    yp[lane + 32] = y1;
}

// ===========================================================================
// Attention: per (window, head). Softmax now 2 threads/row.
// ===========================================================================
__global__ void __launch_bounds__(128) attn_kernel(const float* __restrict__ qkv,
                                                   float* __restrict__ o) {
    __shared__ float sq[64][33];
    __shared__ float sk[64][33];
    __shared__ float sv[64][33];
    __shared__ float ss[64][65];

    const int tid = threadIdx.x;
    const int n = blockIdx.x >> 3;
    const int head = blockIdx.x & 7;
    const float* base = qkv + (long long)n * 64 * 768 + head * 32;

    {
        const int r0 = tid >> 3;
        const int c4 = (tid & 7) * 4;
#pragma unroll
        for (int it = 0; it < 4; it++) {
            const int r = r0 + it * 16;
            const float* rp = base + (long long)r * 768 + c4;
            float4 qv = *(const float4*)(rp);
            float4 kv = *(const float4*)(rp + 256);
            float4 vv = *(const float4*)(rp + 512);
            sq[r][c4 + 0] = qv.x; sq[r][c4 + 1] = qv.y; sq[r][c4 + 2] = qv.z; sq[r][c4 + 3] = qv.w;
            sk[r][c4 + 0] = kv.x; sk[r][c4 + 1] = kv.y; sk[r][c4 + 2] = kv.z; sk[r][c4 + 3] = kv.w;
            sv[r][c4 + 0] = vv.x; sv[r][c4 + 1] = vv.y; sv[r][c4 + 2] = vv.z; sv[r][c4 + 3] = vv.w;
        }
    }
    __syncthreads();

    {
        const int rg = tid >> 3;
        const int cgg = tid & 7;
        float acc[4][8];
#pragma unroll
        for (int i = 0; i < 4; i++)
#pragma unroll
            for (int j = 0; j < 8; j++) acc[i][j] = 0.0f;

#pragma unroll 4
        for (int kk = 0; kk < 32; kk++) {
            float a[4], bb[8];
#pragma unroll
            for (int i = 0; i < 4; i++) a[i] = sq[rg * 4 + i][kk];
#pragma unroll
            for (int j = 0; j < 8; j++) bb[j] = sk[cgg * 8 + j][kk];
#pragma unroll
            for (int i = 0; i < 4; i++)
#pragma unroll
                for (int j = 0; j < 8; j++) acc[i][j] += a[i] * bb[j];
        }
        const float scale = 0.17677669529663689f;
#pragma unroll
        for (int i = 0; i < 4; i++)
#pragma unroll
            for (int j = 0; j < 8; j++)
                ss[rg * 4 + i][cgg * 8 + j] = acc[i][j] * scale;
    }
    __syncthreads();

    // softmax: 2 threads per row, 32 cols each, phase-shifted
    {
        const int row = tid >> 1;
        const int hf = tid & 1;
        const int cb = hf * 32;
        const int ph = hf * 16;
        float mx = -1e30f;
#pragma unroll 8
        for (int j = 0; j < 32; j++) {
            const int c = cb + ((j + ph) & 31);
            mx = fmaxf(mx, ss[row][c]);
        }
        mx = fmaxf(mx, __shfl_xor_sync(0xFFFFFFFFu, mx, 1));
        float sum = 0.0f;
#pragma unroll 8
        for (int j = 0; j < 32; j++) {
            const int c = cb + ((j + ph) & 31);
            float e = expf(ss[row][c] - mx);
            ss[row][c] = e;
            sum += e;
        }
        sum += __shfl_xor_sync(0xFFFFFFFFu, sum, 1);
        const float inv = 1.0f / sum;
#pragma unroll 8
        for (int j = 0; j < 32; j++) {
            const int c = cb + ((j + ph) & 31);
            ss[row][c] *= inv;
        }
    }
    __syncthreads();

    {
        const int rg = tid >> 3;
        const int cgo = tid & 7;
        float acc[4][4];
#pragma unroll
        for (int i = 0; i < 4; i++)
#pragma unroll
            for (int j = 0; j < 4; j++) acc[i][j] = 0.0f;

#pragma unroll 4
        for (int kk = 0; kk < 64; kk++) {
            float a[4], bb[4];
#pragma unroll
            for (int i = 0; i < 4; i++) a[i] = ss[rg * 4 + i][kk];
#pragma unroll
            for (int j = 0; j < 4; j++) bb[j] = sv[kk][cgo * 4 + j];
#pragma unroll
            for (int i = 0; i < 4; i++)
#pragma unroll
                for (int j = 0; j < 4; j++) acc[i][j] += a[i] * bb[j];
        }
#pragma unroll
        for (int i = 0; i < 4; i++) {
            float4 r;
            r.x = acc[i][0]; r.y = acc[i][1]; r.z = acc[i][2]; r.w = acc[i][3];
            *(float4*)&o[((long long)n * 64 + rg * 4 + i) * CDIM + head * 32 + cgo * 4] = r;
        }
    }
}

// ===========================================================================
// Launch
// ===========================================================================
extern "C" void kernel_launch(void* const* d_in, const int* in_sizes, int n_in,
                              void* d_out, int out_size) {
    const float* x      = (const float*)d_in[0];
    const float* qkv_w  = (const float*)d_in[1];
    const float* qkv_b  = (const float*)d_in[2];
    const float* proj_w = (const float*)d_in[3];
    const float* proj_b = (const float*)d_in[4];
    const float* n1_g   = (const float*)d_in[5];
    const float* n1_b   = (const float*)d_in[6];
    const float* n2_g   = (const float*)d_in[7];
    const float* n2_b   = (const float*)d_in[8];
    const float* fc1_w  = (const float*)d_in[9];
    const float* fc1_b  = (const float*)d_in[10];
    const float* fc2_w  = (const float*)d_in[11];
    const float* fc2_b  = (const float*)d_in[12];
    float* out = (float*)d_out;

    float *tok, *y, *qkv, *o, *hid;
    cudaGetSymbolAddress((void**)&tok, g_tok);
    cudaGetSymbolAddress((void**)&y, g_y);
    cudaGetSymbolAddress((void**)&qkv, g_qkv);
    cudaGetSymbolAddress((void**)&o, g_o);
    cudaGetSymbolAddress((void**)&hid, g_hid);

    const int SMEM_GEMM = 65536;  // 2 x (16KB A + 16KB B)
    cudaFuncSetAttribute(mma_gemm<0>, cudaFuncAttributeMaxDynamicSharedMemorySize, SMEM_GEMM);
    cudaFuncSetAttribute(mma_gemm<1>, cudaFuncAttributeMaxDynamicSharedMemorySize, SMEM_GEMM);
    cudaFuncSetAttribute(mma_gemm<2>, cudaFuncAttributeMaxDynamicSharedMemorySize, SMEM_GEMM);

    const dim3 tb(32, 8);
    const dim3 tg(W_ / 32, CDIM / 32, B_ * H_);
    const int MT = NTOK / 128;  // 2048 M-tiles

    // 1. window partition
    gather_kernel<<<tg, tb>>>(x, tok);
    // 2. LN1
    ln_kernel<<<NTOK / 8, 256>>>(tok, n1_g, n1_b, y);
    // 3. QKV gemm
    mma_gemm<0><<<dim3(MT, 768 / 128), 256, SMEM_GEMM>>>(y, qkv_w, qkv_b, nullptr, qkv, 768, 256);
    // 4. windowed attention
    attn_kernel<<<4096 * 8, 128>>>(qkv, o);
    // 5. proj gemm + residual -> tok
    mma_gemm<1><<<dim3(MT, 256 / 128), 256, SMEM_GEMM>>>(o, proj_w, proj_b, tok, tok, 256, 256);
    // 6. LN2
    ln_kernel<<<NTOK / 8, 256>>>(tok, n2_g, n2_b, y);
    // 7. fc1 gemm + GELU
    mma_gemm<2><<<dim3(MT, 1024 / 128), 256, SMEM_GEMM>>>(y, fc1_w, fc1_b, nullptr, hid, 1024, 256);
    // 8. fc2 gemm + residual -> y
    mma_gemm<1><<<dim3(MT, 256 / 128), 256, SMEM_GEMM>>>(hid, fc2_w, fc2_b, tok, y, 256, 1024);
    // 9. un-partition
    scatter_kernel<<<tg, tb>>>(y, out);
}

// round 5
// speedup vs baseline: 1.1631x; 1.1631x over previous
#include <cuda_runtime.h>
#include <math.h>
#include <cstdint>

// Problem constants
#define B_ 16
#define CDIM 256
#define H_ 128
#define W_ 128
#define NTOK 262144   // B*H*W tokens

// Scratch (device globals)
__device__ float g_tok[67108864];    // [NTOK, 256]
__device__ float g_y[67108864];      // [NTOK, 256]
__device__ float g_qkv[201326592];   // [NTOK, 768]
__device__ float g_o[67108864];      // [NTOK, 256]
__device__ float g_hid[268435456];   // [NTOK, 1024]

__device__ __forceinline__ uint32_t f32_tf32(float v) {
    uint32_t u;
    asm("cvt.rna.tf32.f32 %0, %1;" : "=r"(u) : "f"(v));
    return u;
}

__device__ __forceinline__ float gelu_exact(float v) {
    return 0.5f * v * (1.0f + erff(v * 0.70710678118654752f));
}

__device__ __forceinline__ void cpa16(uint32_t dst, const float* src) {
    asm volatile("cp.async.cg.shared.global [%0], [%1], 16;" :: "r"(dst), "l"(src));
}
#define CP_COMMIT() asm volatile("cp.async.commit_group;" ::: "memory")
#define CP_WAIT1()  asm volatile("cp.async.wait_group 1;" ::: "memory")

// ===========================================================================
// TF32 mma.sync GEMM with cp.async 3-stage pipeline.
// Out[M,N] = A[M,K] * W[N,K]^T + bias (+ epilogue)
// CTA tile 128x128, K-chunk 32, 8 warps (warp tile 64x32).
// SMEM holds raw fp32; tf32 conversion happens at fragment-load time.
// EPI: 0=bias, 1=bias+residual, 2=bias+GELU
// ===========================================================================
template <int EPI>
__global__ void __launch_bounds__(256) mma_gemm(const float* __restrict__ A,
                                                const float* __restrict__ W,
                                                const float* __restrict__ bias,
                                                const float* __restrict__ R,
                                                float* __restrict__ Out,
                                                int N, int K) {
    extern __shared__ uint32_t sm[];
    uint32_t* As = sm;               // [3][4096] fp32 bits
    uint32_t* Bs = sm + 3 * 4096;    // [3][4096]

    const int tid = threadIdx.x;
    const int wid = tid >> 5;
    const int lane = tid & 31;
    const long long m0 = (long long)blockIdx.x * 128;
    const int n0 = blockIdx.y * 128;

    const int wm = (wid >> 2) * 64;
    const int wn = (wid & 3) * 32;
    const int lm = lane >> 2;
    const int lk = lane & 3;

    // global load mapping: row gr = tid>>1, 16 cols starting at (tid&1)*16
    const int gr = tid >> 1;
    const int gc = (tid & 1) * 16;
    const int swr = (gr & 7) * 4;

    const float* arow = A + (m0 + gr) * (long long)K + gc;
    const float* brow = W + (long long)(n0 + gr) * K + gc;

    const uint32_t as_b = (uint32_t)__cvta_generic_to_shared(As);
    const uint32_t bs_b = (uint32_t)__cvta_generic_to_shared(Bs);
    // per-thread smem byte offsets for the 4 cp.asyncs (A and B identical)
    uint32_t soff[4];
#pragma unroll
    for (int j = 0; j < 4; j++)
        soff[j] = (uint32_t)(gr * 32 + ((gc + j * 4) ^ swr)) * 4u;

    const int KT = K >> 5;

    // ---- prologue: stages 0,1 ----
#pragma unroll
    for (int s = 0; s < 2; s++) {
        const int ko = s * 32;
        const uint32_t sb = s * 16384u;
#pragma unroll
        for (int j = 0; j < 4; j++) {
            cpa16(as_b + sb + soff[j], arow + ko + j * 4);
            cpa16(bs_b + sb + soff[j], brow + ko + j * 4);
        }
        CP_COMMIT();
    }

    float d[4][4][4];
#pragma unroll
    for (int i = 0; i < 4; i++)
#pragma unroll
        for (int j = 0; j < 4; j++)
#pragma unroll
            for (int q = 0; q < 4; q++) d[i][j][q] = 0.0f;

    int stage = 0;
    for (int kt = 0; kt < KT; kt++) {
        CP_WAIT1();
        __syncthreads();

        // issue stage kt+2 (overlaps compute below)
        if (kt + 2 < KT) {
            const int s2 = (stage + 2) % 3;
            const int ko = (kt + 2) * 32;
            const uint32_t sb = s2 * 16384u;
#pragma unroll
            for (int j = 0; j < 4; j++) {
                cpa16(as_b + sb + soff[j], arow + ko + j * 4);
                cpa16(bs_b + sb + soff[j], brow + ko + j * 4);
            }
        }
        CP_COMMIT();

        // ---- compute from current stage ----
        const uint32_t* Ac = As + stage * 4096;
        const uint32_t* Bc = Bs + stage * 4096;
#pragma unroll
        for (int kk = 0; kk < 32; kk += 8) {
            uint32_t a[4][4];
#pragma unroll
            for (int mf = 0; mf < 4; mf++) {
                const int m = wm + mf * 16 + lm;
                const int sw = (m & 7) * 4;
                const int c0 = (kk + lk) ^ sw;
                const int c1 = (kk + 4 + lk) ^ sw;
                a[mf][0] = f32_tf32(__uint_as_float(Ac[m * 32 + c0]));
                a[mf][1] = f32_tf32(__uint_as_float(Ac[(m + 8) * 32 + c0]));
                a[mf][2] = f32_tf32(__uint_as_float(Ac[m * 32 + c1]));
                a[mf][3] = f32_tf32(__uint_as_float(Ac[(m + 8) * 32 + c1]));
            }
            uint32_t b[4][2];
#pragma unroll
            for (int nf = 0; nf < 4; nf++) {
                const int n = wn + nf * 8 + lm;
                const int sw = (n & 7) * 4;
                b[nf][0] = f32_tf32(__uint_as_float(Bc[n * 32 + ((kk + lk) ^ sw)]));
                b[nf][1] = f32_tf32(__uint_as_float(Bc[n * 32 + ((kk + 4 + lk) ^ sw)]));
            }
#pragma unroll
            for (int mf = 0; mf < 4; mf++)
#pragma unroll
                for (int nf = 0; nf < 4; nf++) {
                    asm volatile(
                        "mma.sync.aligned.m16n8k8.row.col.f32.tf32.tf32.f32 "
                        "{%0,%1,%2,%3}, {%4,%5,%6,%7}, {%8,%9}, {%0,%1,%2,%3};"
                        : "+f"(d[mf][nf][0]), "+f"(d[mf][nf][1]),
                          "+f"(d[mf][nf][2]), "+f"(d[mf][nf][3])
                        : "r"(a[mf][0]), "r"(a[mf][1]), "r"(a[mf][2]), "r"(a[mf][3]),
                          "r"(b[nf][0]), "r"(b[nf][1]));
                }
        }
        stage = (stage + 1) % 3;
    }

    // ---- epilogue ----
#pragma unroll
    for (int nf = 0; nf < 4; nf++) {
        const int gcol = n0 + wn + nf * 8 + 2 * lk;
        const float2 bv = *(const float2*)&bias[gcol];
#pragma unroll
        for (int mf = 0; mf < 4; mf++) {
            const long long row = m0 + wm + mf * 16 + lm;
            float2 v0, v1;
            v0.x = d[mf][nf][0] + bv.x;
            v0.y = d[mf][nf][1] + bv.y;
            v1.x = d[mf][nf][2] + bv.x;
            v1.y = d[mf][nf][3] + bv.y;
            if (EPI == 1) {
                float2 r0 = *(const float2*)&R[row * (long long)N + gcol];
                float2 r1 = *(const float2*)&R[(row + 8) * (long long)N + gcol];
                v0.x += r0.x; v0.y += r0.y;
                v1.x += r1.x; v1.y += r1.y;
            } else if (EPI == 2) {
                v0.x = gelu_exact(v0.x); v0.y = gelu_exact(v0.y);
                v1.x = gelu_exact(v1.x); v1.y = gelu_exact(v1.y);
            }
            *(float2*)&Out[row * (long long)N + gcol] = v0;
            *(float2*)&Out[(row + 8) * (long long)N + gcol] = v1;
        }
    }
}

// ===========================================================================
// Gather / Scatter / LayerNorm
// ===========================================================================
__global__ void __launch_bounds__(256) gather_kernel(const float* __restrict__ x,
                                                     float* __restrict__ tok) {
    __shared__ float tile[32][33];
    const int w0 = blockIdx.x * 32;
    const int c0 = blockIdx.y * 32;
    const int bh = blockIdx.z;
    const int b = bh >> 7, h = bh & 127;
    const int tx = threadIdx.x, ty = threadIdx.y;

    const float* xp = x + ((long long)(b * CDIM + c0)) * (H_ * W_) + h * W_ + w0;
#pragma unroll
    for (int i = 0; i < 4; i++) {
        int c = ty * 4 + i;
        tile[c][tx] = xp[(long long)c * (H_ * W_) + tx];
    }
    __syncthreads();

    const int wy = h >> 3, iy = h & 7;
#pragma unroll
    for (int i = 0; i < 4; i++) {
        int wloc = ty * 4 + i;
        int w = w0 + wloc;
        int wx = w >> 3, ix = w & 7;
        long long r = (((long long)(b * 16 + wy)) * 16 + wx) * 64 + iy * 8 + ix;
        tok[r * CDIM + c0 + tx] = tile[tx][wloc];
    }
}

__global__ void __launch_bounds__(256) scatter_kernel(const float* __restrict__ tok,
                                                      float* __restrict__ x) {
    __shared__ float tile[32][33];
    const int w0 = blockIdx.x * 32;
    const int c0 = blockIdx.y * 32;
    const int bh = blockIdx.z;
    const int b = bh >> 7, h = bh & 127;
    const int tx = threadIdx.x, ty = threadIdx.y;
    const int wy = h >> 3, iy = h & 7;

#pragma unroll
    for (int i = 0; i < 4; i++) {
        int wloc = ty * 4 + i;
        int w = w0 + wloc;
        int wx = w >> 3, ix = w & 7;
        long long r = (((long long)(b * 16 + wy)) * 16 + wx) * 64 + iy * 8 + ix;
        tile[tx][wloc] = tok[r * CDIM + c0 + tx];
    }
    __syncthreads();

    float* xp = x + ((long long)(b * CDIM + c0)) * (H_ * W_) + h * W_ + w0;
#pragma unroll
    for (int i = 0; i < 4; i++) {
        int c = ty * 4 + i;
        xp[(long long)c * (H_ * W_) + tx] = tile[c][tx];
    }
}

__global__ void __launch_bounds__(256) ln_kernel(const float* __restrict__ A,
                                                 const float* __restrict__ g,
                                                 const float* __restrict__ b,
                                                 float* __restrict__ Y) {
    const long long row = (long long)blockIdx.x * 8 + (threadIdx.x >> 5);
    const int lane = threadIdx.x & 31;
    const float4* ap = (const float4*)(A + row * CDIM);
    float4 v0 = ap[lane];
    float4 v1 = ap[lane + 32];

    float s = v0.x + v0.y + v0.z + v0.w + v1.x + v1.y + v1.z + v1.w;
#pragma unroll
    for (int o = 16; o; o >>= 1) s += __shfl_xor_sync(0xFFFFFFFFu, s, o);
    const float mu = s * (1.0f / 256.0f);

    float q = (v0.x - mu) * (v0.x - mu) + (v0.y - mu) * (v0.y - mu)
            + (v0.z - mu) * (v0.z - mu) + (v0.w - mu) * (v0.w - mu)
            + (v1.x - mu) * (v1.x - mu) + (v1.y - mu) * (v1.y - mu)
            + (v1.z - mu) * (v1.z - mu) + (v1.w - mu) * (v1.w - mu);
#pragma unroll
    for (int o = 16; o; o >>= 1) q += __shfl_xor_sync(0xFFFFFFFFu, q, o);
    const float rinv = rsqrtf(q * (1.0f / 256.0f) + 1e-5f);

    const float4* gp = (const float4*)g;
    const float4* bp = (const float4*)b;
    float4 g0 = gp[lane], g1 = gp[lane + 32];
    float4 b0 = bp[lane], b1 = bp[lane + 32];
    float4 y0, y1;
    y0.x = (v0.x - mu) * rinv * g0.x + b0.x;
    y0.y = (v0.y - mu) * rinv * g0.y + b0.y;
    y0.z = (v0.z - mu) * rinv * g0.z + b0.z;
    y0.w = (v0.w - mu) * rinv * g0.w + b0.w;
    y1.x = (v1.x - mu) * rinv * g1.x + b1.x;
    y1.y = (v1.y - mu) * rinv * g1.y + b1.y;
    y1.z = (v1.z - mu) * rinv * g1.z + b1.z;
    y1.w = (v1.w - mu) * rinv * g1.w + b1.w;
    float4* yp = (float4*)(Y + row * CDIM);
    yp[lane] = y0;
    yp[lane + 32] = y1;
}

// ===========================================================================
// Attention: per (window, head). Softmax 2 threads/row.
// ===========================================================================
__global__ void __launch_bounds__(128) attn_kernel(const float* __restrict__ qkv,
                                                   float* __restrict__ o) {
    __shared__ float sq[64][33];
    __shared__ float sk[64][33];
    __shared__ float sv[64][33];
    __shared__ float ss[64][65];

    const int tid = threadIdx.x;
    const int n = blockIdx.x >> 3;
    const int head = blockIdx.x & 7;
    const float* base = qkv + (long long)n * 64 * 768 + head * 32;

    {
        const int r0 = tid >> 3;
        const int c4 = (tid & 7) * 4;
#pragma unroll
        for (int it = 0; it < 4; it++) {
            const int r = r0 + it * 16;
            const float* rp = base + (long long)r * 768 + c4;
            float4 qv = *(const float4*)(rp);
            float4 kv = *(const float4*)(rp + 256);
            float4 vv = *(const float4*)(rp + 512);
            sq[r][c4 + 0] = qv.x; sq[r][c4 + 1] = qv.y; sq[r][c4 + 2] = qv.z; sq[r][c4 + 3] = qv.w;
            sk[r][c4 + 0] = kv.x; sk[r][c4 + 1] = kv.y; sk[r][c4 + 2] = kv.z; sk[r][c4 + 3] = kv.w;
            sv[r][c4 + 0] = vv.x; sv[r][c4 + 1] = vv.y; sv[r][c4 + 2] = vv.z; sv[r][c4 + 3] = vv.w;
        }
    }
    __syncthreads();

    {
        const int rg = tid >> 3;
        const int cgg = tid & 7;
        float acc[4][8];
#pragma unroll
        for (int i = 0; i < 4; i++)
#pragma unroll
            for (int j = 0; j < 8; j++) acc[i][j] = 0.0f;

#pragma unroll 4
        for (int kk = 0; kk < 32; kk++) {
            float a[4], bb[8];
#pragma unroll
            for (int i = 0; i < 4; i++) a[i] = sq[rg * 4 + i][kk];
#pragma unroll
            for (int j = 0; j < 8; j++) bb[j] = sk[cgg * 8 + j][kk];
#pragma unroll
            for (int i = 0; i < 4; i++)
#pragma unroll
                for (int j = 0; j < 8; j++) acc[i][j] += a[i] * bb[j];
        }
        const float scale = 0.17677669529663689f;
#pragma unroll
        for (int i = 0; i < 4; i++)
#pragma unroll
            for (int j = 0; j < 8; j++)
                ss[rg * 4 + i][cgg * 8 + j] = acc[i][j] * scale;
    }
    __syncthreads();

    {
        const int row = tid >> 1;
        const int hf = tid & 1;
        const int cb = hf * 32;
        const int ph = hf * 16;
        float mx = -1e30f;
#pragma unroll 8
        for (int j = 0; j < 32; j++) {
            const int c = cb + ((j + ph) & 31);
            mx = fmaxf(mx, ss[row][c]);
        }
        mx = fmaxf(mx, __shfl_xor_sync(0xFFFFFFFFu, mx, 1));
        float sum = 0.0f;
#pragma unroll 8
        for (int j = 0; j < 32; j++) {
            const int c = cb + ((j + ph) & 31);
            float e = expf(ss[row][c] - mx);
            ss[row][c] = e;
            sum += e;
        }
        sum += __shfl_xor_sync(0xFFFFFFFFu, sum, 1);
        const float inv = 1.0f / sum;
#pragma unroll 8
        for (int j = 0; j < 32; j++) {
            const int c = cb + ((j + ph) & 31);
            ss[row][c] *= inv;
        }
    }
    __syncthreads();

    {
        const int rg = tid >> 3;
        const int cgo = tid & 7;
        float acc[4][4];
#pragma unroll
        for (int i = 0; i < 4; i++)
#pragma unroll
            for (int j = 0; j < 4; j++) acc[i][j] = 0.0f;

#pragma unroll 4
        for (int kk = 0; kk < 64; kk++) {
            float a[4], bb[4];
#pragma unroll
            for (int i = 0; i < 4; i++) a[i] = ss[rg * 4 + i][kk];
#pragma unroll
            for (int j = 0; j < 4; j++) bb[j] = sv[kk][cgo * 4 + j];
#pragma unroll
            for (int i = 0; i < 4; i++)
#pragma unroll
                for (int j = 0; j < 4; j++) acc[i][j] += a[i] * bb[j];
        }
#pragma unroll
        for (int i = 0; i < 4; i++) {
            float4 r;
            r.x = acc[i][0]; r.y = acc[i][1]; r.z = acc[i][2]; r.w = acc[i][3];
            *(float4*)&o[((long long)n * 64 + rg * 4 + i) * CDIM + head * 32 + cgo * 4] = r;
        }
    }
}

// ===========================================================================
// Launch
// ===========================================================================
extern "C" void kernel_launch(void* const* d_in, const int* in_sizes, int n_in,
                              void* d_out, int out_size) {
    const float* x      = (const float*)d_in[0];
    const float* qkv_w  = (const float*)d_in[1];
    const float* qkv_b  = (const float*)d_in[2];
    const float* proj_w = (const float*)d_in[3];
    const float* proj_b = (const float*)d_in[4];
    const float* n1_g   = (const float*)d_in[5];
    const float* n1_b   = (const float*)d_in[6];
    const float* n2_g   = (const float*)d_in[7];
    const float* n2_b   = (const float*)d_in[8];
    const float* fc1_w  = (const float*)d_in[9];
    const float* fc1_b  = (const float*)d_in[10];
    const float* fc2_w  = (const float*)d_in[11];
    const float* fc2_b  = (const float*)d_in[12];
    float* out = (float*)d_out;

    float *tok, *y, *qkv, *o, *hid;
    cudaGetSymbolAddress((void**)&tok, g_tok);
    cudaGetSymbolAddress((void**)&y, g_y);
    cudaGetSymbolAddress((void**)&qkv, g_qkv);
    cudaGetSymbolAddress((void**)&o, g_o);
    cudaGetSymbolAddress((void**)&hid, g_hid);

    const int SMEM_GEMM = 3 * 32768;  // 3 stages x (16KB A + 16KB B) = 96KB
    cudaFuncSetAttribute(mma_gemm<0>, cudaFuncAttributeMaxDynamicSharedMemorySize, SMEM_GEMM);
    cudaFuncSetAttribute(mma_gemm<1>, cudaFuncAttributeMaxDynamicSharedMemorySize, SMEM_GEMM);
    cudaFuncSetAttribute(mma_gemm<2>, cudaFuncAttributeMaxDynamicSharedMemorySize, SMEM_GEMM);

    const dim3 tb(32, 8);
    const dim3 tg(W_ / 32, CDIM / 32, B_ * H_);
    const int MT = NTOK / 128;  // 2048 M-tiles

    // 1. window partition
    gather_kernel<<<tg, tb>>>(x, tok);
    // 2. LN1
    ln_kernel<<<NTOK / 8, 256>>>(tok, n1_g, n1_b, y);
    // 3. QKV gemm
    mma_gemm<0><<<dim3(MT, 768 / 128), 256, SMEM_GEMM>>>(y, qkv_w, qkv_b, nullptr, qkv, 768, 256);
    // 4. windowed attention
    attn_kernel<<<4096 * 8, 128>>>(qkv, o);
    // 5. proj gemm + residual -> tok
    mma_gemm<1><<<dim3(MT, 256 / 128), 256, SMEM_GEMM>>>(o, proj_w, proj_b, tok, tok, 256, 256);
    // 6. LN2
    ln_kernel<<<NTOK / 8, 256>>>(tok, n2_g, n2_b, y);
    // 7. fc1 gemm + GELU
    mma_gemm<2><<<dim3(MT, 1024 / 128), 256, SMEM_GEMM>>>(y, fc1_w, fc1_b, nullptr, hid, 1024, 256);
    // 8. fc2 gemm + residual -> y
    mma_gemm<1><<<dim3(MT, 256 / 128), 256, SMEM_GEMM>>>(hid, fc2_w, fc2_b, tok, y, 256, 1024);
    // 9. un-partition
    scatter_kernel<<<tg, tb>>>(y, out);
}

// round 6
// speedup vs baseline: 1.2710x; 1.0927x over previous
#include <cuda_runtime.h>
#include <math.h>
#include <cstdint>

// Problem constants
#define B_ 16
#define CDIM 256
#define H_ 128
#define W_ 128
#define NTOK 262144   // B*H*W tokens

// Scratch (device globals)
__device__ float g_tok[67108864];    // [NTOK, 256]
__device__ float g_y[67108864];      // [NTOK, 256]
__device__ float g_qkv[201326592];   // [NTOK, 768]
__device__ float g_o[67108864];      // [NTOK, 256]
__device__ float g_hid[268435456];   // [NTOK, 1024]

__device__ __forceinline__ float gelu_exact(float v) {
    return 0.5f * v * (1.0f + erff(v * 0.70710678118654752f));
}

__device__ __forceinline__ void cpa16(uint32_t dst, const float* src) {
    asm volatile("cp.async.cg.shared.global [%0], [%1], 16;" :: "r"(dst), "l"(src));
}
#define CP_COMMIT() asm volatile("cp.async.commit_group;" ::: "memory")
#define CP_WAIT1()  asm volatile("cp.async.wait_group 1;" ::: "memory")

// ===========================================================================
// TF32 mma.sync GEMM, cp.async 3-stage pipeline, 2 CTAs/SM.
// Raw fp32 bits are fed to the tf32 MMA (HW truncates mantissa) — no CVT.
// Out[M,N] = A[M,K] * W[N,K]^T + bias (+ epilogue)
// CTA tile 128x128, K-chunk 32, 8 warps (warp tile 64x32).
// EPI: 0=bias, 1=bias+residual, 2=bias+GELU
// ===========================================================================
template <int EPI>
__global__ void __launch_bounds__(256, 2) mma_gemm(const float* __restrict__ A,
                                                   const float* __restrict__ W,
                                                   const float* __restrict__ bias,
                                                   const float* __restrict__ R,
                                                   float* __restrict__ Out,
                                                   int N, int K) {
    extern __shared__ uint32_t sm[];
    uint32_t* As = sm;               // [3][4096] fp32 bits
    uint32_t* Bs = sm + 3 * 4096;    // [3][4096]

    const int tid = threadIdx.x;
    const int wid = tid >> 5;
    const int lane = tid & 31;
    const long long m0 = (long long)blockIdx.x * 128;
    const int n0 = blockIdx.y * 128;

    const int wm = (wid >> 2) * 64;
    const int wn = (wid & 3) * 32;
    const int lm = lane >> 2;
    const int lk = lane & 3;

    // global load mapping: row gr = tid>>1, 16 cols starting at (tid&1)*16
    const int gr = tid >> 1;
    const int gc = (tid & 1) * 16;
    const int swr = (gr & 7) * 4;

    const float* arow = A + (m0 + gr) * (long long)K + gc;
    const float* brow = W + (long long)(n0 + gr) * K + gc;

    const uint32_t as_b = (uint32_t)__cvta_generic_to_shared(As);
    const uint32_t bs_b = (uint32_t)__cvta_generic_to_shared(Bs);
    uint32_t soff[4];
#pragma unroll
    for (int j = 0; j < 4; j++)
        soff[j] = (uint32_t)(gr * 32 + ((gc + j * 4) ^ swr)) * 4u;

    const int KT = K >> 5;

    // ---- prologue: stages 0,1 ----
#pragma unroll
    for (int s = 0; s < 2; s++) {
        const int ko = s * 32;
        const uint32_t sb = s * 16384u;
#pragma unroll
        for (int j = 0; j < 4; j++) {
            cpa16(as_b + sb + soff[j], arow + ko + j * 4);
            cpa16(bs_b + sb + soff[j], brow + ko + j * 4);
        }
        CP_COMMIT();
    }

    float d[4][4][4];
#pragma unroll
    for (int i = 0; i < 4; i++)
#pragma unroll
        for (int j = 0; j < 4; j++)
#pragma unroll
            for (int q = 0; q < 4; q++) d[i][j][q] = 0.0f;

    int stage = 0;
    for (int kt = 0; kt < KT; kt++) {
        CP_WAIT1();
        __syncthreads();

        // issue stage kt+2 (overlaps compute below)
        if (kt + 2 < KT) {
            const int s2 = (stage + 2) % 3;
            const int ko = (kt + 2) * 32;
            const uint32_t sb = s2 * 16384u;
#pragma unroll
            for (int j = 0; j < 4; j++) {
                cpa16(as_b + sb + soff[j], arow + ko + j * 4);
                cpa16(bs_b + sb + soff[j], brow + ko + j * 4);
            }
        }
        CP_COMMIT();

        // ---- compute from current stage (raw fp32 bits -> tf32 MMA) ----
        const uint32_t* Ac = As + stage * 4096;
        const uint32_t* Bc = Bs + stage * 4096;
#pragma unroll
        for (int kk = 0; kk < 32; kk += 8) {
            uint32_t a[4][4];
#pragma unroll
            for (int mf = 0; mf < 4; mf++) {
                const int m = wm + mf * 16 + lm;
                const int sw = (m & 7) * 4;
                const int c0 = (kk + lk) ^ sw;
                const int c1 = (kk + 4 + lk) ^ sw;
                a[mf][0] = Ac[m * 32 + c0];
                a[mf][1] = Ac[(m + 8) * 32 + c0];
                a[mf][2] = Ac[m * 32 + c1];
                a[mf][3] = Ac[(m + 8) * 32 + c1];
            }
            uint32_t b[4][2];
#pragma unroll
            for (int nf = 0; nf < 4; nf++) {
                const int n = wn + nf * 8 + lm;
                const int sw = (n & 7) * 4;
                b[nf][0] = Bc[n * 32 + ((kk + lk) ^ sw)];
                b[nf][1] = Bc[n * 32 + ((kk + 4 + lk) ^ sw)];
            }
#pragma unroll
            for (int mf = 0; mf < 4; mf++)
#pragma unroll
                for (int nf = 0; nf < 4; nf++) {
                    asm volatile(
                        "mma.sync.aligned.m16n8k8.row.col.f32.tf32.tf32.f32 "
                        "{%0,%1,%2,%3}, {%4,%5,%6,%7}, {%8,%9}, {%0,%1,%2,%3};"
                        : "+f"(d[mf][nf][0]), "+f"(d[mf][nf][1]),
                          "+f"(d[mf][nf][2]), "+f"(d[mf][nf][3])
                        : "r"(a[mf][0]), "r"(a[mf][1]), "r"(a[mf][2]), "r"(a[mf][3]),
                          "r"(b[nf][0]), "r"(b[nf][1]));
                }
        }
        stage = (stage + 1) % 3;
    }

    // ---- epilogue ----
#pragma unroll
    for (int nf = 0; nf < 4; nf++) {
        const int gcol = n0 + wn + nf * 8 + 2 * lk;
        const float2 bv = *(const float2*)&bias[gcol];
#pragma unroll
        for (int mf = 0; mf < 4; mf++) {
            const long long row = m0 + wm + mf * 16 + lm;
            float2 v0, v1;
            v0.x = d[mf][nf][0] + bv.x;
            v0.y = d[mf][nf][1] + bv.y;
            v1.x = d[mf][nf][2] + bv.x;
            v1.y = d[mf][nf][3] + bv.y;
            if (EPI == 1) {
                float2 r0 = *(const float2*)&R[row * (long long)N + gcol];
                float2 r1 = *(const float2*)&R[(row + 8) * (long long)N + gcol];
                v0.x += r0.x; v0.y += r0.y;
                v1.x += r1.x; v1.y += r1.y;
            } else if (EPI == 2) {
                v0.x = gelu_exact(v0.x); v0.y = gelu_exact(v0.y);
                v1.x = gelu_exact(v1.x); v1.y = gelu_exact(v1.y);
            }
            *(float2*)&Out[row * (long long)N + gcol] = v0;
            *(float2*)&Out[(row + 8) * (long long)N + gcol] = v1;
        }
    }
}

// ===========================================================================
// Gather / Scatter / LayerNorm
// ===========================================================================
__global__ void __launch_bounds__(256) gather_kernel(const float* __restrict__ x,
                                                     float* __restrict__ tok) {
    __shared__ float tile[32][33];
    const int w0 = blockIdx.x * 32;
    const int c0 = blockIdx.y * 32;
    const int bh = blockIdx.z;
    const int b = bh >> 7, h = bh & 127;
    const int tx = threadIdx.x, ty = threadIdx.y;

    const float* xp = x + ((long long)(b * CDIM + c0)) * (H_ * W_) + h * W_ + w0;
#pragma unroll
    for (int i = 0; i < 4; i++) {
        int c = ty * 4 + i;
        tile[c][tx] = xp[(long long)c * (H_ * W_) + tx];
    }
    __syncthreads();

    const int wy = h >> 3, iy = h & 7;
#pragma unroll
    for (int i = 0; i < 4; i++) {
        int wloc = ty * 4 + i;
        int w = w0 + wloc;
        int wx = w >> 3, ix = w & 7;
        long long r = (((long long)(b * 16 + wy)) * 16 + wx) * 64 + iy * 8 + ix;
        tok[r * CDIM + c0 + tx] = tile[tx][wloc];
    }
}

__global__ void __launch_bounds__(256) scatter_kernel(const float* __restrict__ tok,
                                                      float* __restrict__ x) {
    __shared__ float tile[32][33];
    const int w0 = blockIdx.x * 32;
    const int c0 = blockIdx.y * 32;
    const int bh = blockIdx.z;
    const int b = bh >> 7, h = bh & 127;
    const int tx = threadIdx.x, ty = threadIdx.y;
    const int wy = h >> 3, iy = h & 7;

#pragma unroll
    for (int i = 0; i < 4; i++) {
        int wloc = ty * 4 + i;
        int w = w0 + wloc;
        int wx = w >> 3, ix = w & 7;
        long long r = (((long long)(b * 16 + wy)) * 16 + wx) * 64 + iy * 8 + ix;
        tile[tx][wloc] = tok[r * CDIM + c0 + tx];
    }
    __syncthreads();

    float* xp = x + ((long long)(b * CDIM + c0)) * (H_ * W_) + h * W_ + w0;
#pragma unroll
    for (int i = 0; i < 4; i++) {
        int c = ty * 4 + i;
        xp[(long long)c * (H_ * W_) + tx] = tile[c][tx];
    }
}

__global__ void __launch_bounds__(256) ln_kernel(const float* __restrict__ A,
                                                 const float* __restrict__ g,
                                                 const float* __restrict__ b,
                                                 float* __restrict__ Y) {
    const long long row = (long long)blockIdx.x * 8 + (threadIdx.x >> 5);
    const int lane = threadIdx.x & 31;
    const float4* ap = (const float4*)(A + row * CDIM);
    float4 v0 = ap[lane];
    float4 v1 = ap[lane + 32];

    float s = v0.x + v0.y + v0.z + v0.w + v1.x + v1.y + v1.z + v1.w;
#pragma unroll
    for (int o = 16; o; o >>= 1) s += __shfl_xor_sync(0xFFFFFFFFu, s, o);
    const float mu = s * (1.0f / 256.0f);

    float q = (v0.x - mu) * (v0.x - mu) + (v0.y - mu) * (v0.y - mu)
            + (v0.z - mu) * (v0.z - mu) + (v0.w - mu) * (v0.w - mu)
            + (v1.x - mu) * (v1.x - mu) + (v1.y - mu) * (v1.y - mu)
            + (v1.z - mu) * (v1.z - mu) + (v1.w - mu) * (v1.w - mu);
#pragma unroll
    for (int o = 16; o; o >>= 1) q += __shfl_xor_sync(0xFFFFFFFFu, q, o);
    const float rinv = rsqrtf(q * (1.0f / 256.0f) + 1e-5f);

    const float4* gp = (const float4*)g;
    const float4* bp = (const float4*)b;
    float4 g0 = gp[lane], g1 = gp[lane + 32];
    float4 b0 = bp[lane], b1 = bp[lane + 32];
    float4 y0, y1;
    y0.x = (v0.x - mu) * rinv * g0.x + b0.x;
    y0.y = (v0.y - mu) * rinv * g0.y + b0.y;
    y0.z = (v0.z - mu) * rinv * g0.z + b0.z;
    y0.w = (v0.w - mu) * rinv * g0.w + b0.w;
    y1.x = (v1.x - mu) * rinv * g1.x + b1.x;
    y1.y = (v1.y - mu) * rinv * g1.y + b1.y;
    y1.z = (v1.z - mu) * rinv * g1.z + b1.z;
    y1.w = (v1.w - mu) * rinv * g1.w + b1.w;
    float4* yp = (float4*)(Y + row * CDIM);
    yp[lane] = y0;
    yp[lane + 32] = y1;
}

// ===========================================================================
// Attention: per (window, head). Softmax 2 threads/row.
// ===========================================================================
__global__ void __launch_bounds__(128) attn_kernel(const float* __restrict__ qkv,
                                                   float* __restrict__ o) {
    __shared__ float sq[64][33];
    __shared__ float sk[64][33];
    __shared__ float sv[64][33];
    __shared__ float ss[64][65];

    const int tid = threadIdx.x;
    const int n = blockIdx.x >> 3;
    const int head = blockIdx.x & 7;
    const float* base = qkv + (long long)n * 64 * 768 + head * 32;

    {
        const int r0 = tid >> 3;
        const int c4 = (tid & 7) * 4;
#pragma unroll
        for (int it = 0; it < 4; it++) {
            const int r = r0 + it * 16;
            const float* rp = base + (long long)r * 768 + c4;
            float4 qv = *(const float4*)(rp);
            float4 kv = *(const float4*)(rp + 256);
            float4 vv = *(const float4*)(rp + 512);
            sq[r][c4 + 0] = qv.x; sq[r][c4 + 1] = qv.y; sq[r][c4 + 2] = qv.z; sq[r][c4 + 3] = qv.w;
            sk[r][c4 + 0] = kv.x; sk[r][c4 + 1] = kv.y; sk[r][c4 + 2] = kv.z; sk[r][c4 + 3] = kv.w;
            sv[r][c4 + 0] = vv.x; sv[r][c4 + 1] = vv.y; sv[r][c4 + 2] = vv.z; sv[r][c4 + 3] = vv.w;
        }
    }
    __syncthreads();

    {
        const int rg = tid >> 3;
        const int cgg = tid & 7;
        float acc[4][8];
#pragma unroll
        for (int i = 0; i < 4; i++)
#pragma unroll
            for (int j = 0; j < 8; j++) acc[i][j] = 0.0f;

#pragma unroll 4
        for (int kk = 0; kk < 32; kk++) {
            float a[4], bb[8];
#pragma unroll
            for (int i = 0; i < 4; i++) a[i] = sq[rg * 4 + i][kk];
#pragma unroll
            for (int j = 0; j < 8; j++) bb[j] = sk[cgg * 8 + j][kk];
#pragma unroll
            for (int i = 0; i < 4; i++)
#pragma unroll
                for (int j = 0; j < 8; j++) acc[i][j] += a[i] * bb[j];
        }
        const float scale = 0.17677669529663689f;
#pragma unroll
        for (int i = 0; i < 4; i++)
#pragma unroll
            for (int j = 0; j < 8; j++)
                ss[rg * 4 + i][cgg * 8 + j] = acc[i][j] * scale;
    }
    __syncthreads();

    {
        const int row = tid >> 1;
        const int hf = tid & 1;
        const int cb = hf * 32;
        const int ph = hf * 16;
        float mx = -1e30f;
#pragma unroll 8
        for (int j = 0; j < 32; j++) {
            const int c = cb + ((j + ph) & 31);
            mx = fmaxf(mx, ss[row][c]);
        }
        mx = fmaxf(mx, __shfl_xor_sync(0xFFFFFFFFu, mx, 1));
        float sum = 0.0f;
#pragma unroll 8
        for (int j = 0; j < 32; j++) {
            const int c = cb + ((j + ph) & 31);
            float e = expf(ss[row][c] - mx);
            ss[row][c] = e;
            sum += e;
        }
        sum += __shfl_xor_sync(0xFFFFFFFFu, sum, 1);
        const float inv = 1.0f / sum;
#pragma unroll 8
        for (int j = 0; j < 32; j++) {
            const int c = cb + ((j + ph) & 31);
            ss[row][c] *= inv;
        }
    }
    __syncthreads();

    {
        const int rg = tid >> 3;
        const int cgo = tid & 7;
        float acc[4][4];
#pragma unroll
        for (int i = 0; i < 4; i++)
#pragma unroll
            for (int j = 0; j < 4; j++) acc[i][j] = 0.0f;

#pragma unroll 4
        for (int kk = 0; kk < 64; kk++) {
            float a[4], bb[4];
#pragma unroll
            for (int i = 0; i < 4; i++) a[i] = ss[rg * 4 + i][kk];
#pragma unroll
            for (int j = 0; j < 4; j++) bb[j] = sv[kk][cgo * 4 + j];
#pragma unroll
            for (int i = 0; i < 4; i++)
#pragma unroll
                for (int j = 0; j < 4; j++) acc[i][j] += a[i] * bb[j];
        }
#pragma unroll
        for (int i = 0; i < 4; i++) {
            float4 r;
            r.x = acc[i][0]; r.y = acc[i][1]; r.z = acc[i][2]; r.w = acc[i][3];
            *(float4*)&o[((long long)n * 64 + rg * 4 + i) * CDIM + head * 32 + cgo * 4] = r;
        }
    }
}

// ===========================================================================
// Launch
// ===========================================================================
extern "C" void kernel_launch(void* const* d_in, const int* in_sizes, int n_in,
                              void* d_out, int out_size) {
    const float* x      = (const float*)d_in[0];
    const float* qkv_w  = (const float*)d_in[1];
    const float* qkv_b  = (const float*)d_in[2];
    const float* proj_w = (const float*)d_in[3];
    const float* proj_b = (const float*)d_in[4];
    const float* n1_g   = (const float*)d_in[5];
    const float* n1_b   = (const float*)d_in[6];
    const float* n2_g   = (const float*)d_in[7];
    const float* n2_b   = (const float*)d_in[8];
    const float* fc1_w  = (const float*)d_in[9];
    const float* fc1_b  = (const float*)d_in[10];
    const float* fc2_w  = (const float*)d_in[11];
    const float* fc2_b  = (const float*)d_in[12];
    float* out = (float*)d_out;

    float *tok, *y, *qkv, *o, *hid;
    cudaGetSymbolAddress((void**)&tok, g_tok);
    cudaGetSymbolAddress((void**)&y, g_y);
    cudaGetSymbolAddress((void**)&qkv, g_qkv);
    cudaGetSymbolAddress((void**)&o, g_o);
    cudaGetSymbolAddress((void**)&hid, g_hid);

    const int SMEM_GEMM = 3 * 32768;  // 3 stages x (16KB A + 16KB B) = 96KB
    cudaFuncSetAttribute(mma_gemm<0>, cudaFuncAttributeMaxDynamicSharedMemorySize, SMEM_GEMM);
    cudaFuncSetAttribute(mma_gemm<1>, cudaFuncAttributeMaxDynamicSharedMemorySize, SMEM_GEMM);
    cudaFuncSetAttribute(mma_gemm<2>, cudaFuncAttributeMaxDynamicSharedMemorySize, SMEM_GEMM);

    const dim3 tb(32, 8);
    const dim3 tg(W_ / 32, CDIM / 32, B_ * H_);
    const int MT = NTOK / 128;  // 2048 M-tiles

    // 1. window partition
    gather_kernel<<<tg, tb>>>(x, tok);
    // 2. LN1
    ln_kernel<<<NTOK / 8, 256>>>(tok, n1_g, n1_b, y);
    // 3. QKV gemm
    mma_gemm<0><<<dim3(MT, 768 / 128), 256, SMEM_GEMM>>>(y, qkv_w, qkv_b, nullptr, qkv, 768, 256);
    // 4. windowed attention
    attn_kernel<<<4096 * 8, 128>>>(qkv, o);
    // 5. proj gemm + residual -> tok
    mma_gemm<1><<<dim3(MT, 256 / 128), 256, SMEM_GEMM>>>(o, proj_w, proj_b, tok, tok, 256, 256);
    // 6. LN2
    ln_kernel<<<NTOK / 8, 256>>>(tok, n2_g, n2_b, y);
    // 7. fc1 gemm + GELU
    mma_gemm<2><<<dim3(MT, 1024 / 128), 256, SMEM_GEMM>>>(y, fc1_w, fc1_b, nullptr, hid, 1024, 256);
    // 8. fc2 gemm + residual -> y
    mma_gemm<1><<<dim3(MT, 256 / 128), 256, SMEM_GEMM>>>(hid, fc2_w, fc2_b, tok, y, 256, 1024);
    // 9. un-partition
    scatter_kernel<<<tg, tb>>>(y, out);
}

// round 7
// speedup vs baseline: 1.2944x; 1.0184x over previous
#include <cuda_runtime.h>
#include <math.h>
#include <cstdint>

// Problem constants
#define B_ 16
#define CDIM 256
#define H_ 128
#define W_ 128
#define NTOK 262144   // B*H*W tokens

// Scratch (device globals)
__device__ float g_tok[67108864];    // [NTOK, 256]
__device__ float g_y[67108864];      // [NTOK, 256]
__device__ float g_qkv[201326592];   // [NTOK, 768]
__device__ float g_o[67108864];      // [NTOK, 256]
__device__ float g_hid[268435456];   // [NTOK, 1024]

__device__ __forceinline__ float gelu_exact(float v) {
    return 0.5f * v * (1.0f + erff(v * 0.70710678118654752f));
}

__device__ __forceinline__ void cpa16(uint32_t dst, const float* src) {
    asm volatile("cp.async.cg.shared.global [%0], [%1], 16;" :: "r"(dst), "l"(src));
}
#define CP_COMMIT() asm volatile("cp.async.commit_group;" ::: "memory")
#define CP_WAIT0()  asm volatile("cp.async.wait_group 0;" ::: "memory")

// ===========================================================================
// TF32 mma.sync GEMM, cp.async 2-stage pipeline, 64KB smem -> 2 CTAs/SM.
// Raw fp32 bits fed to tf32 MMA (HW truncates mantissa).
// Out[M,N] = A[M,K] * W[N,K]^T + bias (+ epilogue)
// CTA tile 128x128, K-chunk 32, 8 warps (warp tile 64x32).
// EPI: 0=bias, 1=bias+residual, 2=bias+GELU
// ===========================================================================
template <int EPI>
__global__ void __launch_bounds__(256, 2) mma_gemm(const float* __restrict__ A,
                                                   const float* __restrict__ W,
                                                   const float* __restrict__ bias,
                                                   const float* __restrict__ R,
                                                   float* __restrict__ Out,
                                                   int N, int K) {
    extern __shared__ uint32_t sm[];
    uint32_t* As = sm;               // [2][4096] fp32 bits
    uint32_t* Bs = sm + 2 * 4096;    // [2][4096]

    const int tid = threadIdx.x;
    const int wid = tid >> 5;
    const int lane = tid & 31;
    const long long m0 = (long long)blockIdx.x * 128;
    const int n0 = blockIdx.y * 128;

    const int wm = (wid >> 2) * 64;
    const int wn = (wid & 3) * 32;
    const int lm = lane >> 2;
    const int lk = lane & 3;

    // global load mapping: row gr = tid>>1, 16 cols starting at (tid&1)*16
    const int gr = tid >> 1;
    const int gc = (tid & 1) * 16;
    const int swr = (gr & 7) * 4;

    const float* arow = A + (m0 + gr) * (long long)K + gc;
    const float* brow = W + (long long)(n0 + gr) * K + gc;

    const uint32_t as_b = (uint32_t)__cvta_generic_to_shared(As);
    const uint32_t bs_b = (uint32_t)__cvta_generic_to_shared(Bs);
    uint32_t soff[4];
#pragma unroll
    for (int j = 0; j < 4; j++)
        soff[j] = (uint32_t)(gr * 32 + ((gc + j * 4) ^ swr)) * 4u;

    const int KT = K >> 5;

    // ---- prologue: stage 0 ----
#pragma unroll
    for (int j = 0; j < 4; j++) {
        cpa16(as_b + soff[j], arow + j * 4);
        cpa16(bs_b + soff[j], brow + j * 4);
    }
    CP_COMMIT();

    float d[4][4][4];
#pragma unroll
    for (int i = 0; i < 4; i++)
#pragma unroll
        for (int j = 0; j < 4; j++)
#pragma unroll
            for (int q = 0; q < 4; q++) d[i][j][q] = 0.0f;

    for (int kt = 0; kt < KT; kt++) {
        const int cur = kt & 1;
        CP_WAIT0();            // stage cur's load complete (only pending group)
        __syncthreads();       // all warps done computing stage cur^1

        // issue next chunk into the other stage (overlaps compute below)
        if (kt + 1 < KT) {
            const int ko = (kt + 1) * 32;
            const uint32_t sb = (cur ^ 1) * 16384u;
#pragma unroll
            for (int j = 0; j < 4; j++) {
                cpa16(as_b + sb + soff[j], arow + ko + j * 4);
                cpa16(bs_b + sb + soff[j], brow + ko + j * 4);
            }
            CP_COMMIT();
        }

        // ---- compute from current stage ----
        const uint32_t* Ac = As + cur * 4096;
        const uint32_t* Bc = Bs + cur * 4096;
#pragma unroll
        for (int kk = 0; kk < 32; kk += 8) {
            uint32_t a[4][4];
#pragma unroll
            for (int mf = 0; mf < 4; mf++) {
                const int m = wm + mf * 16 + lm;
                const int sw = (m & 7) * 4;
                const int c0 = (kk + lk) ^ sw;
                const int c1 = (kk + 4 + lk) ^ sw;
                a[mf][0] = Ac[m * 32 + c0];
                a[mf][1] = Ac[(m + 8) * 32 + c0];
                a[mf][2] = Ac[m * 32 + c1];
                a[mf][3] = Ac[(m + 8) * 32 + c1];
            }
            uint32_t b[4][2];
#pragma unroll
            for (int nf = 0; nf < 4; nf++) {
                const int n = wn + nf * 8 + lm;
                const int sw = (n & 7) * 4;
                b[nf][0] = Bc[n * 32 + ((kk + lk) ^ sw)];
                b[nf][1] = Bc[n * 32 + ((kk + 4 + lk) ^ sw)];
            }
#pragma unroll
            for (int mf = 0; mf < 4; mf++)
#pragma unroll
                for (int nf = 0; nf < 4; nf++) {
                    asm volatile(
                        "mma.sync.aligned.m16n8k8.row.col.f32.tf32.tf32.f32 "
                        "{%0,%1,%2,%3}, {%4,%5,%6,%7}, {%8,%9}, {%0,%1,%2,%3};"
                        : "+f"(d[mf][nf][0]), "+f"(d[mf][nf][1]),
                          "+f"(d[mf][nf][2]), "+f"(d[mf][nf][3])
                        : "r"(a[mf][0]), "r"(a[mf][1]), "r"(a[mf][2]), "r"(a[mf][3]),
                          "r"(b[nf][0]), "r"(b[nf][1]));
                }
        }
    }

    // ---- epilogue ----
#pragma unroll
    for (int nf = 0; nf < 4; nf++) {
        const int gcol = n0 + wn + nf * 8 + 2 * lk;
        const float2 bv = *(const float2*)&bias[gcol];
#pragma unroll
        for (int mf = 0; mf < 4; mf++) {
            const long long row = m0 + wm + mf * 16 + lm;
            float2 v0, v1;
            v0.x = d[mf][nf][0] + bv.x;
            v0.y = d[mf][nf][1] + bv.y;
            v1.x = d[mf][nf][2] + bv.x;
            v1.y = d[mf][nf][3] + bv.y;
            if (EPI == 1) {
                float2 r0 = *(const float2*)&R[row * (long long)N + gcol];
                float2 r1 = *(const float2*)&R[(row + 8) * (long long)N + gcol];
                v0.x += r0.x; v0.y += r0.y;
                v1.x += r1.x; v1.y += r1.y;
            } else if (EPI == 2) {
                v0.x = gelu_exact(v0.x); v0.y = gelu_exact(v0.y);
                v1.x = gelu_exact(v1.x); v1.y = gelu_exact(v1.y);
            }
            *(float2*)&Out[row * (long long)N + gcol] = v0;
            *(float2*)&Out[(row + 8) * (long long)N + gcol] = v1;
        }
    }
}

// ===========================================================================
// Gather / Scatter / LayerNorm
// ===========================================================================
__global__ void __launch_bounds__(256) gather_kernel(const float* __restrict__ x,
                                                     float* __restrict__ tok) {
    __shared__ float tile[32][33];
    const int w0 = blockIdx.x * 32;
    const int c0 = blockIdx.y * 32;
    const int bh = blockIdx.z;
    const int b = bh >> 7, h = bh & 127;
    const int tx = threadIdx.x, ty = threadIdx.y;

    const float* xp = x + ((long long)(b * CDIM + c0)) * (H_ * W_) + h * W_ + w0;
#pragma unroll
    for (int i = 0; i < 4; i++) {
        int c = ty * 4 + i;
        tile[c][tx] = xp[(long long)c * (H_ * W_) + tx];
    }
    __syncthreads();

    const int wy = h >> 3, iy = h & 7;
#pragma unroll
    for (int i = 0; i < 4; i++) {
        int wloc = ty * 4 + i;
        int w = w0 + wloc;
        int wx = w >> 3, ix = w & 7;
        long long r = (((long long)(b * 16 + wy)) * 16 + wx) * 64 + iy * 8 + ix;
        tok[r * CDIM + c0 + tx] = tile[tx][wloc];
    }
}

__global__ void __launch_bounds__(256) scatter_kernel(const float* __restrict__ tok,
                                                      float* __restrict__ x) {
    __shared__ float tile[32][33];
    const int w0 = blockIdx.x * 32;
    const int c0 = blockIdx.y * 32;
    const int bh = blockIdx.z;
    const int b = bh >> 7, h = bh & 127;
    const int tx = threadIdx.x, ty = threadIdx.y;
    const int wy = h >> 3, iy = h & 7;

#pragma unroll
    for (int i = 0; i < 4; i++) {
        int wloc = ty * 4 + i;
        int w = w0 + wloc;
        int wx = w >> 3, ix = w & 7;
        long long r = (((long long)(b * 16 + wy)) * 16 + wx) * 64 + iy * 8 + ix;
        tile[tx][wloc] = tok[r * CDIM + c0 + tx];
    }
    __syncthreads();

    float* xp = x + ((long long)(b * CDIM + c0)) * (H_ * W_) + h * W_ + w0;
#pragma unroll
    for (int i = 0; i < 4; i++) {
        int c = ty * 4 + i;
        xp[(long long)c * (H_ * W_) + tx] = tile[c][tx];
    }
}

__global__ void __launch_bounds__(256) ln_kernel(const float* __restrict__ A,
                                                 const float* __restrict__ g,
                                                 const float* __restrict__ b,
                                                 float* __restrict__ Y) {
    const long long row = (long long)blockIdx.x * 8 + (threadIdx.x >> 5);
    const int lane = threadIdx.x & 31;
    const float4* ap = (const float4*)(A + row * CDIM);
    float4 v0 = ap[lane];
    float4 v1 = ap[lane + 32];

    float s = v0.x + v0.y + v0.z + v0.w + v1.x + v1.y + v1.z + v1.w;
#pragma unroll
    for (int o = 16; o; o >>= 1) s += __shfl_xor_sync(0xFFFFFFFFu, s, o);
    const float mu = s * (1.0f / 256.0f);

    float q = (v0.x - mu) * (v0.x - mu) + (v0.y - mu) * (v0.y - mu)
            + (v0.z - mu) * (v0.z - mu) + (v0.w - mu) * (v0.w - mu)
            + (v1.x - mu) * (v1.x - mu) + (v1.y - mu) * (v1.y - mu)
            + (v1.z - mu) * (v1.z - mu) + (v1.w - mu) * (v1.w - mu);
#pragma unroll
    for (int o = 16; o; o >>= 1) q += __shfl_xor_sync(0xFFFFFFFFu, q, o);
    const float rinv = rsqrtf(q * (1.0f / 256.0f) + 1e-5f);

    const float4* gp = (const float4*)g;
    const float4* bp = (const float4*)b;
    float4 g0 = gp[lane], g1 = gp[lane + 32];
    float4 b0 = bp[lane], b1 = bp[lane + 32];
    float4 y0, y1;
    y0.x = (v0.x - mu) * rinv * g0.x + b0.x;
    y0.y = (v0.y - mu) * rinv * g0.y + b0.y;
    y0.z = (v0.z - mu) * rinv * g0.z + b0.z;
    y0.w = (v0.w - mu) * rinv * g0.w + b0.w;
    y1.x = (v1.x - mu) * rinv * g1.x + b1.x;
    y1.y = (v1.y - mu) * rinv * g1.y + b1.y;
    y1.z = (v1.z - mu) * rinv * g1.z + b1.z;
    y1.w = (v1.w - mu) * rinv * g1.w + b1.w;
    float4* yp = (float4*)(Y + row * CDIM);
    yp[lane] = y0;
    yp[lane + 32] = y1;
}

// ===========================================================================
// Attention: per (window, head). float4 smem ops, K tile XOR-swizzled by
// 4*(row>>3) so per-thread K row loads hit distinct banks.
// ===========================================================================
__global__ void __launch_bounds__(128) attn_kernel(const float* __restrict__ qkv,
                                                   float* __restrict__ o) {
    __shared__ __align__(16) float sq[64][36];
    __shared__ __align__(16) float sk[64][36];
    __shared__ __align__(16) float sv[64][36];
    __shared__ __align__(16) float ss[64][68];

    const int tid = threadIdx.x;
    const int n = blockIdx.x >> 3;
    const int head = blockIdx.x & 7;
    const float* base = qkv + (long long)n * 64 * 768 + head * 32;

    {
        const int r0 = tid >> 3;          // 0..15
        const int c4 = (tid & 7) * 4;     // 0..28
#pragma unroll
        for (int it = 0; it < 4; it++) {
            const int r = r0 + it * 16;
            const float* rp = base + (long long)r * 768 + c4;
            float4 qv = *(const float4*)(rp);
            float4 kv = *(const float4*)(rp + 256);
            float4 vv = *(const float4*)(rp + 512);
            *(float4*)&sq[r][c4] = qv;
            *(float4*)&sk[r][c4 ^ (4 * ((r >> 3) & 7))] = kv;
            *(float4*)&sv[r][c4] = vv;
        }
    }
    __syncthreads();

    // scores: thread computes 4x8 tile; float4 over d
    {
        const int rg = tid >> 3;   // rows rg*4..+4
        const int cgg = tid & 7;   // cols cgg*8..+8
        const int kx = 4 * cgg;    // xor for K rows cgg*8+j  ((row>>3)==cgg)
        float acc[4][8];
#pragma unroll
        for (int i = 0; i < 4; i++)
#pragma unroll
            for (int j = 0; j < 8; j++) acc[i][j] = 0.0f;

#pragma unroll
        for (int kk = 0; kk < 32; kk += 4) {
            float4 q4[4], k4[8];
#pragma unroll
            for (int i = 0; i < 4; i++) q4[i] = *(const float4*)&sq[rg * 4 + i][kk];
#pragma unroll
            for (int j = 0; j < 8; j++) k4[j] = *(const float4*)&sk[cgg * 8 + j][kk ^ kx];
#pragma unroll
            for (int i = 0; i < 4; i++)
#pragma unroll
                for (int j = 0; j < 8; j++)
                    acc[i][j] += q4[i].x * k4[j].x + q4[i].y * k4[j].y
                               + q4[i].z * k4[j].z + q4[i].w * k4[j].w;
        }
        const float scale = 0.17677669529663689f;  // 1/sqrt(32)
#pragma unroll
        for (int i = 0; i < 4; i++) {
            float4 s0, s1;
            s0.x = acc[i][0] * scale; s0.y = acc[i][1] * scale;
            s0.z = acc[i][2] * scale; s0.w = acc[i][3] * scale;
            s1.x = acc[i][4] * scale; s1.y = acc[i][5] * scale;
            s1.z = acc[i][6] * scale; s1.w = acc[i][7] * scale;
            *(float4*)&ss[rg * 4 + i][cgg * 8] = s0;
            *(float4*)&ss[rg * 4 + i][cgg * 8 + 4] = s1;
        }
    }
    __syncthreads();

    // softmax: 2 threads per row, 32 cols each, phase-shifted
    {
        const int row = tid >> 1;
        const int hf = tid & 1;
        const int cb = hf * 32;
        const int ph = hf * 16;
        float mx = -1e30f;
#pragma unroll 8
        for (int j = 0; j < 32; j++) {
            const int c = cb + ((j + ph) & 31);
            mx = fmaxf(mx, ss[row][c]);
        }
        mx = fmaxf(mx, __shfl_xor_sync(0xFFFFFFFFu, mx, 1));
        float sum = 0.0f;
#pragma unroll 8
        for (int j = 0; j < 32; j++) {
            const int c = cb + ((j + ph) & 31);
            float e = expf(ss[row][c] - mx);
            ss[row][c] = e;
            sum += e;
        }
        sum += __shfl_xor_sync(0xFFFFFFFFu, sum, 1);
        const float inv = 1.0f / sum;
#pragma unroll 8
        for (int j = 0; j < 32; j++) {
            const int c = cb + ((j + ph) & 31);
            ss[row][c] *= inv;
        }
    }
    __syncthreads();

    // o = attn @ v : thread computes 4x4 tile; float4 over k
    {
        const int rg = tid >> 3;       // rows rg*4..+4
        const int cgo = tid & 7;       // cols cgo*4..+4
        float acc[4][4];
#pragma unroll
        for (int i = 0; i < 4; i++)
#pragma unroll
            for (int j = 0; j < 4; j++) acc[i][j] = 0.0f;

#pragma unroll
        for (int kk = 0; kk < 64; kk += 4) {
            float4 p4[4], v4[4];
#pragma unroll
            for (int i = 0; i < 4; i++) p4[i] = *(const float4*)&ss[rg * 4 + i][kk];
#pragma unroll
            for (int t = 0; t < 4; t++) v4[t] = *(const float4*)&sv[kk + t][cgo * 4];
#pragma unroll
            for (int i = 0; i < 4; i++) {
                acc[i][0] += p4[i].x * v4[0].x + p4[i].y * v4[1].x + p4[i].z * v4[2].x + p4[i].w * v4[3].x;
                acc[i][1] += p4[i].x * v4[0].y + p4[i].y * v4[1].y + p4[i].z * v4[2].y + p4[i].w * v4[3].y;
                acc[i][2] += p4[i].x * v4[0].z + p4[i].y * v4[1].z + p4[i].z * v4[2].z + p4[i].w * v4[3].z;
                acc[i][3] += p4[i].x * v4[0].w + p4[i].y * v4[1].w + p4[i].z * v4[2].w + p4[i].w * v4[3].w;
            }
        }
#pragma unroll
        for (int i = 0; i < 4; i++) {
            float4 r;
            r.x = acc[i][0]; r.y = acc[i][1]; r.z = acc[i][2]; r.w = acc[i][3];
            *(float4*)&o[((long long)n * 64 + rg * 4 + i) * CDIM + head * 32 + cgo * 4] = r;
        }
    }
}

// ===========================================================================
// Launch
// ===========================================================================
extern "C" void kernel_launch(void* const* d_in, const int* in_sizes, int n_in,
                              void* d_out, int out_size) {
    const float* x      = (const float*)d_in[0];
    const float* qkv_w  = (const float*)d_in[1];
    const float* qkv_b  = (const float*)d_in[2];
    const float* proj_w = (const float*)d_in[3];
    const float* proj_b = (const float*)d_in[4];
    const float* n1_g   = (const float*)d_in[5];
    const float* n1_b   = (const float*)d_in[6];
    const float* n2_g   = (const float*)d_in[7];
    const float* n2_b   = (const float*)d_in[8];
    const float* fc1_w  = (const float*)d_in[9];
    const float* fc1_b  = (const float*)d_in[10];
    const float* fc2_w  = (const float*)d_in[11];
    const float* fc2_b  = (const float*)d_in[12];
    float* out = (float*)d_out;

    float *tok, *y, *qkv, *o, *hid;
    cudaGetSymbolAddress((void**)&tok, g_tok);
    cudaGetSymbolAddress((void**)&y, g_y);
    cudaGetSymbolAddress((void**)&qkv, g_qkv);
    cudaGetSymbolAddress((void**)&o, g_o);
    cudaGetSymbolAddress((void**)&hid, g_hid);

    const int SMEM_GEMM = 2 * 32768;  // 2 stages x (16KB A + 16KB B) = 64KB
    cudaFuncSetAttribute(mma_gemm<0>, cudaFuncAttributeMaxDynamicSharedMemorySize, SMEM_GEMM);
    cudaFuncSetAttribute(mma_gemm<1>, cudaFuncAttributeMaxDynamicSharedMemorySize, SMEM_GEMM);
    cudaFuncSetAttribute(mma_gemm<2>, cudaFuncAttributeMaxDynamicSharedMemorySize, SMEM_GEMM);

    const dim3 tb(32, 8);
    const dim3 tg(W_ / 32, CDIM / 32, B_ * H_);
    const int MT = NTOK / 128;  // 2048 M-tiles

    // 1. window partition
    gather_kernel<<<tg, tb>>>(x, tok);
    // 2. LN1
    ln_kernel<<<NTOK / 8, 256>>>(tok, n1_g, n1_b, y);
    // 3. QKV gemm
    mma_gemm<0><<<dim3(MT, 768 / 128), 256, SMEM_GEMM>>>(y, qkv_w, qkv_b, nullptr, qkv, 768, 256);
    // 4. windowed attention
    attn_kernel<<<4096 * 8, 128>>>(qkv, o);
    // 5. proj gemm + residual -> tok
    mma_gemm<1><<<dim3(MT, 256 / 128), 256, SMEM_GEMM>>>(o, proj_w, proj_b, tok, tok, 256, 256);
    // 6. LN2
    ln_kernel<<<NTOK / 8, 256>>>(tok, n2_g, n2_b, y);
    // 7. fc1 gemm + GELU
    mma_gemm<2><<<dim3(MT, 1024 / 128), 256, SMEM_GEMM>>>(y, fc1_w, fc1_b, nullptr, hid, 1024, 256);
    // 8. fc2 gemm + residual -> y
    mma_gemm<1><<<dim3(MT, 256 / 128), 256, SMEM_GEMM>>>(hid, fc2_w, fc2_b, tok, y, 256, 1024);
    // 9. un-partition
    scatter_kernel<<<tg, tb>>>(y, out);
}

// round 8
// speedup vs baseline: 1.9780x; 1.5282x over previous
#include <cuda_runtime.h>
#include <cuda_fp16.h>
#include <math.h>
#include <cstdint>

// Problem constants
#define B_ 16
#define CDIM 256
#define H_ 128
#define W_ 128
#define NTOK 262144   // B*H*W tokens

// Scratch (device globals)
__device__ float  g_tok[67108864];     // [NTOK, 256] fp32 residual stream
__device__ float  g_y[67108864];       // [NTOK, 256] fp32 final pre-scatter
__device__ __half g_yh[67108864];      // [NTOK, 256] LN output fp16
__device__ __half g_qkvh[201326592];   // [NTOK, 768] fp16
__device__ __half g_oh[67108864];      // [NTOK, 256] fp16
__device__ __half g_hidh[268435456];   // [NTOK, 1024] fp16
__device__ __half g_wh[786432];        // qkv_w|proj_w|fc1_w|fc2_w fp16

#define WOFF_QKV 0
#define WOFF_PROJ 196608
#define WOFF_FC1 262144
#define WOFF_FC2 524288

__device__ __forceinline__ float gelu_exact(float v) {
    return 0.5f * v * (1.0f + erff(v * 0.70710678118654752f));
}

__device__ __forceinline__ void cpa16(uint32_t dst, const void* src) {
    asm volatile("cp.async.cg.shared.global [%0], [%1], 16;" :: "r"(dst), "l"(src));
}
#define CP_COMMIT() asm volatile("cp.async.commit_group;" ::: "memory")
#define CP_WAIT1()  asm volatile("cp.async.wait_group 1;" ::: "memory")

// ===========================================================================
// Weight conversion fp32 -> fp16 (all four matrices in one grid-stride kernel)
// ===========================================================================
__global__ void __launch_bounds__(256) cvt_weights(const float* __restrict__ qkv_w,
                                                   const float* __restrict__ proj_w,
                                                   const float* __restrict__ fc1_w,
                                                   const float* __restrict__ fc2_w) {
    for (int i = blockIdx.x * 256 + threadIdx.x; i < 786432; i += gridDim.x * 256) {
        float v;
        if (i < WOFF_PROJ)      v = qkv_w[i - WOFF_QKV];
        else if (i < WOFF_FC1)  v = proj_w[i - WOFF_PROJ];
        else if (i < WOFF_FC2)  v = fc1_w[i - WOFF_FC1];
        else                    v = fc2_w[i - WOFF_FC2];
        g_wh[i] = __float2half_rn(v);
    }
}

// ===========================================================================
// FP16 mma.sync m16n8k16 GEMM, cp.async 3-stage pipeline, 48KB smem, 2 CTA/SM.
// Out[M,N] = A[M,K] * W[N,K]^T + bias (+ epilogue)
// CTA tile 128x128, K-chunk 32 halves, 8 warps (warp tile 64x32).
// SMEM rows: 16 u32 (32 halves); XOR swizzle col ^= ((row>>1)&3)*4.
// EPI: 0=bias->f16, 1=bias+residual(fp32)->f32, 2=bias+GELU->f16
// ===========================================================================
template <int EPI>
__global__ void __launch_bounds__(256, 2) mma_gemm_h(const __half* __restrict__ A,
                                                     const __half* __restrict__ Wm,
                                                     const float* __restrict__ bias,
                                                     const float* __restrict__ R,
                                                     void* __restrict__ OutV,
                                                     int N, int K) {
    __shared__ uint32_t As[3 * 2048];
    __shared__ uint32_t Bs[3 * 2048];

    const int tid = threadIdx.x;
    const int wid = tid >> 5;
    const int lane = tid & 31;
    const long long m0 = (long long)blockIdx.x * 128;
    const int n0 = blockIdx.y * 128;

    const int wm = (wid >> 2) * 64;
    const int wn = (wid & 3) * 32;
    const int lm = lane >> 2;
    const int lk = lane & 3;

    // global->smem mapping: row gr = tid>>1; segs (tid&1)+2j (16B = 8 halves each)
    const int gr = tid >> 1;
    const int sw_g = ((gr >> 1) & 3) * 4;

    const __half* arow = A + (m0 + gr) * (long long)K;
    const __half* brow = Wm + (long long)(n0 + gr) * K;

    const uint32_t as_b = (uint32_t)__cvta_generic_to_shared(As);
    const uint32_t bs_b = (uint32_t)__cvta_generic_to_shared(Bs);
    uint32_t soff[2];
    int gseg[2];
#pragma unroll
    for (int j = 0; j < 2; j++) {
        const int seg = (tid & 1) + 2 * j;
        gseg[j] = seg * 8;  // halves offset in row
        soff[j] = (uint32_t)(gr * 16 + ((seg * 4) ^ sw_g)) * 4u;
    }

    const int KT = K >> 5;

    // ---- prologue: stages 0,1 ----
#pragma unroll
    for (int s = 0; s < 2; s++) {
        const int ko = s * 32;
        const uint32_t sb = s * 8192u;
#pragma unroll
        for (int j = 0; j < 2; j++) {
            cpa16(as_b + sb + soff[j], arow + ko + gseg[j]);
            cpa16(bs_b + sb + soff[j], brow + ko + gseg[j]);
        }
        CP_COMMIT();
    }

    float d[4][4][4];
#pragma unroll
    for (int i = 0; i < 4; i++)
#pragma unroll
        for (int j = 0; j < 4; j++)
#pragma unroll
            for (int q = 0; q < 4; q++) d[i][j][q] = 0.0f;

    int stage = 0;
    for (int kt = 0; kt < KT; kt++) {
        CP_WAIT1();
        __syncthreads();

        if (kt + 2 < KT) {
            const int s2 = stage + 2 >= 3 ? stage - 1 : stage + 2;
            const int ko = (kt + 2) * 32;
            const uint32_t sb = s2 * 8192u;
#pragma unroll
            for (int j = 0; j < 2; j++) {
                cpa16(as_b + sb + soff[j], arow + ko + gseg[j]);
                cpa16(bs_b + sb + soff[j], brow + ko + gseg[j]);
            }
        }
        CP_COMMIT();

        const uint32_t* Ac = As + stage * 2048;
        const uint32_t* Bc = Bs + stage * 2048;
#pragma unroll
        for (int ks = 0; ks < 2; ks++) {
            const int kkc = ks * 8;   // u32 col base of this k16 step
            uint32_t a[4][4];
#pragma unroll
            for (int mf = 0; mf < 4; mf++) {
                const int m = wm + mf * 16 + lm;
                const int sw = ((m >> 1) & 3) * 4;
                const int c0 = (kkc + lk) ^ sw;
                const int c1 = (kkc + lk + 4) ^ sw;
                a[mf][0] = Ac[m * 16 + c0];
                a[mf][1] = Ac[(m + 8) * 16 + c0];
                a[mf][2] = Ac[m * 16 + c1];
                a[mf][3] = Ac[(m + 8) * 16 + c1];
            }
            uint32_t b[4][2];
#pragma unroll
            for (int nf = 0; nf < 4; nf++) {
                const int n = wn + nf * 8 + lm;
                const int sw = ((n >> 1) & 3) * 4;
                b[nf][0] = Bc[n * 16 + ((kkc + lk) ^ sw)];
                b[nf][1] = Bc[n * 16 + ((kkc + lk + 4) ^ sw)];
            }
#pragma unroll
            for (int mf = 0; mf < 4; mf++)
#pragma unroll
                for (int nf = 0; nf < 4; nf++) {
                    asm volatile(
                        "mma.sync.aligned.m16n8k16.row.col.f32.f16.f16.f32 "
                        "{%0,%1,%2,%3}, {%4,%5,%6,%7}, {%8,%9}, {%0,%1,%2,%3};"
                        : "+f"(d[mf][nf][0]), "+f"(d[mf][nf][1]),
                          "+f"(d[mf][nf][2]), "+f"(d[mf][nf][3])
                        : "r"(a[mf][0]), "r"(a[mf][1]), "r"(a[mf][2]), "r"(a[mf][3]),
                          "r"(b[nf][0]), "r"(b[nf][1]));
                }
        }
        stage = stage + 1 >= 3 ? 0 : stage + 1;
    }

    // ---- epilogue ----
#pragma unroll
    for (int nf = 0; nf < 4; nf++) {
        const int gcol = n0 + wn + nf * 8 + 2 * lk;
        const float2 bv = *(const float2*)&bias[gcol];
#pragma unroll
        for (int mf = 0; mf < 4; mf++) {
            const long long row = m0 + wm + mf * 16 + lm;
            float2 v0, v1;
            v0.x = d[mf][nf][0] + bv.x;
            v0.y = d[mf][nf][1] + bv.y;
            v1.x = d[mf][nf][2] + bv.x;
            v1.y = d[mf][nf][3] + bv.y;
            if (EPI == 1) {
                float2 r0 = *(const float2*)&R[row * (long long)N + gcol];
                float2 r1 = *(const float2*)&R[(row + 8) * (long long)N + gcol];
                v0.x += r0.x; v0.y += r0.y;
                v1.x += r1.x; v1.y += r1.y;
                float* Out = (float*)OutV;
                *(float2*)&Out[row * (long long)N + gcol] = v0;
                *(float2*)&Out[(row + 8) * (long long)N + gcol] = v1;
            } else {
                if (EPI == 2) {
                    v0.x = gelu_exact(v0.x); v0.y = gelu_exact(v0.y);
                    v1.x = gelu_exact(v1.x); v1.y = gelu_exact(v1.y);
                }
                __half* Out = (__half*)OutV;
                *(__half2*)&Out[row * (long long)N + gcol] = __floats2half2_rn(v0.x, v0.y);
                *(__half2*)&Out[(row + 8) * (long long)N + gcol] = __floats2half2_rn(v1.x, v1.y);
            }
        }
    }
}

// ===========================================================================
// Gather / Scatter (fp32, unchanged)
// ===========================================================================
__global__ void __launch_bounds__(256) gather_kernel(const float* __restrict__ x,
                                                     float* __restrict__ tok) {
    __shared__ float tile[32][33];
    const int w0 = blockIdx.x * 32;
    const int c0 = blockIdx.y * 32;
    const int bh = blockIdx.z;
    const int b = bh >> 7, h = bh & 127;
    const int tx = threadIdx.x, ty = threadIdx.y;

    const float* xp = x + ((long long)(b * CDIM + c0)) * (H_ * W_) + h * W_ + w0;
#pragma unroll
    for (int i = 0; i < 4; i++) {
        int c = ty * 4 + i;
        tile[c][tx] = xp[(long long)c * (H_ * W_) + tx];
    }
    __syncthreads();

    const int wy = h >> 3, iy = h & 7;
#pragma unroll
    for (int i = 0; i < 4; i++) {
        int wloc = ty * 4 + i;
        int w = w0 + wloc;
        int wx = w >> 3, ix = w & 7;
        long long r = (((long long)(b * 16 + wy)) * 16 + wx) * 64 + iy * 8 + ix;
        tok[r * CDIM + c0 + tx] = tile[tx][wloc];
    }
}

__global__ void __launch_bounds__(256) scatter_kernel(const float* __restrict__ tok,
                                                      float* __restrict__ x) {
    __shared__ float tile[32][33];
    const int w0 = blockIdx.x * 32;
    const int c0 = blockIdx.y * 32;
    const int bh = blockIdx.z;
    const int b = bh >> 7, h = bh & 127;
    const int tx = threadIdx.x, ty = threadIdx.y;
    const int wy = h >> 3, iy = h & 7;

#pragma unroll
    for (int i = 0; i < 4; i++) {
        int wloc = ty * 4 + i;
        int w = w0 + wloc;
        int wx = w >> 3, ix = w & 7;
        long long r = (((long long)(b * 16 + wy)) * 16 + wx) * 64 + iy * 8 + ix;
        tile[tx][wloc] = tok[r * CDIM + c0 + tx];
    }
    __syncthreads();

    float* xp = x + ((long long)(b * CDIM + c0)) * (H_ * W_) + h * W_ + w0;
#pragma unroll
    for (int i = 0; i < 4; i++) {
        int c = ty * 4 + i;
        xp[(long long)c * (H_ * W_) + tx] = tile[c][tx];
    }
}

// ===========================================================================
// LayerNorm: fp32 in -> fp16 out
// ===========================================================================
__global__ void __launch_bounds__(256) ln_kernel(const float* __restrict__ A,
                                                 const float* __restrict__ g,
                                                 const float* __restrict__ b,
                                                 __half* __restrict__ Y) {
    const long long row = (long long)blockIdx.x * 8 + (threadIdx.x >> 5);
    const int lane = threadIdx.x & 31;
    const float4* ap = (const float4*)(A + row * CDIM);
    float4 v0 = ap[lane];
    float4 v1 = ap[lane + 32];

    float s = v0.x + v0.y + v0.z + v0.w + v1.x + v1.y + v1.z + v1.w;
#pragma unroll
    for (int o = 16; o; o >>= 1) s += __shfl_xor_sync(0xFFFFFFFFu, s, o);
    const float mu = s * (1.0f / 256.0f);

    float q = (v0.x - mu) * (v0.x - mu) + (v0.y - mu) * (v0.y - mu)
            + (v0.z - mu) * (v0.z - mu) + (v0.w - mu) * (v0.w - mu)
            + (v1.x - mu) * (v1.x - mu) + (v1.y - mu) * (v1.y - mu)
            + (v1.z - mu) * (v1.z - mu) + (v1.w - mu) * (v1.w - mu);
#pragma unroll
    for (int o = 16; o; o >>= 1) q += __shfl_xor_sync(0xFFFFFFFFu, q, o);
    const float rinv = rsqrtf(q * (1.0f / 256.0f) + 1e-5f);

    const float4* gp = (const float4*)g;
    const float4* bp = (const float4*)b;
    float4 g0 = gp[lane], g1 = gp[lane + 32];
    float4 b0 = bp[lane], b1 = bp[lane + 32];

    __half* yrow = Y + row * CDIM;
    *(__half2*)&yrow[lane * 4]       = __floats2half2_rn((v0.x - mu) * rinv * g0.x + b0.x,
                                                         (v0.y - mu) * rinv * g0.y + b0.y);
    *(__half2*)&yrow[lane * 4 + 2]   = __floats2half2_rn((v0.z - mu) * rinv * g0.z + b0.z,
                                                         (v0.w - mu) * rinv * g0.w + b0.w);
    *(__half2*)&yrow[lane * 4 + 128] = __floats2half2_rn((v1.x - mu) * rinv * g1.x + b1.x,
                                                         (v1.y - mu) * rinv * g1.y + b1.y);
    *(__half2*)&yrow[lane * 4 + 130] = __floats2half2_rn((v1.z - mu) * rinv * g1.z + b1.z,
                                                         (v1.w - mu) * rinv * g1.w + b1.w);
}

// ===========================================================================
// Attention: per (window, head). fp16 qkv in, fp32 smem compute, fp16 o out.
// ===========================================================================
__global__ void __launch_bounds__(128) attn_kernel(const __half* __restrict__ qkv,
                                                   __half* __restrict__ o) {
    __shared__ __align__(16) float sq[64][36];
    __shared__ __align__(16) float sk[64][36];
    __shared__ __align__(16) float sv[64][36];
    __shared__ __align__(16) float ss[64][68];

    const int tid = threadIdx.x;
    const int n = blockIdx.x >> 3;
    const int head = blockIdx.x & 7;
    const __half* base = qkv + (long long)n * 64 * 768 + head * 32;

    {
        const int r0 = tid >> 3;
        const int c4 = (tid & 7) * 4;
#pragma unroll
        for (int it = 0; it < 4; it++) {
            const int r = r0 + it * 16;
            const __half2* rp = (const __half2*)(base + (long long)r * 768 + c4);
            float2 q0 = __half22float2(rp[0]);
            float2 q1 = __half22float2(rp[1]);
            float2 k0 = __half22float2(rp[128]);
            float2 k1 = __half22float2(rp[129]);
            float2 v0 = __half22float2(rp[256]);
            float2 v1 = __half22float2(rp[257]);
            const int kc = c4 ^ (4 * ((r >> 3) & 7));
            sq[r][c4] = q0.x; sq[r][c4 + 1] = q0.y; sq[r][c4 + 2] = q1.x; sq[r][c4 + 3] = q1.y;
            sk[r][kc] = k0.x; sk[r][kc + 1] = k0.y; sk[r][kc + 2] = k1.x; sk[r][kc + 3] = k1.y;
            sv[r][c4] = v0.x; sv[r][c4 + 1] = v0.y; sv[r][c4 + 2] = v1.x; sv[r][c4 + 3] = v1.y;
        }
    }
    __syncthreads();

    {
        const int rg = tid >> 3;
        const int cgg = tid & 7;
        const int kx = 4 * cgg;
        float acc[4][8];
#pragma unroll
        for (int i = 0; i < 4; i++)
#pragma unroll
            for (int j = 0; j < 8; j++) acc[i][j] = 0.0f;

#pragma unroll
        for (int kk = 0; kk < 32; kk += 4) {
            float4 q4[4], k4[8];
#pragma unroll
            for (int i = 0; i < 4; i++) q4[i] = *(const float4*)&sq[rg * 4 + i][kk];
#pragma unroll
            for (int j = 0; j < 8; j++) k4[j] = *(const float4*)&sk[cgg * 8 + j][kk ^ kx];
#pragma unroll
            for (int i = 0; i < 4; i++)
#pragma unroll
                for (int j = 0; j < 8; j++)
                    acc[i][j] += q4[i].x * k4[j].x + q4[i].y * k4[j].y
                               + q4[i].z * k4[j].z + q4[i].w * k4[j].w;
        }
        const float scale = 0.17677669529663689f;
#pragma unroll
        for (int i = 0; i < 4; i++) {
            float4 s0, s1;
            s0.x = acc[i][0] * scale; s0.y = acc[i][1] * scale;
            s0.z = acc[i][2] * scale; s0.w = acc[i][3] * scale;
            s1.x = acc[i][4] * scale; s1.y = acc[i][5] * scale;
            s1.z = acc[i][6] * scale; s1.w = acc[i][7] * scale;
            *(float4*)&ss[rg * 4 + i][cgg * 8] = s0;
            *(float4*)&ss[rg * 4 + i][cgg * 8 + 4] = s1;
        }
    }
    __syncthreads();

    {
        const int row = tid >> 1;
        const int hf = tid & 1;
        const int cb = hf * 32;
        const int ph = hf * 16;
        float mx = -1e30f;
#pragma unroll 8
        for (int j = 0; j < 32; j++) {
            const int c = cb + ((j + ph) & 31);
            mx = fmaxf(mx, ss[row][c]);
        }
        mx = fmaxf(mx, __shfl_xor_sync(0xFFFFFFFFu, mx, 1));
        float sum = 0.0f;
#pragma unroll 8
        for (int j = 0; j < 32; j++) {
            const int c = cb + ((j + ph) & 31);
            float e = expf(ss[row][c] - mx);
            ss[row][c] = e;
            sum += e;
        }
        sum += __shfl_xor_sync(0xFFFFFFFFu, sum, 1);
        const float inv = 1.0f / sum;
#pragma unroll 8
        for (int j = 0; j < 32; j++) {
            const int c = cb + ((j + ph) & 31);
            ss[row][c] *= inv;
        }
    }
    __syncthreads();

    {
        const int rg = tid >> 3;
        const int cgo = tid & 7;
        float acc[4][4];
#pragma unroll
        for (int i = 0; i < 4; i++)
#pragma unroll
            for (int j = 0; j < 4; j++) acc[i][j] = 0.0f;

#pragma unroll
        for (int kk = 0; kk < 64; kk += 4) {
            float4 p4[4], v4[4];
#pragma unroll
            for (int i = 0; i < 4; i++) p4[i] = *(const float4*)&ss[rg * 4 + i][kk];
#pragma unroll
            for (int t = 0; t < 4; t++) v4[t] = *(const float4*)&sv[kk + t][cgo * 4];
#pragma unroll
            for (int i = 0; i < 4; i++) {
                acc[i][0] += p4[i].x * v4[0].x + p4[i].y * v4[1].x + p4[i].z * v4[2].x + p4[i].w * v4[3].x;
                acc[i][1] += p4[i].x * v4[0].y + p4[i].y * v4[1].y + p4[i].z * v4[2].y + p4[i].w * v4[3].y;
                acc[i][2] += p4[i].x * v4[0].z + p4[i].y * v4[1].z + p4[i].z * v4[2].z + p4[i].w * v4[3].z;
                acc[i][3] += p4[i].x * v4[0].w + p4[i].y * v4[1].w + p4[i].z * v4[2].w + p4[i].w * v4[3].w;
            }
        }
#pragma unroll
        for (int i = 0; i < 4; i++) {
            __half* orow = o + ((long long)n * 64 + rg * 4 + i) * CDIM + head * 32 + cgo * 4;
            *(__half2*)&orow[0] = __floats2half2_rn(acc[i][0], acc[i][1]);
            *(__half2*)&orow[2] = __floats2half2_rn(acc[i][2], acc[i][3]);
        }
    }
}

// ===========================================================================
// Launch
// ===========================================================================
extern "C" void kernel_launch(void* const* d_in, const int* in_sizes, int n_in,
                              void* d_out, int out_size) {
    const float* x      = (const float*)d_in[0];
    const float* qkv_w  = (const float*)d_in[1];
    const float* qkv_b  = (const float*)d_in[2];
    const float* proj_w = (const float*)d_in[3];
    const float* proj_b = (const float*)d_in[4];
    const float* n1_g   = (const float*)d_in[5];
    const float* n1_b   = (const float*)d_in[6];
    const float* n2_g   = (const float*)d_in[7];
    const float* n2_b   = (const float*)d_in[8];
    const float* fc1_w  = (const float*)d_in[9];
    const float* fc1_b  = (const float*)d_in[10];
    const float* fc2_w  = (const float*)d_in[11];
    const float* fc2_b  = (const float*)d_in[12];
    float* out = (float*)d_out;

    float *tok, *y;
    __half *yh, *qkvh, *oh, *hidh, *wh;
    cudaGetSymbolAddress((void**)&tok, g_tok);
    cudaGetSymbolAddress((void**)&y, g_y);
    cudaGetSymbolAddress((void**)&yh, g_yh);
    cudaGetSymbolAddress((void**)&qkvh, g_qkvh);
    cudaGetSymbolAddress((void**)&oh, g_oh);
    cudaGetSymbolAddress((void**)&hidh, g_hidh);
    cudaGetSymbolAddress((void**)&wh, g_wh);

    const dim3 tb(32, 8);
    const dim3 tg(W_ / 32, CDIM / 32, B_ * H_);
    const int MT = NTOK / 128;  // 2048 M-tiles

    // 0. weights -> fp16
    cvt_weights<<<512, 256>>>(qkv_w, proj_w, fc1_w, fc2_w);
    // 1. window partition
    gather_kernel<<<tg, tb>>>(x, tok);
    // 2. LN1 -> fp16
    ln_kernel<<<NTOK / 8, 256>>>(tok, n1_g, n1_b, yh);
    // 3. QKV gemm (fp16)
    mma_gemm_h<0><<<dim3(MT, 6), 256>>>(yh, wh + WOFF_QKV, qkv_b, nullptr, qkvh, 768, 256);
    // 4. windowed attention
    attn_kernel<<<4096 * 8, 128>>>(qkvh, oh);
    // 5. proj gemm + residual -> tok (fp32)
    mma_gemm_h<1><<<dim3(MT, 2), 256>>>(oh, wh + WOFF_PROJ, proj_b, tok, tok, 256, 256);
    // 6. LN2 -> fp16
    ln_kernel<<<NTOK / 8, 256>>>(tok, n2_g, n2_b, yh);
    // 7. fc1 gemm + GELU -> fp16
    mma_gemm_h<2><<<dim3(MT, 8), 256>>>(yh, wh + WOFF_FC1, fc1_b, nullptr, hidh, 1024, 256);
    // 8. fc2 gemm + residual -> y (fp32)
    mma_gemm_h<1><<<dim3(MT, 2), 256>>>(hidh, wh + WOFF_FC2, fc2_b, tok, y, 256, 1024);
    // 9. un-partition
    scatter_kernel<<<tg, tb>>>(y, out);
}

// round 10
// speedup vs baseline: 2.3763x; 1.2013x over previous
#include <cuda_runtime.h>
#include <cuda_fp16.h>
#include <math.h>
#include <cstdint>

// Problem constants
#define B_ 16
#define CDIM 256
#define H_ 128
#define W_ 128
#define NTOK 262144   // B*H*W tokens

// Scratch (device globals)
__device__ float  g_tok[67108864];     // [NTOK, 256] fp32 residual stream
__device__ float  g_y[67108864];       // [NTOK, 256] fp32 final pre-scatter
__device__ __half g_yh[67108864];      // [NTOK, 256] LN output fp16
__device__ __half g_qkvh[201326592];   // [NTOK, 768] fp16
__device__ __half g_oh[67108864];      // [NTOK, 256] fp16
__device__ __half g_hidh[268435456];   // [NTOK, 1024] fp16
__device__ __half g_wh[786432];        // qkv_w|proj_w|fc1_w|fc2_w fp16

#define WOFF_QKV 0
#define WOFF_PROJ 196608
#define WOFF_FC1 262144
#define WOFF_FC2 524288

__device__ __forceinline__ float gelu_exact(float v) {
    return 0.5f * v * (1.0f + erff(v * 0.70710678118654752f));
}

__device__ __forceinline__ uint32_t h2_u32(__half2 v) {
    return *reinterpret_cast<uint32_t*>(&v);
}

__device__ __forceinline__ void cpa16(uint32_t dst, const void* src) {
    asm volatile("cp.async.cg.shared.global [%0], [%1], 16;" :: "r"(dst), "l"(src));
}
#define CP_COMMIT() asm volatile("cp.async.commit_group;" ::: "memory")
#define CP_WAIT1()  asm volatile("cp.async.wait_group 1;" ::: "memory")

#define MMA_H(dd, a0, a1, a2, a3, b0, b1) \
    asm volatile( \
        "mma.sync.aligned.m16n8k16.row.col.f32.f16.f16.f32 " \
        "{%0,%1,%2,%3}, {%4,%5,%6,%7}, {%8,%9}, {%0,%1,%2,%3};" \
        : "+f"((dd)[0]), "+f"((dd)[1]), "+f"((dd)[2]), "+f"((dd)[3]) \
        : "r"(a0), "r"(a1), "r"(a2), "r"(a3), "r"(b0), "r"(b1))

// ===========================================================================
// Weight conversion fp32 -> fp16
// ===========================================================================
__global__ void __launch_bounds__(256) cvt_weights(const float* __restrict__ qkv_w,
                                                   const float* __restrict__ proj_w,
                                                   const float* __restrict__ fc1_w,
                                                   const float* __restrict__ fc2_w) {
    for (int i = blockIdx.x * 256 + threadIdx.x; i < 786432; i += gridDim.x * 256) {
        float v;
        if (i < WOFF_PROJ)      v = qkv_w[i - WOFF_QKV];
        else if (i < WOFF_FC1)  v = proj_w[i - WOFF_PROJ];
        else if (i < WOFF_FC2)  v = fc1_w[i - WOFF_FC1];
        else                    v = fc2_w[i - WOFF_FC2];
        g_wh[i] = __float2half_rn(v);
    }
}

// ===========================================================================
// FP16 mma.sync GEMM (unchanged from R8)
// ===========================================================================
template <int EPI>
__global__ void __launch_bounds__(256, 2) mma_gemm_h(const __half* __restrict__ A,
                                                     const __half* __restrict__ Wm,
                                                     const float* __restrict__ bias,
                                                     const float* __restrict__ R,
                                                     void* __restrict__ OutV,
                                                     int N, int K) {
    __shared__ uint32_t As[3 * 2048];
    __shared__ uint32_t Bs[3 * 2048];

    const int tid = threadIdx.x;
    const int wid = tid >> 5;
    const int lane = tid & 31;
    const long long m0 = (long long)blockIdx.x * 128;
    const int n0 = blockIdx.y * 128;

    const int wm = (wid >> 2) * 64;
    const int wn = (wid & 3) * 32;
    const int lm = lane >> 2;
    const int lk = lane & 3;

    const int gr = tid >> 1;
    const int sw_g = ((gr >> 1) & 3) * 4;

    const __half* arow = A + (m0 + gr) * (long long)K;
    const __half* brow = Wm + (long long)(n0 + gr) * K;

    const uint32_t as_b = (uint32_t)__cvta_generic_to_shared(As);
    const uint32_t bs_b = (uint32_t)__cvta_generic_to_shared(Bs);
    uint32_t soff[2];
    int gseg[2];
#pragma unroll
    for (int j = 0; j < 2; j++) {
        const int seg = (tid & 1) + 2 * j;
        gseg[j] = seg * 8;
        soff[j] = (uint32_t)(gr * 16 + ((seg * 4) ^ sw_g)) * 4u;
    }

    const int KT = K >> 5;

#pragma unroll
    for (int s = 0; s < 2; s++) {
        const int ko = s * 32;
        const uint32_t sb = s * 8192u;
#pragma unroll
        for (int j = 0; j < 2; j++) {
            cpa16(as_b + sb + soff[j], arow + ko + gseg[j]);
            cpa16(bs_b + sb + soff[j], brow + ko + gseg[j]);
        }
        CP_COMMIT();
    }

    float d[4][4][4];
#pragma unroll
    for (int i = 0; i < 4; i++)
#pragma unroll
        for (int j = 0; j < 4; j++)
#pragma unroll
            for (int q = 0; q < 4; q++) d[i][j][q] = 0.0f;

    int stage = 0;
    for (int kt = 0; kt < KT; kt++) {
        CP_WAIT1();
        __syncthreads();

        if (kt + 2 < KT) {
            const int s2 = stage + 2 >= 3 ? stage - 1 : stage + 2;
            const int ko = (kt + 2) * 32;
            const uint32_t sb = s2 * 8192u;
#pragma unroll
            for (int j = 0; j < 2; j++) {
                cpa16(as_b + sb + soff[j], arow + ko + gseg[j]);
                cpa16(bs_b + sb + soff[j], brow + ko + gseg[j]);
            }
        }
        CP_COMMIT();

        const uint32_t* Ac = As + stage * 2048;
        const uint32_t* Bc = Bs + stage * 2048;
#pragma unroll
        for (int ks = 0; ks < 2; ks++) {
            const int kkc = ks * 8;
            uint32_t a[4][4];
#pragma unroll
            for (int mf = 0; mf < 4; mf++) {
                const int m = wm + mf * 16 + lm;
                const int sw = ((m >> 1) & 3) * 4;
                const int c0 = (kkc + lk) ^ sw;
                const int c1 = (kkc + lk + 4) ^ sw;
                a[mf][0] = Ac[m * 16 + c0];
                a[mf][1] = Ac[(m + 8) * 16 + c0];
                a[mf][2] = Ac[m * 16 + c1];
                a[mf][3] = Ac[(m + 8) * 16 + c1];
            }
            uint32_t b[4][2];
#pragma unroll
            for (int nf = 0; nf < 4; nf++) {
                const int n = wn + nf * 8 + lm;
                const int sw = ((n >> 1) & 3) * 4;
                b[nf][0] = Bc[n * 16 + ((kkc + lk) ^ sw)];
                b[nf][1] = Bc[n * 16 + ((kkc + lk + 4) ^ sw)];
            }
#pragma unroll
            for (int mf = 0; mf < 4; mf++)
#pragma unroll
                for (int nf = 0; nf < 4; nf++)
                    MMA_H(d[mf][nf], a[mf][0], a[mf][1], a[mf][2], a[mf][3],
                          b[nf][0], b[nf][1]);
        }
        stage = stage + 1 >= 3 ? 0 : stage + 1;
    }

#pragma unroll
    for (int nf = 0; nf < 4; nf++) {
        const int gcol = n0 + wn + nf * 8 + 2 * lk;
        const float2 bv = *(const float2*)&bias[gcol];
#pragma unroll
        for (int mf = 0; mf < 4; mf++) {
            const long long row = m0 + wm + mf * 16 + lm;
            float2 v0, v1;
            v0.x = d[mf][nf][0] + bv.x;
            v0.y = d[mf][nf][1] + bv.y;
            v1.x = d[mf][nf][2] + bv.x;
            v1.y = d[mf][nf][3] + bv.y;
            if (EPI == 1) {
                float2 r0 = *(const float2*)&R[row * (long long)N + gcol];
                float2 r1 = *(const float2*)&R[(row + 8) * (long long)N + gcol];
                v0.x += r0.x; v0.y += r0.y;
                v1.x += r1.x; v1.y += r1.y;
                float* Out = (float*)OutV;
                *(float2*)&Out[row * (long long)N + gcol] = v0;
                *(float2*)&Out[(row + 8) * (long long)N + gcol] = v1;
            } else {
                if (EPI == 2) {
                    v0.x = gelu_exact(v0.x); v0.y = gelu_exact(v0.y);
                    v1.x = gelu_exact(v1.x); v1.y = gelu_exact(v1.y);
                }
                __half* Out = (__half*)OutV;
                *(__half2*)&Out[row * (long long)N + gcol] = __floats2half2_rn(v0.x, v0.y);
                *(__half2*)&Out[(row + 8) * (long long)N + gcol] = __floats2half2_rn(v1.x, v1.y);
            }
        }
    }
}

// ===========================================================================
// Gather / Scatter (fp32, unchanged)
// ===========================================================================
__global__ void __launch_bounds__(256) gather_kernel(const float* __restrict__ x,
                                                     float* __restrict__ tok) {
    __shared__ float tile[32][33];
    const int w0 = blockIdx.x * 32;
    const int c0 = blockIdx.y * 32;
    const int bh = blockIdx.z;
    const int b = bh >> 7, h = bh & 127;
    const int tx = threadIdx.x, ty = threadIdx.y;

    const float* xp = x + ((long long)(b * CDIM + c0)) * (H_ * W_) + h * W_ + w0;
#pragma unroll
    for (int i = 0; i < 4; i++) {
        int c = ty * 4 + i;
        tile[c][tx] = xp[(long long)c * (H_ * W_) + tx];
    }
    __syncthreads();

    const int wy = h >> 3, iy = h & 7;
#pragma unroll
    for (int i = 0; i < 4; i++) {
        int wloc = ty * 4 + i;
        int w = w0 + wloc;
        int wx = w >> 3, ix = w & 7;
        long long r = (((long long)(b * 16 + wy)) * 16 + wx) * 64 + iy * 8 + ix;
        tok[r * CDIM + c0 + tx] = tile[tx][wloc];
    }
}

__global__ void __launch_bounds__(256) scatter_kernel(const float* __restrict__ tok,
                                                      float* __restrict__ x) {
    __shared__ float tile[32][33];
    const int w0 = blockIdx.x * 32;
    const int c0 = blockIdx.y * 32;
    const int bh = blockIdx.z;
    const int b = bh >> 7, h = bh & 127;
    const int tx = threadIdx.x, ty = threadIdx.y;
    const int wy = h >> 3, iy = h & 7;

#pragma unroll
    for (int i = 0; i < 4; i++) {
        int wloc = ty * 4 + i;
        int w = w0 + wloc;
        int wx = w >> 3, ix = w & 7;
        long long r = (((long long)(b * 16 + wy)) * 16 + wx) * 64 + iy * 8 + ix;
        tile[tx][wloc] = tok[r * CDIM + c0 + tx];
    }
    __syncthreads();

    float* xp = x + ((long long)(b * CDIM + c0)) * (H_ * W_) + h * W_ + w0;
#pragma unroll
    for (int i = 0; i < 4; i++) {
        int c = ty * 4 + i;
        xp[(long long)c * (H_ * W_) + tx] = tile[c][tx];
    }
}

// ===========================================================================
// LayerNorm: fp32 in -> fp16 out (unchanged)
// ===========================================================================
__global__ void __launch_bounds__(256) ln_kernel(const float* __restrict__ A,
                                                 const float* __restrict__ g,
                                                 const float* __restrict__ b,
                                                 __half* __restrict__ Y) {
    const long long row = (long long)blockIdx.x * 8 + (threadIdx.x >> 5);
    const int lane = threadIdx.x & 31;
    const float4* ap = (const float4*)(A + row * CDIM);
    float4 v0 = ap[lane];
    float4 v1 = ap[lane + 32];

    float s = v0.x + v0.y + v0.z + v0.w + v1.x + v1.y + v1.z + v1.w;
#pragma unroll
    for (int o = 16; o; o >>= 1) s += __shfl_xor_sync(0xFFFFFFFFu, s, o);
    const float mu = s * (1.0f / 256.0f);

    float q = (v0.x - mu) * (v0.x - mu) + (v0.y - mu) * (v0.y - mu)
            + (v0.z - mu) * (v0.z - mu) + (v0.w - mu) * (v0.w - mu)
            + (v1.x - mu) * (v1.x - mu) + (v1.y - mu) * (v1.y - mu)
            + (v1.z - mu) * (v1.z - mu) + (v1.w - mu) * (v1.w - mu);
#pragma unroll
    for (int o = 16; o; o >>= 1) q += __shfl_xor_sync(0xFFFFFFFFu, q, o);
    const float rinv = rsqrtf(q * (1.0f / 256.0f) + 1e-5f);

    const float4* gp = (const float4*)g;
    const float4* bp = (const float4*)b;
    float4 g0 = gp[lane], g1 = gp[lane + 32];
    float4 b0 = bp[lane], b1 = bp[lane + 32];

    __half* yrow = Y + row * CDIM;
    *(__half2*)&yrow[lane * 4]       = __floats2half2_rn((v0.x - mu) * rinv * g0.x + b0.x,
                                                         (v0.y - mu) * rinv * g0.y + b0.y);
    *(__half2*)&yrow[lane * 4 + 2]   = __floats2half2_rn((v0.z - mu) * rinv * g0.z + b0.z,
                                                         (v0.w - mu) * rinv * g0.w + b0.w);
    *(__half2*)&yrow[lane * 4 + 128] = __floats2half2_rn((v1.x - mu) * rinv * g1.x + b1.x,
                                                         (v1.y - mu) * rinv * g1.y + b1.y);
    *(__half2*)&yrow[lane * 4 + 130] = __floats2half2_rn((v1.z - mu) * rinv * g1.z + b1.z,
                                                         (v1.w - mu) * rinv * g1.w + b1.w);
}

// ===========================================================================
// Tensor-core window attention. One CTA per window (512 thr = 16 warps).
// Warp w: head = w>>1, row-half = w&1 (32 queries).
// smem: sqk [64][520] fp16 (q cols 0..255 | k cols 256..511, pad 8)
//       svt [8][32][72] fp16 (per-head V transposed: [d][token], pad 8)
// QK^T and PV via m16n8k16; softmax in registers (unnormalized fp16 P).
// ===========================================================================
#define SQK_STRIDE 520
#define SVT_H 2304         // 32*72
#define ATTN_SMEM ((64 * SQK_STRIDE + 8 * SVT_H) * 2)

__global__ void __launch_bounds__(512) attn_mma(const __half* __restrict__ qkv,
                                                __half* __restrict__ o) {
    extern __shared__ __half sm_h[];
    __half* sqk = sm_h;                     // [64][520]
    __half* svt = sm_h + 64 * SQK_STRIDE;   // [8][32][72]

    const int tid = threadIdx.x;
    const int n = blockIdx.x;
    const long long gbase = (long long)n * 64 * 768;

    // ---- stage q,k (rows of 512 halves) ----
#pragma unroll
    for (int i = 0; i < 8; i++) {
        const int c = tid + 512 * i;
        const int t = c >> 6;
        const int col = (c & 63) * 8;
        *(uint4*)&sqk[t * SQK_STRIDE + col] = *(const uint4*)&qkv[gbase + t * 768 + col];
    }
    // ---- stage v transposed per head ----
#pragma unroll
    for (int i = 0; i < 16; i++) {
        const int p = tid + 512 * i;
        const int t = p >> 7;
        const int d0 = (p & 127) * 2;
        __half2 v = *(const __half2*)&qkv[gbase + t * 768 + 512 + d0];
        const int h = d0 >> 5, dh = d0 & 31;
        svt[h * SVT_H + dh * 72 + t] = __low2half(v);
        svt[h * SVT_H + (dh + 1) * 72 + t] = __high2half(v);
    }
    __syncthreads();

    const int w = tid >> 5, lane = tid & 31;
    const int h = w >> 1, rh = w & 1;
    const int lm = lane >> 2, lk = lane & 3;

    const __half* qb = sqk + h * 32 + 2 * lk;
    const __half* kb = sqk + 256 + h * 32 + 2 * lk;

    float acc[2][8][4];
#pragma unroll
    for (int i = 0; i < 2; i++)
#pragma unroll
        for (int j = 0; j < 8; j++)
#pragma unroll
            for (int q = 0; q < 4; q++) acc[i][j][q] = 0.0f;

    // ---- QK^T: 64x(32x64) ----
#pragma unroll
    for (int kt = 0; kt < 2; kt++) {
        uint32_t a[2][4];
#pragma unroll
        for (int mt = 0; mt < 2; mt++) {
            const int r0 = rh * 32 + mt * 16 + lm;
            const __half* q0 = qb + kt * 16;
            a[mt][0] = *(const uint32_t*)&q0[r0 * SQK_STRIDE];
            a[mt][1] = *(const uint32_t*)&q0[(r0 + 8) * SQK_STRIDE];
            a[mt][2] = *(const uint32_t*)&q0[r0 * SQK_STRIDE + 8];
            a[mt][3] = *(const uint32_t*)&q0[(r0 + 8) * SQK_STRIDE + 8];
        }
#pragma unroll
        for (int nt = 0; nt < 8; nt++) {
            const int kr = nt * 8 + lm;
            const __half* k0 = kb + kt * 16;
            uint32_t b0 = *(const uint32_t*)&k0[kr * SQK_STRIDE];
            uint32_t b1 = *(const uint32_t*)&k0[kr * SQK_STRIDE + 8];
#pragma unroll
            for (int mt = 0; mt < 2; mt++)
                MMA_H(acc[mt][nt], a[mt][0], a[mt][1], a[mt][2], a[mt][3], b0, b1);
        }
    }

    // ---- softmax (registers) ----
    const float cs = 0.17677669529663689f * 1.4426950408889634f;  // scale*log2e
    float rs[2][2];  // reciprocal sums: [mt][row lm / lm+8]
#pragma unroll
    for (int mt = 0; mt < 2; mt++) {
        float m0 = -1e30f, m1 = -1e30f;
#pragma unroll
        for (int nt = 0; nt < 8; nt++) {
            m0 = fmaxf(m0, fmaxf(acc[mt][nt][0], acc[mt][nt][1]));
            m1 = fmaxf(m1, fmaxf(acc[mt][nt][2], acc[mt][nt][3]));
        }
        m0 = fmaxf(m0, __shfl_xor_sync(0xFFFFFFFFu, m0, 1));
        m0 = fmaxf(m0, __shfl_xor_sync(0xFFFFFFFFu, m0, 2));
        m1 = fmaxf(m1, __shfl_xor_sync(0xFFFFFFFFu, m1, 1));
        m1 = fmaxf(m1, __shfl_xor_sync(0xFFFFFFFFu, m1, 2));
        float s0 = 0.0f, s1 = 0.0f;
#pragma unroll
        for (int nt = 0; nt < 8; nt++) {
            float e0 = exp2f((acc[mt][nt][0] - m0) * cs);
            float e1 = exp2f((acc[mt][nt][1] - m0) * cs);
            float e2 = exp2f((acc[mt][nt][2] - m1) * cs);
            float e3 = exp2f((acc[mt][nt][3] - m1) * cs);
            acc[mt][nt][0] = e0; acc[mt][nt][1] = e1;
            acc[mt][nt][2] = e2; acc[mt][nt][3] = e3;
            s0 += e0 + e1; s1 += e2 + e3;
        }
        s0 += __shfl_xor_sync(0xFFFFFFFFu, s0, 1);
        s0 += __shfl_xor_sync(0xFFFFFFFFu, s0, 2);
        s1 += __shfl_xor_sync(0xFFFFFFFFu, s1, 1);
        s1 += __shfl_xor_sync(0xFFFFFFFFu, s1, 2);
        rs[mt][0] = 1.0f / s0;
        rs[mt][1] = 1.0f / s1;
    }

    // ---- PV: P(32x64) @ V(64x32), P from registers (fp16 pack) ----
    float oacc[2][4][4];
#pragma unroll
    for (int i = 0; i < 2; i++)
#pragma unroll
        for (int j = 0; j < 4; j++)
#pragma unroll
            for (int q = 0; q < 4; q++) oacc[i][j][q] = 0.0f;

    const __half* vb0 = svt + h * SVT_H + 2 * lk;
#pragma unroll
    for (int kt4 = 0; kt4 < 4; kt4++) {
        uint32_t pa[2][4];
#pragma unroll
        for (int mt = 0; mt < 2; mt++) {
            pa[mt][0] = h2_u32(__floats2half2_rn(acc[mt][2 * kt4][0], acc[mt][2 * kt4][1]));
            pa[mt][1] = h2_u32(__floats2half2_rn(acc[mt][2 * kt4][2], acc[mt][2 * kt4][3]));
            pa[mt][2] = h2_u32(__floats2half2_rn(acc[mt][2 * kt4 + 1][0], acc[mt][2 * kt4 + 1][1]));
            pa[mt][3] = h2_u32(__floats2half2_rn(acc[mt][2 * kt4 + 1][2], acc[mt][2 * kt4 + 1][3]));
        }
#pragma unroll
        for (int dn = 0; dn < 4; dn++) {
            const __half* vb = vb0 + (dn * 8 + lm) * 72 + kt4 * 16;
            uint32_t b0 = *(const uint32_t*)&vb[0];
            uint32_t b1 = *(const uint32_t*)&vb[8];
#pragma unroll
            for (int mt = 0; mt < 2; mt++)
                MMA_H(oacc[mt][dn], pa[mt][0], pa[mt][1], pa[mt][2], pa[mt][3], b0, b1);
        }
    }

    // ---- epilogue: normalize, fp16, write ----
#pragma unroll
    for (int mt = 0; mt < 2; mt++) {
        const int r0 = rh * 32 + mt * 16 + lm;
#pragma unroll
        for (int dn = 0; dn < 4; dn++) {
            const int col = h * 32 + dn * 8 + 2 * lk;
            __half* o0 = o + ((long long)n * 64 + r0) * CDIM + col;
            __half* o1 = o + ((long long)n * 64 + r0 + 8) * CDIM + col;
            *(__half2*)o0 = __floats2half2_rn(oacc[mt][dn][0] * rs[mt][0],
                                              oacc[mt][dn][1] * rs[mt][0]);
            *(__half2*)o1 = __floats2half2_rn(oacc[mt][dn][2] * rs[mt][1],
                                              oacc[mt][dn][3] * rs[mt][1]);
        }
    }
}

// ===========================================================================
// Launch
// ===========================================================================
extern "C" void kernel_launch(void* const* d_in, const int* in_sizes, int n_in,
                              void* d_out, int out_size) {
    const float* x      = (const float*)d_in[0];
    const float* qkv_w  = (const float*)d_in[1];
    const float* qkv_b  = (const float*)d_in[2];
    const float* proj_w = (const float*)d_in[3];
    const float* proj_b = (const float*)d_in[4];
    const float* n1_g   = (const float*)d_in[5];
    const float* n1_b   = (const float*)d_in[6];
    const float* n2_g   = (const float*)d_in[7];
    const float* n2_b   = (const float*)d_in[8];
    const float* fc1_w  = (const float*)d_in[9];
    const float* fc1_b  = (const float*)d_in[10];
    const float* fc2_w  = (const float*)d_in[11];
    const float* fc2_b  = (const float*)d_in[12];
    float* out = (float*)d_out;

    float *tok, *y;
    __half *yh, *qkvh, *oh, *hidh, *wh;
    cudaGetSymbolAddress((void**)&tok, g_tok);
    cudaGetSymbolAddress((void**)&y, g_y);
    cudaGetSymbolAddress((void**)&yh, g_yh);
    cudaGetSymbolAddress((void**)&qkvh, g_qkvh);
    cudaGetSymbolAddress((void**)&oh, g_oh);
    cudaGetSymbolAddress((void**)&hidh, g_hidh);
    cudaGetSymbolAddress((void**)&wh, g_wh);

    cudaFuncSetAttribute(attn_mma, cudaFuncAttributeMaxDynamicSharedMemorySize, ATTN_SMEM);

    const dim3 tb(32, 8);
    const dim3 tg(W_ / 32, CDIM / 32, B_ * H_);
    const int MT = NTOK / 128;  // 2048 M-tiles

    // 0. weights -> fp16
    cvt_weights<<<512, 256>>>(qkv_w, proj_w, fc1_w, fc2_w);
    // 1. window partition
    gather_kernel<<<tg, tb>>>(x, tok);
    // 2. LN1 -> fp16
    ln_kernel<<<NTOK / 8, 256>>>(tok, n1_g, n1_b, yh);
    // 3. QKV gemm
    mma_gemm_h<0><<<dim3(MT, 6), 256>>>(yh, wh + WOFF_QKV, qkv_b, nullptr, qkvh, 768, 256);
    // 4. windowed attention (tensor cores)
    attn_mma<<<4096, 512, ATTN_SMEM>>>(qkvh, oh);
    // 5. proj gemm + residual -> tok (fp32)
    mma_gemm_h<1><<<dim3(MT, 2), 256>>>(oh, wh + WOFF_PROJ, proj_b, tok, tok, 256, 256);
    // 6. LN2 -> fp16
    ln_kernel<<<NTOK / 8, 256>>>(tok, n2_g, n2_b, yh);
    // 7. fc1 gemm + GELU -> fp16
    mma_gemm_h<2><<<dim3(MT, 8), 256>>>(yh, wh + WOFF_FC1, fc1_b, nullptr, hidh, 1024, 256);
    // 8. fc2 gemm + residual -> y (fp32)
    mma_gemm_h<1><<<dim3(MT, 2), 256>>>(hidh, wh + WOFF_FC2, fc2_b, tok, y, 256, 1024);
    // 9. un-partition
    scatter_kernel<<<tg, tb>>>(y, out);
}

// round 11
// speedup vs baseline: 2.5094x; 1.0560x over previous
#include <cuda_runtime.h>
#include <cuda_fp16.h>
#include <math.h>
#include <cstdint>

// Problem constants
#define B_ 16
#define CDIM 256
#define H_ 128
#define W_ 128
#define NTOK 262144   // B*H*W tokens

// Scratch (device globals)
__device__ float  g_tok[67108864];     // [NTOK, 256] fp32 residual stream
__device__ __half g_yh[67108864];      // [NTOK, 256] LN output fp16
__device__ __half g_qkvh[201326592];   // [NTOK, 768] fp16
__device__ __half g_oh[67108864];      // [NTOK, 256] fp16
__device__ __half g_hidh[268435456];   // [NTOK, 1024] fp16
__device__ __half g_wh[786432];        // qkv_w|proj_w|fc1_w|fc2_w fp16

#define WOFF_QKV 0
#define WOFF_PROJ 196608
#define WOFF_FC1 262144
#define WOFF_FC2 524288

__device__ __forceinline__ float gelu_exact(float v) {
    return 0.5f * v * (1.0f + erff(v * 0.70710678118654752f));
}

__device__ __forceinline__ uint32_t h2_u32(__half2 v) {
    return *reinterpret_cast<uint32_t*>(&v);
}

__device__ __forceinline__ void cpa16(uint32_t dst, const void* src) {
    asm volatile("cp.async.cg.shared.global [%0], [%1], 16;" :: "r"(dst), "l"(src));
}
#define CP_COMMIT() asm volatile("cp.async.commit_group;" ::: "memory")
#define CP_WAIT1()  asm volatile("cp.async.wait_group 1;" ::: "memory")

#define MMA_H(dd, a0, a1, a2, a3, b0, b1) \
    asm volatile( \
        "mma.sync.aligned.m16n8k16.row.col.f32.f16.f16.f32 " \
        "{%0,%1,%2,%3}, {%4,%5,%6,%7}, {%8,%9}, {%0,%1,%2,%3};" \
        : "+f"((dd)[0]), "+f"((dd)[1]), "+f"((dd)[2]), "+f"((dd)[3]) \
        : "r"(a0), "r"(a1), "r"(a2), "r"(a3), "r"(b0), "r"(b1))

// ===========================================================================
// Weight conversion fp32 -> fp16
// ===========================================================================
__global__ void __launch_bounds__(256) cvt_weights(const float* __restrict__ qkv_w,
                                                   const float* __restrict__ proj_w,
                                                   const float* __restrict__ fc1_w,
                                                   const float* __restrict__ fc2_w) {
    for (int i = blockIdx.x * 256 + threadIdx.x; i < 786432; i += gridDim.x * 256) {
        float v;
        if (i < WOFF_PROJ)      v = qkv_w[i - WOFF_QKV];
        else if (i < WOFF_FC1)  v = proj_w[i - WOFF_PROJ];
        else if (i < WOFF_FC2)  v = fc1_w[i - WOFF_FC1];
        else                    v = fc2_w[i - WOFF_FC2];
        g_wh[i] = __float2half_rn(v);
    }
}

// ===========================================================================
// FP16 mma.sync GEMM. Grid = (n_tiles, m_tiles) so CTAs sharing an A M-tile
// are co-resident (A hits L2 after the first fetch).
// EPI: 0=bias->f16, 1=bias+residual(fp32)->f32, 2=bias+GELU->f16,
//      3=bias+residual -> scatter NCHW fp32 (fc2 + un-partition fused)
// ===========================================================================
template <int EPI>
__global__ void __launch_bounds__(256, 2) mma_gemm_h(const __half* __restrict__ A,
                                                     const __half* __restrict__ Wm,
                                                     const float* __restrict__ bias,
                                                     const float* __restrict__ R,
                                                     void* __restrict__ OutV,
                                                     int N, int K) {
    __shared__ uint32_t As[3 * 2048];
    __shared__ uint32_t Bs[3 * 2048];

    const int tid = threadIdx.x;
    const int wid = tid >> 5;
    const int lane = tid & 31;
    const long long m0 = (long long)blockIdx.y * 128;
    const int n0 = blockIdx.x * 128;

    const int wm = (wid >> 2) * 64;
    const int wn = (wid & 3) * 32;
    const int lm = lane >> 2;
    const int lk = lane & 3;

    const int gr = tid >> 1;
    const int sw_g = ((gr >> 1) & 3) * 4;

    const __half* arow = A + (m0 + gr) * (long long)K;
    const __half* brow = Wm + (long long)(n0 + gr) * K;

    const uint32_t as_b = (uint32_t)__cvta_generic_to_shared(As);
    const uint32_t bs_b = (uint32_t)__cvta_generic_to_shared(Bs);
    uint32_t soff[2];
    int gseg[2];
#pragma unroll
    for (int j = 0; j < 2; j++) {
        const int seg = (tid & 1) + 2 * j;
        gseg[j] = seg * 8;
        soff[j] = (uint32_t)(gr * 16 + ((seg * 4) ^ sw_g)) * 4u;
    }

    const int KT = K >> 5;

#pragma unroll
    for (int s = 0; s < 2; s++) {
        const int ko = s * 32;
        const uint32_t sb = s * 8192u;
#pragma unroll
        for (int j = 0; j < 2; j++) {
            cpa16(as_b + sb + soff[j], arow + ko + gseg[j]);
            cpa16(bs_b + sb + soff[j], brow + ko + gseg[j]);
        }
        CP_COMMIT();
    }

    float d[4][4][4];
#pragma unroll
    for (int i = 0; i < 4; i++)
#pragma unroll
        for (int j = 0; j < 4; j++)
#pragma unroll
            for (int q = 0; q < 4; q++) d[i][j][q] = 0.0f;

    int stage = 0;
    for (int kt = 0; kt < KT; kt++) {
        CP_WAIT1();
        __syncthreads();

        if (kt + 2 < KT) {
            const int s2 = stage + 2 >= 3 ? stage - 1 : stage + 2;
            const int ko = (kt + 2) * 32;
            const uint32_t sb = s2 * 8192u;
#pragma unroll
            for (int j = 0; j < 2; j++) {
                cpa16(as_b + sb + soff[j], arow + ko + gseg[j]);
                cpa16(bs_b + sb + soff[j], brow + ko + gseg[j]);
            }
        }
        CP_COMMIT();

        const uint32_t* Ac = As + stage * 2048;
        const uint32_t* Bc = Bs + stage * 2048;
#pragma unroll
        for (int ks = 0; ks < 2; ks++) {
            const int kkc = ks * 8;
            uint32_t a[4][4];
#pragma unroll
            for (int mf = 0; mf < 4; mf++) {
                const int m = wm + mf * 16 + lm;
                const int sw = ((m >> 1) & 3) * 4;
                const int c0 = (kkc + lk) ^ sw;
                const int c1 = (kkc + lk + 4) ^ sw;
                a[mf][0] = Ac[m * 16 + c0];
                a[mf][1] = Ac[(m + 8) * 16 + c0];
                a[mf][2] = Ac[m * 16 + c1];
                a[mf][3] = Ac[(m + 8) * 16 + c1];
            }
            uint32_t b[4][2];
#pragma unroll
            for (int nf = 0; nf < 4; nf++) {
                const int n = wn + nf * 8 + lm;
                const int sw = ((n >> 1) & 3) * 4;
                b[nf][0] = Bc[n * 16 + ((kkc + lk) ^ sw)];
                b[nf][1] = Bc[n * 16 + ((kkc + lk + 4) ^ sw)];
            }
#pragma unroll
            for (int mf = 0; mf < 4; mf++)
#pragma unroll
                for (int nf = 0; nf < 4; nf++)
                    MMA_H(d[mf][nf], a[mf][0], a[mf][1], a[mf][2], a[mf][3],
                          b[nf][0], b[nf][1]);
        }
        stage = stage + 1 >= 3 ? 0 : stage + 1;
    }

#pragma unroll
    for (int nf = 0; nf < 4; nf++) {
        const int gcol = n0 + wn + nf * 8 + 2 * lk;
        const float2 bv = *(const float2*)&bias[gcol];
#pragma unroll
        for (int mf = 0; mf < 4; mf++) {
            const long long row = m0 + wm + mf * 16 + lm;
            float2 v0, v1;
            v0.x = d[mf][nf][0] + bv.x;
            v0.y = d[mf][nf][1] + bv.y;
            v1.x = d[mf][nf][2] + bv.x;
            v1.y = d[mf][nf][3] + bv.y;
            if (EPI == 1) {
                float2 r0 = *(const float2*)&R[row * (long long)N + gcol];
                float2 r1 = *(const float2*)&R[(row + 8) * (long long)N + gcol];
                v0.x += r0.x; v0.y += r0.y;
                v1.x += r1.x; v1.y += r1.y;
                float* Out = (float*)OutV;
                *(float2*)&Out[row * (long long)N + gcol] = v0;
                *(float2*)&Out[(row + 8) * (long long)N + gcol] = v1;
            } else if (EPI == 3) {
                float2 r0 = *(const float2*)&R[row * (long long)N + gcol];
                float2 r1 = *(const float2*)&R[(row + 8) * (long long)N + gcol];
                v0.x += r0.x; v0.y += r0.y;
                v1.x += r1.x; v1.y += r1.y;
                // scatter to NCHW
                const int n_ = (int)(row >> 6);
                const int t_ = (int)(row & 63);
                const int bb = n_ >> 8, wy = (n_ >> 4) & 15, wx = n_ & 15;
                const int hh = wy * 8 + (t_ >> 3), ww = wx * 8 + (t_ & 7);
                float* Out = (float*)OutV;
                const long long base0 =
                    ((long long)(bb * 256 + gcol) << 14) + hh * 128 + ww;
                Out[base0] = v0.x;
                Out[base0 + 16384] = v0.y;
                Out[base0 + 128] = v1.x;          // row+8 -> h+1, same w
                Out[base0 + 16384 + 128] = v1.y;
            } else {
                if (EPI == 2) {
                    v0.x = gelu_exact(v0.x); v0.y = gelu_exact(v0.y);
                    v1.x = gelu_exact(v1.x); v1.y = gelu_exact(v1.y);
                }
                __half* Out = (__half*)OutV;
                *(__half2*)&Out[row * (long long)N + gcol] = __floats2half2_rn(v0.x, v0.y);
                *(__half2*)&Out[(row + 8) * (long long)N + gcol] = __floats2half2_rn(v1.x, v1.y);
            }
        }
    }
}

// ===========================================================================
// Fused gather + LN1. One CTA per window (256 threads).
// x[B,C,H,W] window -> smem [64 tok][256 c] (xor swizzle c^=4*iy) -> LN ->
// tok fp32 (residual stream) + yh fp16 (GEMM A).
// ===========================================================================
__global__ void __launch_bounds__(256) gather_ln(const float* __restrict__ x,
                                                 const float* __restrict__ g,
                                                 const float* __restrict__ b,
                                                 float* __restrict__ tok,
                                                 __half* __restrict__ yh) {
    extern __shared__ float st[];   // [64][256], swizzled

    const int tid = threadIdx.x;
    const int n = blockIdx.x;
    const int bb = n >> 8, wy = (n >> 4) & 15, wx = n & 15;

    // load: thread handles 8 (c, iy) pairs, 8 floats (ix) each
#pragma unroll
    for (int j = 0; j < 8; j++) {
        const int p = tid + 256 * j;
        const int c = p >> 3;
        const int iy = p & 7;
        const float* xp = x + (((long long)(bb * 256 + c)) << 14)
                        + (wy * 8 + iy) * 128 + wx * 8;
        float4 u0 = *(const float4*)xp;
        float4 u1 = *(const float4*)(xp + 4);
        const int cs = c ^ (iy * 4);
        float* row0 = st + (iy * 8) * 256;
        row0[0 * 256 + cs] = u0.x;
        row0[1 * 256 + cs] = u0.y;
        row0[2 * 256 + cs] = u0.z;
        row0[3 * 256 + cs] = u0.w;
        row0[4 * 256 + cs] = u1.x;
        row0[5 * 256 + cs] = u1.y;
        row0[6 * 256 + cs] = u1.z;
        row0[7 * 256 + cs] = u1.w;
    }
    __syncthreads();

    // LN: warp w handles rows w*8 .. w*8+7; lane holds c = 4l..4l+3, 128+4l..+3
    const int w = tid >> 5, lane = tid & 31;
#pragma unroll
    for (int r = 0; r < 8; r++) {
        const int t = w * 8 + r;
        const int xr = ((t >> 3) & 7) * 4;
        const float* row = st + t * 256;
        float4 v0 = *(const float4*)&row[(4 * lane) ^ xr];
        float4 v1 = *(const float4*)&row[(128 + 4 * lane) ^ xr];

        float s = v0.x + v0.y + v0.z + v0.w + v1.x + v1.y + v1.z + v1.w;
#pragma unroll
        for (int o = 16; o; o >>= 1) s += __shfl_xor_sync(0xFFFFFFFFu, s, o);
        const float mu = s * (1.0f / 256.0f);

        float q = (v0.x - mu) * (v0.x - mu) + (v0.y - mu) * (v0.y - mu)
                + (v0.z - mu) * (v0.z - mu) + (v0.w - mu) * (v0.w - mu)
                + (v1.x - mu) * (v1.x - mu) + (v1.y - mu) * (v1.y - mu)
                + (v1.z - mu) * (v1.z - mu) + (v1.w - mu) * (v1.w - mu);
#pragma unroll
        for (int o = 16; o; o >>= 1) q += __shfl_xor_sync(0xFFFFFFFFu, q, o);
        const float rinv = rsqrtf(q * (1.0f / 256.0f) + 1e-5f);

        const long long grow = (long long)n * 64 + t;
        // residual stream (raw window values)
        *(float4*)&tok[grow * CDIM + 4 * lane] = v0;
        *(float4*)&tok[grow * CDIM + 128 + 4 * lane] = v1;

        float4 g0 = *(const float4*)&g[4 * lane];
        float4 g1 = *(const float4*)&g[128 + 4 * lane];
        float4 b0 = *(const float4*)&b[4 * lane];
        float4 b1 = *(const float4*)&b[128 + 4 * lane];
        __half* yrow = yh + grow * CDIM;
        __half2 h0 = __floats2half2_rn((v0.x - mu) * rinv * g0.x + b0.x,
                                       (v0.y - mu) * rinv * g0.y + b0.y);
        __half2 h1 = __floats2half2_rn((v0.z - mu) * rinv * g0.z + b0.z,
                                       (v0.w - mu) * rinv * g0.w + b0.w);
        __half2 h2 = __floats2half2_rn((v1.x - mu) * rinv * g1.x + b1.x,
                                       (v1.y - mu) * rinv * g1.y + b1.y);
        __half2 h3 = __floats2half2_rn((v1.z - mu) * rinv * g1.z + b1.z,
                                       (v1.w - mu) * rinv * g1.w + b1.w);
        *(__half2*)&yrow[4 * lane] = h0;
        *(__half2*)&yrow[4 * lane + 2] = h1;
        *(__half2*)&yrow[128 + 4 * lane] = h2;
        *(__half2*)&yrow[128 + 4 * lane + 2] = h3;
    }
}

// ===========================================================================
// LayerNorm (LN2): fp32 in -> fp16 out
// ===========================================================================
__global__ void __launch_bounds__(256) ln_kernel(const float* __restrict__ A,
                                                 const float* __restrict__ g,
                                                 const float* __restrict__ b,
                                                 __half* __restrict__ Y) {
    const long long row = (long long)blockIdx.x * 8 + (threadIdx.x >> 5);
    const int lane = threadIdx.x & 31;
    const float4* ap = (const float4*)(A + row * CDIM);
    float4 v0 = ap[lane];
    float4 v1 = ap[lane + 32];

    float s = v0.x + v0.y + v0.z + v0.w + v1.x + v1.y + v1.z + v1.w;
#pragma unroll
    for (int o = 16; o; o >>= 1) s += __shfl_xor_sync(0xFFFFFFFFu, s, o);
    const float mu = s * (1.0f / 256.0f);

    float q = (v0.x - mu) * (v0.x - mu) + (v0.y - mu) * (v0.y - mu)
            + (v0.z - mu) * (v0.z - mu) + (v0.w - mu) * (v0.w - mu)
            + (v1.x - mu) * (v1.x - mu) + (v1.y - mu) * (v1.y - mu)
            + (v1.z - mu) * (v1.z - mu) + (v1.w - mu) * (v1.w - mu);
#pragma unroll
    for (int o = 16; o; o >>= 1) q += __shfl_xor_sync(0xFFFFFFFFu, q, o);
    const float rinv = rsqrtf(q * (1.0f / 256.0f) + 1e-5f);

    const float4* gp = (const float4*)g;
    const float4* bp = (const float4*)b;
    float4 g0 = gp[lane], g1 = gp[lane + 32];
    float4 b0 = bp[lane], b1 = bp[lane + 32];

    __half* yrow = Y + row * CDIM;
    *(__half2*)&yrow[lane * 4]       = __floats2half2_rn((v0.x - mu) * rinv * g0.x + b0.x,
                                                         (v0.y - mu) * rinv * g0.y + b0.y);
    *(__half2*)&yrow[lane * 4 + 2]   = __floats2half2_rn((v0.z - mu) * rinv * g0.z + b0.z,
                                                         (v0.w - mu) * rinv * g0.w + b0.w);
    *(__half2*)&yrow[lane * 4 + 128] = __floats2half2_rn((v1.x - mu) * rinv * g1.x + b1.x,
                                                         (v1.y - mu) * rinv * g1.y + b1.y);
    *(__half2*)&yrow[lane * 4 + 130] = __floats2half2_rn((v1.z - mu) * rinv * g1.z + b1.z,
                                                         (v1.w - mu) * rinv * g1.w + b1.w);
}

// ===========================================================================
// Tensor-core window attention (unchanged from R10)
// ===========================================================================
#define SQK_STRIDE 520
#define SVT_H 2304
#define ATTN_SMEM ((64 * SQK_STRIDE + 8 * SVT_H) * 2)

__global__ void __launch_bounds__(512) attn_mma(const __half* __restrict__ qkv,
                                                __half* __restrict__ o) {
    extern __shared__ __half sm_h[];
    __half* sqk = sm_h;
    __half* svt = sm_h + 64 * SQK_STRIDE;

    const int tid = threadIdx.x;
    const int n = blockIdx.x;
    const long long gbase = (long long)n * 64 * 768;

#pragma unroll
    for (int i = 0; i < 8; i++) {
        const int c = tid + 512 * i;
        const int t = c >> 6;
        const int col = (c & 63) * 8;
        *(uint4*)&sqk[t * SQK_STRIDE + col] = *(const uint4*)&qkv[gbase + t * 768 + col];
    }
#pragma unroll
    for (int i = 0; i < 16; i++) {
        const int p = tid + 512 * i;
        const int t = p >> 7;
        const int d0 = (p & 127) * 2;
        __half2 v = *(const __half2*)&qkv[gbase + t * 768 + 512 + d0];
        const int h = d0 >> 5, dh = d0 & 31;
        svt[h * SVT_H + dh * 72 + t] = __low2half(v);
        svt[h * SVT_H + (dh + 1) * 72 + t] = __high2half(v);
    }
    __syncthreads();

    const int w = tid >> 5, lane = tid & 31;
    const int h = w >> 1, rh = w & 1;
    const int lm = lane >> 2, lk = lane & 3;

    const __half* qb = sqk + h * 32 + 2 * lk;
    const __half* kb = sqk + 256 + h * 32 + 2 * lk;

    float acc[2][8][4];
#pragma unroll
    for (int i = 0; i < 2; i++)
#pragma unroll
        for (int j = 0; j < 8; j++)
#pragma unroll
            for (int q = 0; q < 4; q++) acc[i][j][q] = 0.0f;

#pragma unroll
    for (int kt = 0; kt < 2; kt++) {
        uint32_t a[2][4];
#pragma unroll
        for (int mt = 0; mt < 2; mt++) {
            const int r0 = rh * 32 + mt * 16 + lm;
            const __half* q0 = qb + kt * 16;
            a[mt][0] = *(const uint32_t*)&q0[r0 * SQK_STRIDE];
            a[mt][1] = *(const uint32_t*)&q0[(r0 + 8) * SQK_STRIDE];
            a[mt][2] = *(const uint32_t*)&q0[r0 * SQK_STRIDE + 8];
            a[mt][3] = *(const uint32_t*)&q0[(r0 + 8) * SQK_STRIDE + 8];
        }
#pragma unroll
        for (int nt = 0; nt < 8; nt++) {
            const int kr = nt * 8 + lm;
            const __half* k0 = kb + kt * 16;
            uint32_t b0 = *(const uint32_t*)&k0[kr * SQK_STRIDE];
            uint32_t b1 = *(const uint32_t*)&k0[kr * SQK_STRIDE + 8];
#pragma unroll
            for (int mt = 0; mt < 2; mt++)
                MMA_H(acc[mt][nt], a[mt][0], a[mt][1], a[mt][2], a[mt][3], b0, b1);
        }
    }

    const float cs = 0.17677669529663689f * 1.4426950408889634f;
    float rs[2][2];
#pragma unroll
    for (int mt = 0; mt < 2; mt++) {
        float m0 = -1e30f, m1 = -1e30f;
#pragma unroll
        for (int nt = 0; nt < 8; nt++) {
            m0 = fmaxf(m0, fmaxf(acc[mt][nt][0], acc[mt][nt][1]));
            m1 = fmaxf(m1, fmaxf(acc[mt][nt][2], acc[mt][nt][3]));
        }
        m0 = fmaxf(m0, __shfl_xor_sync(0xFFFFFFFFu, m0, 1));
        m0 = fmaxf(m0, __shfl_xor_sync(0xFFFFFFFFu, m0, 2));
        m1 = fmaxf(m1, __shfl_xor_sync(0xFFFFFFFFu, m1, 1));
        m1 = fmaxf(m1, __shfl_xor_sync(0xFFFFFFFFu, m1, 2));
        float s0 = 0.0f, s1 = 0.0f;
#pragma unroll
        for (int nt = 0; nt < 8; nt++) {
            float e0 = exp2f((acc[mt][nt][0] - m0) * cs);
            float e1 = exp2f((acc[mt][nt][1] - m0) * cs);
            float e2 = exp2f((acc[mt][nt][2] - m1) * cs);
            float e3 = exp2f((acc[mt][nt][3] - m1) * cs);
            acc[mt][nt][0] = e0; acc[mt][nt][1] = e1;
            acc[mt][nt][2] = e2; acc[mt][nt][3] = e3;
            s0 += e0 + e1; s1 += e2 + e3;
        }
        s0 += __shfl_xor_sync(0xFFFFFFFFu, s0, 1);
        s0 += __shfl_xor_sync(0xFFFFFFFFu, s0, 2);
        s1 += __shfl_xor_sync(0xFFFFFFFFu, s1, 1);
        s1 += __shfl_xor_sync(0xFFFFFFFFu, s1, 2);
        rs[mt][0] = 1.0f / s0;
        rs[mt][1] = 1.0f / s1;
    }

    float oacc[2][4][4];
#pragma unroll
    for (int i = 0; i < 2; i++)
#pragma unroll
        for (int j = 0; j < 4; j++)
#pragma unroll
            for (int q = 0; q < 4; q++) oacc[i][j][q] = 0.0f;

    const __half* vb0 = svt + h * SVT_H + 2 * lk;
#pragma unroll
    for (int kt4 = 0; kt4 < 4; kt4++) {
        uint32_t pa[2][4];
#pragma unroll
        for (int mt = 0; mt < 2; mt++) {
            pa[mt][0] = h2_u32(__floats2half2_rn(acc[mt][2 * kt4][0], acc[mt][2 * kt4][1]));
            pa[mt][1] = h2_u32(__floats2half2_rn(acc[mt][2 * kt4][2], acc[mt][2 * kt4][3]));
            pa[mt][2] = h2_u32(__floats2half2_rn(acc[mt][2 * kt4 + 1][0], acc[mt][2 * kt4 + 1][1]));
            pa[mt][3] = h2_u32(__floats2half2_rn(acc[mt][2 * kt4 + 1][2], acc[mt][2 * kt4 + 1][3]));
        }
#pragma unroll
        for (int dn = 0; dn < 4; dn++) {
            const __half* vb = vb0 + (dn * 8 + lm) * 72 + kt4 * 16;
            uint32_t b0 = *(const uint32_t*)&vb[0];
            uint32_t b1 = *(const uint32_t*)&vb[8];
#pragma unroll
            for (int mt = 0; mt < 2; mt++)
                MMA_H(oacc[mt][dn], pa[mt][0], pa[mt][1], pa[mt][2], pa[mt][3], b0, b1);
        }
    }

#pragma unroll
    for (int mt = 0; mt < 2; mt++) {
        const int r0 = rh * 32 + mt * 16 + lm;
#pragma unroll
        for (int dn = 0; dn < 4; dn++) {
            const int col = h * 32 + dn * 8 + 2 * lk;
            __half* o0 = o + ((long long)n * 64 + r0) * CDIM + col;
            __half* o1 = o + ((long long)n * 64 + r0 + 8) * CDIM + col;
            *(__half2*)o0 = __floats2half2_rn(oacc[mt][dn][0] * rs[mt][0],
                                              oacc[mt][dn][1] * rs[mt][0]);
            *(__half2*)o1 = __floats2half2_rn(oacc[mt][dn][2] * rs[mt][1],
                                              oacc[mt][dn][3] * rs[mt][1]);
        }
    }
}

// ===========================================================================
// Launch
// ===========================================================================
extern "C" void kernel_launch(void* const* d_in, const int* in_sizes, int n_in,
                              void* d_out, int out_size) {
    const float* x      = (const float*)d_in[0];
    const float* qkv_w  = (const float*)d_in[1];
    const float* qkv_b  = (const float*)d_in[2];
    const float* proj_w = (const float*)d_in[3];
    const float* proj_b = (const float*)d_in[4];
    const float* n1_g   = (const float*)d_in[5];
    const float* n1_b   = (const float*)d_in[6];
    const float* n2_g   = (const float*)d_in[7];
    const float* n2_b   = (const float*)d_in[8];
    const float* fc1_w  = (const float*)d_in[9];
    const float* fc1_b  = (const float*)d_in[10];
    const float* fc2_w  = (const float*)d_in[11];
    const float* fc2_b  = (const float*)d_in[12];
    float* out = (float*)d_out;

    float *tok;
    __half *yh, *qkvh, *oh, *hidh, *wh;
    cudaGetSymbolAddress((void**)&tok, g_tok);
    cudaGetSymbolAddress((void**)&yh, g_yh);
    cudaGetSymbolAddress((void**)&qkvh, g_qkvh);
    cudaGetSymbolAddress((void**)&oh, g_oh);
    cudaGetSymbolAddress((void**)&hidh, g_hidh);
    cudaGetSymbolAddress((void**)&wh, g_wh);

    cudaFuncSetAttribute(attn_mma, cudaFuncAttributeMaxDynamicSharedMemorySize, ATTN_SMEM);
    const int GLN_SMEM = 64 * 256 * 4;  // 64KB
    cudaFuncSetAttribute(gather_ln, cudaFuncAttributeMaxDynamicSharedMemorySize, GLN_SMEM);

    const int MT = NTOK / 128;  // 2048 M-tiles

    // 0. weights -> fp16
    cvt_weights<<<512, 256>>>(qkv_w, proj_w, fc1_w, fc2_w);
    // 1+2. window partition + LN1 (fused)
    gather_ln<<<4096, 256, GLN_SMEM>>>(x, n1_g, n1_b, tok, yh);
    // 3. QKV gemm (grid: n fastest for A L2 reuse)
    mma_gemm_h<0><<<dim3(6, MT), 256>>>(yh, wh + WOFF_QKV, qkv_b, nullptr, qkvh, 768, 256);
    // 4. windowed attention (tensor cores)
    attn_mma<<<4096, 512, ATTN_SMEM>>>(qkvh, oh);
    // 5. proj gemm + residual -> tok (fp32)
    mma_gemm_h<1><<<dim3(2, MT), 256>>>(oh, wh + WOFF_PROJ, proj_b, tok, tok, 256, 256);
    // 6. LN2 -> fp16
    ln_kernel<<<NTOK / 8, 256>>>(tok, n2_g, n2_b, yh);
    // 7. fc1 gemm + GELU -> fp16
    mma_gemm_h<2><<<dim3(8, MT), 256>>>(yh, wh + WOFF_FC1, fc1_b, nullptr, hidh, 1024, 256);
    // 8. fc2 gemm + residual + scatter -> out (fused un-partition)
    mma_gemm_h<3><<<dim3(2, MT), 256>>>(hidh, wh + WOFF_FC2, fc2_b, tok, out, 256, 1024);
}

// round 12
// speedup vs baseline: 2.9967x; 1.1942x over previous
#include <cuda_runtime.h>
#include <cuda_fp16.h>
#include <math.h>
#include <cstdint>

// Problem constants
#define B_ 16
#define CDIM 256
#define H_ 128
#define W_ 128
#define NTOK 262144   // B*H*W tokens

// Scratch (device globals)
__device__ float  g_tok[67108864];     // [NTOK, 256] fp32 residual stream
__device__ __half g_yh[67108864];      // [NTOK, 256] LN output fp16
__device__ __half g_qkvh[201326592];   // [NTOK, 768] fp16
__device__ __half g_oh[67108864];      // [NTOK, 256] fp16
__device__ __half g_hidh[268435456];   // [NTOK, 1024] fp16
__device__ __half g_wh[786432];        // qkv_w|proj_w|fc1_w|fc2_w fp16

#define WOFF_QKV 0
#define WOFF_PROJ 196608
#define WOFF_FC1 262144
#define WOFF_FC2 524288

__device__ __forceinline__ float gelu_exact(float v) {
    return 0.5f * v * (1.0f + erff(v * 0.70710678118654752f));
}

__device__ __forceinline__ uint32_t h2_u32(__half2 v) {
    return *reinterpret_cast<uint32_t*>(&v);
}

__device__ __forceinline__ void cpa16(uint32_t dst, const void* src) {
    asm volatile("cp.async.cg.shared.global [%0], [%1], 16;" :: "r"(dst), "l"(src));
}
#define CP_COMMIT() asm volatile("cp.async.commit_group;" ::: "memory")
#define CP_WAIT1()  asm volatile("cp.async.wait_group 1;" ::: "memory")

#define MMA_H(dd, a0, a1, a2, a3, b0, b1) \
    asm volatile( \
        "mma.sync.aligned.m16n8k16.row.col.f32.f16.f16.f32 " \
        "{%0,%1,%2,%3}, {%4,%5,%6,%7}, {%8,%9}, {%0,%1,%2,%3};" \
        : "+f"((dd)[0]), "+f"((dd)[1]), "+f"((dd)[2]), "+f"((dd)[3]) \
        : "r"(a0), "r"(a1), "r"(a2), "r"(a3), "r"(b0), "r"(b1))

#define LDSM_X4(r0, r1, r2, r3, addr) \
    asm volatile("ldmatrix.sync.aligned.m8n8.x4.shared.b16 {%0,%1,%2,%3}, [%4];" \
        : "=r"(r0), "=r"(r1), "=r"(r2), "=r"(r3) : "r"(addr))

// ===========================================================================
// Weight conversion fp32 -> fp16
// ===========================================================================
__global__ void __launch_bounds__(256) cvt_weights(const float* __restrict__ qkv_w,
                                                   const float* __restrict__ proj_w,
                                                   const float* __restrict__ fc1_w,
                                                   const float* __restrict__ fc2_w) {
    for (int i = blockIdx.x * 256 + threadIdx.x; i < 786432; i += gridDim.x * 256) {
        float v;
        if (i < WOFF_PROJ)      v = qkv_w[i - WOFF_QKV];
        else if (i < WOFF_FC1)  v = proj_w[i - WOFF_PROJ];
        else if (i < WOFF_FC2)  v = fc1_w[i - WOFF_FC1];
        else                    v = fc2_w[i - WOFF_FC2];
        g_wh[i] = __float2half_rn(v);
    }
}

// ===========================================================================
// FP16 mma.sync GEMM, ldmatrix fragment loads, K-chunk 64 halves (128B rows,
// swizzle granule^(row&7): conflict-free LDSM), 3-stage cp.async, 2 CTA/SM.
// Grid = (n_tiles, m_tiles) for A L2 reuse.
// EPI: 0=bias->f16, 1=bias+residual(fp32)->f32, 2=bias+GELU->f16,
//      3=bias+residual -> scatter NCHW fp32
// ===========================================================================
template <int EPI>
__global__ void __launch_bounds__(256, 2) mma_gemm_h(const __half* __restrict__ A,
                                                     const __half* __restrict__ Wm,
                                                     const float* __restrict__ bias,
                                                     const float* __restrict__ R,
                                                     void* __restrict__ OutV,
                                                     int N, int K) {
    extern __shared__ uint32_t sm[];
    uint32_t* As = sm;              // 3 stages x 4096 u32 (128 rows x 32 u32)
    uint32_t* Bs = sm + 12288;

    const int tid = threadIdx.x;
    const int wid = tid >> 5;
    const int lane = tid & 31;
    const long long m0 = (long long)blockIdx.y * 128;
    const int n0 = blockIdx.x * 128;

    const int wm = (wid >> 2) * 64;
    const int wn = (wid & 3) * 32;
    const int lm = lane >> 2;
    const int lk = lane & 3;

    const uint32_t as_b = (uint32_t)__cvta_generic_to_shared(As);
    const uint32_t bs_b = (uint32_t)__cvta_generic_to_shared(Bs);

    // cp.async mapping: id = tid + 256*j -> row = id>>3 (0..127), seg = id&7
    uint32_t soff[4];
    const __half* aptr[4];
    const __half* bptr[4];
#pragma unroll
    for (int j = 0; j < 4; j++) {
        const int id = tid + 256 * j;
        const int row = id >> 3;
        const int seg = id & 7;
        soff[j] = (uint32_t)(row * 32 + ((seg * 4) ^ ((row & 7) * 4))) * 4u;
        aptr[j] = A + (m0 + row) * (long long)K + seg * 8;
        bptr[j] = Wm + (long long)(n0 + row) * K + seg * 8;
    }

    const int KT = K >> 6;

    // ---- prologue: stages 0,1 ----
#pragma unroll
    for (int s = 0; s < 2; s++) {
        const uint32_t sb = s * 16384u;
#pragma unroll
        for (int j = 0; j < 4; j++) {
            cpa16(as_b + sb + soff[j], aptr[j] + s * 64);
            cpa16(bs_b + sb + soff[j], bptr[j] + s * 64);
        }
        CP_COMMIT();
    }

    // ldmatrix per-lane address components
    const int l8 = lane & 7;
    const int subm = (lane >> 3) & 1;    // A: m+8 select / B: k+8 select
    const int subk = lane >> 4;          // A: k+8 select / B: n+8 select
    uint32_t aRowOff[4], aSwz[4];
#pragma unroll
    for (int mf = 0; mf < 4; mf++) {
        const int rowA = wm + mf * 16 + subm * 8 + l8;
        aRowOff[mf] = (uint32_t)rowA * 32;
        aSwz[mf] = (uint32_t)(rowA & 7) * 4;
    }
    uint32_t bRowOff[2], bSwz[2];
#pragma unroll
    for (int p = 0; p < 2; p++) {
        const int rowB = wn + p * 16 + subk * 8 + l8;
        bRowOff[p] = (uint32_t)rowB * 32;
        bSwz[p] = (uint32_t)(rowB & 7) * 4;
    }

    float d[4][4][4];
#pragma unroll
    for (int i = 0; i < 4; i++)
#pragma unroll
        for (int j = 0; j < 4; j++)
#pragma unroll
            for (int q = 0; q < 4; q++) d[i][j][q] = 0.0f;

    int stage = 0;
    for (int kt = 0; kt < KT; kt++) {
        CP_WAIT1();
        __syncthreads();

        if (kt + 2 < KT) {
            const int s2 = stage + 2 >= 3 ? stage - 1 : stage + 2;
            const int ko = (kt + 2) * 64;
            const uint32_t sb = s2 * 16384u;
#pragma unroll
            for (int j = 0; j < 4; j++) {
                cpa16(as_b + sb + soff[j], aptr[j] + ko);
                cpa16(bs_b + sb + soff[j], bptr[j] + ko);
            }
        }
        CP_COMMIT();

        const uint32_t aBase = as_b + stage * 16384u;
        const uint32_t bBase = bs_b + stage * 16384u;
#pragma unroll
        for (int ks = 0; ks < 4; ks++) {
            const uint32_t kcA = (uint32_t)(ks * 8 + subk * 4);
            const uint32_t kcB = (uint32_t)(ks * 8 + subm * 4);
            uint32_t a[4][4];
#pragma unroll
            for (int mf = 0; mf < 4; mf++) {
                const uint32_t addr = aBase + (aRowOff[mf] + (kcA ^ aSwz[mf])) * 4u;
                LDSM_X4(a[mf][0], a[mf][1], a[mf][2], a[mf][3], addr);
            }
            uint32_t b[4][2];
#pragma unroll
            for (int p = 0; p < 2; p++) {
                const uint32_t addr = bBase + (bRowOff[p] + (kcB ^ bSwz[p])) * 4u;
                LDSM_X4(b[2 * p][0], b[2 * p][1], b[2 * p + 1][0], b[2 * p + 1][1], addr);
            }
#pragma unroll
            for (int mf = 0; mf < 4; mf++)
#pragma unroll
                for (int nf = 0; nf < 4; nf++)
                    MMA_H(d[mf][nf], a[mf][0], a[mf][1], a[mf][2], a[mf][3],
                          b[nf][0], b[nf][1]);
        }
        stage = stage + 1 >= 3 ? 0 : stage + 1;
    }

    // ---- epilogue ----
#pragma unroll
    for (int nf = 0; nf < 4; nf++) {
        const int gcol = n0 + wn + nf * 8 + 2 * lk;
        const float2 bv = *(const float2*)&bias[gcol];
#pragma unroll
        for (int mf = 0; mf < 4; mf++) {
            const long long row = m0 + wm + mf * 16 + lm;
            float2 v0, v1;
            v0.x = d[mf][nf][0] + bv.x;
            v0.y = d[mf][nf][1] + bv.y;
            v1.x = d[mf][nf][2] + bv.x;
            v1.y = d[mf][nf][3] + bv.y;
            if (EPI == 1) {
                float2 r0 = *(const float2*)&R[row * (long long)N + gcol];
                float2 r1 = *(const float2*)&R[(row + 8) * (long long)N + gcol];
                v0.x += r0.x; v0.y += r0.y;
                v1.x += r1.x; v1.y += r1.y;
                float* Out = (float*)OutV;
                *(float2*)&Out[row * (long long)N + gcol] = v0;
                *(float2*)&Out[(row + 8) * (long long)N + gcol] = v1;
            } else if (EPI == 3) {
                float2 r0 = *(const float2*)&R[row * (long long)N + gcol];
                float2 r1 = *(const float2*)&R[(row + 8) * (long long)N + gcol];
                v0.x += r0.x; v0.y += r0.y;
                v1.x += r1.x; v1.y += r1.y;
                const int n_ = (int)(row >> 6);
                const int t_ = (int)(row & 63);
                const int bb = n_ >> 8, wy = (n_ >> 4) & 15, wx = n_ & 15;
                const int hh = wy * 8 + (t_ >> 3), ww = wx * 8 + (t_ & 7);
                float* Out = (float*)OutV;
                const long long base0 =
                    ((long long)(bb * 256 + gcol) << 14) + hh * 128 + ww;
                Out[base0] = v0.x;
                Out[base0 + 16384] = v0.y;
                Out[base0 + 128] = v1.x;
                Out[base0 + 16384 + 128] = v1.y;
            } else {
                if (EPI == 2) {
                    v0.x = gelu_exact(v0.x); v0.y = gelu_exact(v0.y);
                    v1.x = gelu_exact(v1.x); v1.y = gelu_exact(v1.y);
                }
                __half* Out = (__half*)OutV;
                *(__half2*)&Out[row * (long long)N + gcol] = __floats2half2_rn(v0.x, v0.y);
                *(__half2*)&Out[(row + 8) * (long long)N + gcol] = __floats2half2_rn(v1.x, v1.y);
            }
        }
    }
}

// ===========================================================================
// Fused gather + LN1 (unchanged from R11)
// ===========================================================================
__global__ void __launch_bounds__(256) gather_ln(const float* __restrict__ x,
                                                 const float* __restrict__ g,
                                                 const float* __restrict__ b,
                                                 float* __restrict__ tok,
                                                 __half* __restrict__ yh) {
    extern __shared__ float st[];

    const int tid = threadIdx.x;
    const int n = blockIdx.x;
    const int bb = n >> 8, wy = (n >> 4) & 15, wx = n & 15;

#pragma unroll
    for (int j = 0; j < 8; j++) {
        const int p = tid + 256 * j;
        const int c = p >> 3;
        const int iy = p & 7;
        const float* xp = x + (((long long)(bb * 256 + c)) << 14)
                        + (wy * 8 + iy) * 128 + wx * 8;
        float4 u0 = *(const float4*)xp;
        float4 u1 = *(const float4*)(xp + 4);
        const int cs = c ^ (iy * 4);
        float* row0 = st + (iy * 8) * 256;
        row0[0 * 256 + cs] = u0.x;
        row0[1 * 256 + cs] = u0.y;
        row0[2 * 256 + cs] = u0.z;
        row0[3 * 256 + cs] = u0.w;
        row0[4 * 256 + cs] = u1.x;
        row0[5 * 256 + cs] = u1.y;
        row0[6 * 256 + cs] = u1.z;
        row0[7 * 256 + cs] = u1.w;
    }
    __syncthreads();

    const int w = tid >> 5, lane = tid & 31;
#pragma unroll
    for (int r = 0; r < 8; r++) {
        const int t = w * 8 + r;
        const int xr = ((t >> 3) & 7) * 4;
        const float* row = st + t * 256;
        float4 v0 = *(const float4*)&row[(4 * lane) ^ xr];
        float4 v1 = *(const float4*)&row[(128 + 4 * lane) ^ xr];

        float s = v0.x + v0.y + v0.z + v0.w + v1.x + v1.y + v1.z + v1.w;
#pragma unroll
        for (int o = 16; o; o >>= 1) s += __shfl_xor_sync(0xFFFFFFFFu, s, o);
        const float mu = s * (1.0f / 256.0f);

        float q = (v0.x - mu) * (v0.x - mu) + (v0.y - mu) * (v0.y - mu)
                + (v0.z - mu) * (v0.z - mu) + (v0.w - mu) * (v0.w - mu)
                + (v1.x - mu) * (v1.x - mu) + (v1.y - mu) * (v1.y - mu)
                + (v1.z - mu) * (v1.z - mu) + (v1.w - mu) * (v1.w - mu);
#pragma unroll
        for (int o = 16; o; o >>= 1) q += __shfl_xor_sync(0xFFFFFFFFu, q, o);
        const float rinv = rsqrtf(q * (1.0f / 256.0f) + 1e-5f);

        const long long grow = (long long)n * 64 + t;
        *(float4*)&tok[grow * CDIM + 4 * lane] = v0;
        *(float4*)&tok[grow * CDIM + 128 + 4 * lane] = v1;

        float4 g0 = *(const float4*)&g[4 * lane];
        float4 g1 = *(const float4*)&g[128 + 4 * lane];
        float4 b0 = *(const float4*)&b[4 * lane];
        float4 b1 = *(const float4*)&b[128 + 4 * lane];
        __half* yrow = yh + grow * CDIM;
        *(__half2*)&yrow[4 * lane] = __floats2half2_rn((v0.x - mu) * rinv * g0.x + b0.x,
                                                       (v0.y - mu) * rinv * g0.y + b0.y);
        *(__half2*)&yrow[4 * lane + 2] = __floats2half2_rn((v0.z - mu) * rinv * g0.z + b0.z,
                                                           (v0.w - mu) * rinv * g0.w + b0.w);
        *(__half2*)&yrow[128 + 4 * lane] = __floats2half2_rn((v1.x - mu) * rinv * g1.x + b1.x,
                                                             (v1.y - mu) * rinv * g1.y + b1.y);
        *(__half2*)&yrow[128 + 4 * lane + 2] = __floats2half2_rn((v1.z - mu) * rinv * g1.z + b1.z,
                                                                 (v1.w - mu) * rinv * g1.w + b1.w);
    }
}

// ===========================================================================
// LayerNorm (LN2): fp32 in -> fp16 out (unchanged)
// ===========================================================================
__global__ void __launch_bounds__(256) ln_kernel(const float* __restrict__ A,
                                                 const float* __restrict__ g,
                                                 const float* __restrict__ b,
                                                 __half* __restrict__ Y) {
    const long long row = (long long)blockIdx.x * 8 + (threadIdx.x >> 5);
    const int lane = threadIdx.x & 31;
    const float4* ap = (const float4*)(A + row * CDIM);
    float4 v0 = ap[lane];
    float4 v1 = ap[lane + 32];

    float s = v0.x + v0.y + v0.z + v0.w + v1.x + v1.y + v1.z + v1.w;
#pragma unroll
    for (int o = 16; o; o >>= 1) s += __shfl_xor_sync(0xFFFFFFFFu, s, o);
    const float mu = s * (1.0f / 256.0f);

    float q = (v0.x - mu) * (v0.x - mu) + (v0.y - mu) * (v0.y - mu)
            + (v0.z - mu) * (v0.z - mu) + (v0.w - mu) * (v0.w - mu)
            + (v1.x - mu) * (v1.x - mu) + (v1.y - mu) * (v1.y - mu)
            + (v1.z - mu) * (v1.z - mu) + (v1.w - mu) * (v1.w - mu);
#pragma unroll
    for (int o = 16; o; o >>= 1) q += __shfl_xor_sync(0xFFFFFFFFu, q, o);
    const float rinv = rsqrtf(q * (1.0f / 256.0f) + 1e-5f);

    const float4* gp = (const float4*)g;
    const float4* bp = (const float4*)b;
    float4 g0 = gp[lane], g1 = gp[lane + 32];
    float4 b0 = bp[lane], b1 = bp[lane + 32];

    __half* yrow = Y + row * CDIM;
    *(__half2*)&yrow[lane * 4]       = __floats2half2_rn((v0.x - mu) * rinv * g0.x + b0.x,
                                                         (v0.y - mu) * rinv * g0.y + b0.y);
    *(__half2*)&yrow[lane * 4 + 2]   = __floats2half2_rn((v0.z - mu) * rinv * g0.z + b0.z,
                                                         (v0.w - mu) * rinv * g0.w + b0.w);
    *(__half2*)&yrow[lane * 4 + 128] = __floats2half2_rn((v1.x - mu) * rinv * g1.x + b1.x,
                                                         (v1.y - mu) * rinv * g1.y + b1.y);
    *(__half2*)&yrow[lane * 4 + 130] = __floats2half2_rn((v1.z - mu) * rinv * g1.z + b1.z,
                                                         (v1.w - mu) * rinv * g1.w + b1.w);
}

// ===========================================================================
// Tensor-core window attention (unchanged from R10/R11)
// ===========================================================================
#define SQK_STRIDE 520
#define SVT_H 2304
#define ATTN_SMEM ((64 * SQK_STRIDE + 8 * SVT_H) * 2)

__global__ void __launch_bounds__(512) attn_mma(const __half* __restrict__ qkv,
                                                __half* __restrict__ o) {
    extern __shared__ __half sm_h[];
    __half* sqk = sm_h;
    __half* svt = sm_h + 64 * SQK_STRIDE;

    const int tid = threadIdx.x;
    const int n = blockIdx.x;
    const long long gbase = (long long)n * 64 * 768;

#pragma unroll
    for (int i = 0; i < 8; i++) {
        const int c = tid + 512 * i;
        const int t = c >> 6;
        const int col = (c & 63) * 8;
        *(uint4*)&sqk[t * SQK_STRIDE + col] = *(const uint4*)&qkv[gbase + t * 768 + col];
    }
#pragma unroll
    for (int i = 0; i < 16; i++) {
        const int p = tid + 512 * i;
        const int t = p >> 7;
        const int d0 = (p & 127) * 2;
        __half2 v = *(const __half2*)&qkv[gbase + t * 768 + 512 + d0];
        const int h = d0 >> 5, dh = d0 & 31;
        svt[h * SVT_H + dh * 72 + t] = __low2half(v);
        svt[h * SVT_H + (dh + 1) * 72 + t] = __high2half(v);
    }
    __syncthreads();

    const int w = tid >> 5, lane = tid & 31;
    const int h = w >> 1, rh = w & 1;
    const int lm = lane >> 2, lk = lane & 3;

    const __half* qb = sqk + h * 32 + 2 * lk;
    const __half* kb = sqk + 256 + h * 32 + 2 * lk;

    float acc[2][8][4];
#pragma unroll
    for (int i = 0; i < 2; i++)
#pragma unroll
        for (int j = 0; j < 8; j++)
#pragma unroll
            for (int q = 0; q < 4; q++) acc[i][j][q] = 0.0f;

#pragma unroll
    for (int kt = 0; kt < 2; kt++) {
        uint32_t a[2][4];
#pragma unroll
        for (int mt = 0; mt < 2; mt++) {
            const int r0 = rh * 32 + mt * 16 + lm;
            const __half* q0 = qb + kt * 16;
            a[mt][0] = *(const uint32_t*)&q0[r0 * SQK_STRIDE];
            a[mt][1] = *(const uint32_t*)&q0[(r0 + 8) * SQK_STRIDE];
            a[mt][2] = *(const uint32_t*)&q0[r0 * SQK_STRIDE + 8];
            a[mt][3] = *(const uint32_t*)&q0[(r0 + 8) * SQK_STRIDE + 8];
        }
#pragma unroll
        for (int nt = 0; nt < 8; nt++) {
            const int kr = nt * 8 + lm;
            const __half* k0 = kb + kt * 16;
            uint32_t b0 = *(const uint32_t*)&k0[kr * SQK_STRIDE];
            uint32_t b1 = *(const uint32_t*)&k0[kr * SQK_STRIDE + 8];
#pragma unroll
            for (int mt = 0; mt < 2; mt++)
                MMA_H(acc[mt][nt], a[mt][0], a[mt][1], a[mt][2], a[mt][3], b0, b1);
        }
    }

    const float cs = 0.17677669529663689f * 1.4426950408889634f;
    float rs[2][2];
#pragma unroll
    for (int mt = 0; mt < 2; mt++) {
        float m0 = -1e30f, m1 = -1e30f;
#pragma unroll
        for (int nt = 0; nt < 8; nt++) {
            m0 = fmaxf(m0, fmaxf(acc[mt][nt][0], acc[mt][nt][1]));
            m1 = fmaxf(m1, fmaxf(acc[mt][nt][2], acc[mt][nt][3]));
        }
        m0 = fmaxf(m0, __shfl_xor_sync(0xFFFFFFFFu, m0, 1));
        m0 = fmaxf(m0, __shfl_xor_sync(0xFFFFFFFFu, m0, 2));
        m1 = fmaxf(m1, __shfl_xor_sync(0xFFFFFFFFu, m1, 1));
        m1 = fmaxf(m1, __shfl_xor_sync(0xFFFFFFFFu, m1, 2));
        float s0 = 0.0f, s1 = 0.0f;
#pragma unroll
        for (int nt = 0; nt < 8; nt++) {
            float e0 = exp2f((acc[mt][nt][0] - m0) * cs);
            float e1 = exp2f((acc[mt][nt][1] - m0) * cs);
            float e2 = exp2f((acc[mt][nt][2] - m1) * cs);
            float e3 = exp2f((acc[mt][nt][3] - m1) * cs);
            acc[mt][nt][0] = e0; acc[mt][nt][1] = e1;
            acc[mt][nt][2] = e2; acc[mt][nt][3] = e3;
            s0 += e0 + e1; s1 += e2 + e3;
        }
        s0 += __shfl_xor_sync(0xFFFFFFFFu, s0, 1);
        s0 += __shfl_xor_sync(0xFFFFFFFFu, s0, 2);
        s1 += __shfl_xor_sync(0xFFFFFFFFu, s1, 1);
        s1 += __shfl_xor_sync(0xFFFFFFFFu, s1, 2);
        rs[mt][0] = 1.0f / s0;
        rs[mt][1] = 1.0f / s1;
    }

    float oacc[2][4][4];
#pragma unroll
    for (int i = 0; i < 2; i++)
#pragma unroll
        for (int j = 0; j < 4; j++)
#pragma unroll
            for (int q = 0; q < 4; q++) oacc[i][j][q] = 0.0f;

    const __half* vb0 = svt + h * SVT_H + 2 * lk;
#pragma unroll
    for (int kt4 = 0; kt4 < 4; kt4++) {
        uint32_t pa[2][4];
#pragma unroll
        for (int mt = 0; mt < 2; mt++) {
            pa[mt][0] = h2_u32(__floats2half2_rn(acc[mt][2 * kt4][0], acc[mt][2 * kt4][1]));
            pa[mt][1] = h2_u32(__floats2half2_rn(acc[mt][2 * kt4][2], acc[mt][2 * kt4][3]));
            pa[mt][2] = h2_u32(__floats2half2_rn(acc[mt][2 * kt4 + 1][0], acc[mt][2 * kt4 + 1][1]));
            pa[mt][3] = h2_u32(__floats2half2_rn(acc[mt][2 * kt4 + 1][2], acc[mt][2 * kt4 + 1][3]));
        }
#pragma unroll
        for (int dn = 0; dn < 4; dn++) {
            const __half* vb = vb0 + (dn * 8 + lm) * 72 + kt4 * 16;
            uint32_t b0 = *(const uint32_t*)&vb[0];
            uint32_t b1 = *(const uint32_t*)&vb[8];
#pragma unroll
            for (int mt = 0; mt < 2; mt++)
                MMA_H(oacc[mt][dn], pa[mt][0], pa[mt][1], pa[mt][2], pa[mt][3], b0, b1);
        }
    }

#pragma unroll
    for (int mt = 0; mt < 2; mt++) {
        const int r0 = rh * 32 + mt * 16 + lm;
#pragma unroll
        for (int dn = 0; dn < 4; dn++) {
            const int col = h * 32 + dn * 8 + 2 * lk;
            __half* o0 = o + ((long long)n * 64 + r0) * CDIM + col;
            __half* o1 = o + ((long long)n * 64 + r0 + 8) * CDIM + col;
            *(__half2*)o0 = __floats2half2_rn(oacc[mt][dn][0] * rs[mt][0],
                                              oacc[mt][dn][1] * rs[mt][0]);
            *(__half2*)o1 = __floats2half2_rn(oacc[mt][dn][2] * rs[mt][1],
                                              oacc[mt][dn][3] * rs[mt][1]);
        }
    }
}

// ===========================================================================
// Launch
// ===========================================================================
extern "C" void kernel_launch(void* const* d_in, const int* in_sizes, int n_in,
                              void* d_out, int out_size) {
    const float* x      = (const float*)d_in[0];
    const float* qkv_w  = (const float*)d_in[1];
    const float* qkv_b  = (const float*)d_in[2];
    const float* proj_w = (const float*)d_in[3];
    const float* proj_b = (const float*)d_in[4];
    const float* n1_g   = (const float*)d_in[5];
    const float* n1_b   = (const float*)d_in[6];
    const float* n2_g   = (const float*)d_in[7];
    const float* n2_b   = (const float*)d_in[8];
    const float* fc1_w  = (const float*)d_in[9];
    const float* fc1_b  = (const float*)d_in[10];
    const float* fc2_w  = (const float*)d_in[11];
    const float* fc2_b  = (const float*)d_in[12];
    float* out = (float*)d_out;

    float *tok;
    __half *yh, *qkvh, *oh, *hidh, *wh;
    cudaGetSymbolAddress((void**)&tok, g_tok);
    cudaGetSymbolAddress((void**)&yh, g_yh);
    cudaGetSymbolAddress((void**)&qkvh, g_qkvh);
    cudaGetSymbolAddress((void**)&oh, g_oh);
    cudaGetSymbolAddress((void**)&hidh, g_hidh);
    cudaGetSymbolAddress((void**)&wh, g_wh);

    cudaFuncSetAttribute(attn_mma, cudaFuncAttributeMaxDynamicSharedMemorySize, ATTN_SMEM);
    const int GLN_SMEM = 64 * 256 * 4;
    cudaFuncSetAttribute(gather_ln, cudaFuncAttributeMaxDynamicSharedMemorySize, GLN_SMEM);
    const int GEMM_SMEM = 98304;  // 3 stages x (16KB A + 16KB B)
    cudaFuncSetAttribute(mma_gemm_h<0>, cudaFuncAttributeMaxDynamicSharedMemorySize, GEMM_SMEM);
    cudaFuncSetAttribute(mma_gemm_h<1>, cudaFuncAttributeMaxDynamicSharedMemorySize, GEMM_SMEM);
    cudaFuncSetAttribute(mma_gemm_h<2>, cudaFuncAttributeMaxDynamicSharedMemorySize, GEMM_SMEM);
    cudaFuncSetAttribute(mma_gemm_h<3>, cudaFuncAttributeMaxDynamicSharedMemorySize, GEMM_SMEM);

    const int MT = NTOK / 128;  // 2048 M-tiles

    // 0. weights -> fp16
    cvt_weights<<<512, 256>>>(qkv_w, proj_w, fc1_w, fc2_w);
    // 1+2. window partition + LN1 (fused)
    gather_ln<<<4096, 256, GLN_SMEM>>>(x, n1_g, n1_b, tok, yh);
    // 3. QKV gemm
    mma_gemm_h<0><<<dim3(6, MT), 256, GEMM_SMEM>>>(yh, wh + WOFF_QKV, qkv_b, nullptr, qkvh, 768, 256);
    // 4. windowed attention
    attn_mma<<<4096, 512, ATTN_SMEM>>>(qkvh, oh);
    // 5. proj gemm + residual -> tok
    mma_gemm_h<1><<<dim3(2, MT), 256, GEMM_SMEM>>>(oh, wh + WOFF_PROJ, proj_b, tok, tok, 256, 256);
    // 6. LN2 -> fp16
    ln_kernel<<<NTOK / 8, 256>>>(tok, n2_g, n2_b, yh);
    // 7. fc1 gemm + GELU
    mma_gemm_h<2><<<dim3(8, MT), 256, GEMM_SMEM>>>(yh, wh + WOFF_FC1, fc1_b, nullptr, hidh, 1024, 256);
    // 8. fc2 gemm + residual + scatter -> out
    mma_gemm_h<3><<<dim3(2, MT), 256, GEMM_SMEM>>>(hidh, wh + WOFF_FC2, fc2_b, tok, out, 256, 1024);
}

// round 14
// speedup vs baseline: 3.0288x; 1.0107x over previous
#include <cuda_runtime.h>
#include <cuda_fp16.h>
#include <math.h>
#include <cstdint>

// Problem constants
#define B_ 16
#define CDIM 256
#define H_ 128
#define W_ 128
#define NTOK 262144   // B*H*W tokens

// Scratch (device globals)
__device__ float  g_tok[67108864];     // [NTOK, 256] fp32 residual stream
__device__ __half g_yh[67108864];      // [NTOK, 256] LN output fp16
__device__ __half g_qkvh[201326592];   // [NTOK, 768] fp16
__device__ __half g_oh[67108864];      // [NTOK, 256] fp16
__device__ __half g_hidh[268435456];   // [NTOK, 1024] fp16
__device__ __half g_wh[786432];        // qkv_w|proj_w|fc1_w|fc2_w fp16

#define WOFF_QKV 0
#define WOFF_PROJ 196608
#define WOFF_FC1 262144
#define WOFF_FC2 524288

__device__ __forceinline__ float gelu_exact(float v) {
    return 0.5f * v * (1.0f + erff(v * 0.70710678118654752f));
}

__device__ __forceinline__ uint32_t h2_u32(__half2 v) {
    return *reinterpret_cast<uint32_t*>(&v);
}

__device__ __forceinline__ void cpa16(uint32_t dst, const void* src) {
    asm volatile("cp.async.cg.shared.global [%0], [%1], 16;" :: "r"(dst), "l"(src));
}
#define CP_COMMIT() asm volatile("cp.async.commit_group;" ::: "memory")
#define CP_WAIT1()  asm volatile("cp.async.wait_group 1;" ::: "memory")

#define MMA_H(dd, a0, a1, a2, a3, b0, b1) \
    asm volatile( \
        "mma.sync.aligned.m16n8k16.row.col.f32.f16.f16.f32 " \
        "{%0,%1,%2,%3}, {%4,%5,%6,%7}, {%8,%9}, {%0,%1,%2,%3};" \
        : "+f"((dd)[0]), "+f"((dd)[1]), "+f"((dd)[2]), "+f"((dd)[3]) \
        : "r"(a0), "r"(a1), "r"(a2), "r"(a3), "r"(b0), "r"(b1))

#define LDSM_X4(r0, r1, r2, r3, addr) \
    asm volatile("ldmatrix.sync.aligned.m8n8.x4.shared.b16 {%0,%1,%2,%3}, [%4];" \
        : "=r"(r0), "=r"(r1), "=r"(r2), "=r"(r3) : "r"(addr))

// ===========================================================================
// Weight conversion fp32 -> fp16
// ===========================================================================
__global__ void __launch_bounds__(256) cvt_weights(const float* __restrict__ qkv_w,
                                                   const float* __restrict__ proj_w,
                                                   const float* __restrict__ fc1_w,
                                                   const float* __restrict__ fc2_w) {
    for (int i = blockIdx.x * 256 + threadIdx.x; i < 786432; i += gridDim.x * 256) {
        float v;
        if (i < WOFF_PROJ)      v = qkv_w[i - WOFF_QKV];
        else if (i < WOFF_FC1)  v = proj_w[i - WOFF_PROJ];
        else if (i < WOFF_FC2)  v = fc1_w[i - WOFF_FC1];
        else                    v = fc2_w[i - WOFF_FC2];
        g_wh[i] = __float2half_rn(v);
    }
}

// ===========================================================================
// FP16 mma.sync GEMM, ldmatrix fragment loads (unchanged from R12).
// EPI: 0=bias->f16, 2=bias+GELU->f16, 3=bias+residual->scatter NCHW fp32
// ===========================================================================
template <int EPI>
__global__ void __launch_bounds__(256, 2) mma_gemm_h(const __half* __restrict__ A,
                                                     const __half* __restrict__ Wm,
                                                     const float* __restrict__ bias,
                                                     const float* __restrict__ R,
                                                     void* __restrict__ OutV,
                                                     int N, int K) {
    extern __shared__ uint32_t sm[];
    uint32_t* As = sm;
    uint32_t* Bs = sm + 12288;

    const int tid = threadIdx.x;
    const int wid = tid >> 5;
    const int lane = tid & 31;
    const long long m0 = (long long)blockIdx.y * 128;
    const int n0 = blockIdx.x * 128;

    const int wm = (wid >> 2) * 64;
    const int wn = (wid & 3) * 32;
    const int lm = lane >> 2;
    const int lk = lane & 3;

    const uint32_t as_b = (uint32_t)__cvta_generic_to_shared(As);
    const uint32_t bs_b = (uint32_t)__cvta_generic_to_shared(Bs);

    uint32_t soff[4];
    const __half* aptr[4];
    const __half* bptr[4];
#pragma unroll
    for (int j = 0; j < 4; j++) {
        const int id = tid + 256 * j;
        const int row = id >> 3;
        const int seg = id & 7;
        soff[j] = (uint32_t)(row * 32 + ((seg * 4) ^ ((row & 7) * 4))) * 4u;
        aptr[j] = A + (m0 + row) * (long long)K + seg * 8;
        bptr[j] = Wm + (long long)(n0 + row) * K + seg * 8;
    }

    const int KT = K >> 6;

#pragma unroll
    for (int s = 0; s < 2; s++) {
        const uint32_t sb = s * 16384u;
#pragma unroll
        for (int j = 0; j < 4; j++) {
            cpa16(as_b + sb + soff[j], aptr[j] + s * 64);
            cpa16(bs_b + sb + soff[j], bptr[j] + s * 64);
        }
        CP_COMMIT();
    }

    const int l8 = lane & 7;
    const int subm = (lane >> 3) & 1;
    const int subk = lane >> 4;
    uint32_t aRowOff[4], aSwz[4];
#pragma unroll
    for (int mf = 0; mf < 4; mf++) {
        const int rowA = wm + mf * 16 + subm * 8 + l8;
        aRowOff[mf] = (uint32_t)rowA * 32;
        aSwz[mf] = (uint32_t)(rowA & 7) * 4;
    }
    uint32_t bRowOff[2], bSwz[2];
#pragma unroll
    for (int p = 0; p < 2; p++) {
        const int rowB = wn + p * 16 + subk * 8 + l8;
        bRowOff[p] = (uint32_t)rowB * 32;
        bSwz[p] = (uint32_t)(rowB & 7) * 4;
    }

    float d[4][4][4];
#pragma unroll
    for (int i = 0; i < 4; i++)
#pragma unroll
        for (int j = 0; j < 4; j++)
#pragma unroll
            for (int q = 0; q < 4; q++) d[i][j][q] = 0.0f;

    int stage = 0;
    for (int kt = 0; kt < KT; kt++) {
        CP_WAIT1();
        __syncthreads();

        if (kt + 2 < KT) {
            const int s2 = stage + 2 >= 3 ? stage - 1 : stage + 2;
            const int ko = (kt + 2) * 64;
            const uint32_t sb = s2 * 16384u;
#pragma unroll
            for (int j = 0; j < 4; j++) {
                cpa16(as_b + sb + soff[j], aptr[j] + ko);
                cpa16(bs_b + sb + soff[j], bptr[j] + ko);
            }
        }
        CP_COMMIT();

        const uint32_t aBase = as_b + stage * 16384u;
        const uint32_t bBase = bs_b + stage * 16384u;
#pragma unroll
        for (int ks = 0; ks < 4; ks++) {
            const uint32_t kcA = (uint32_t)(ks * 8 + subk * 4);
            const uint32_t kcB = (uint32_t)(ks * 8 + subm * 4);
            uint32_t a[4][4];
#pragma unroll
            for (int mf = 0; mf < 4; mf++) {
                const uint32_t addr = aBase + (aRowOff[mf] + (kcA ^ aSwz[mf])) * 4u;
                LDSM_X4(a[mf][0], a[mf][1], a[mf][2], a[mf][3], addr);
            }
            uint32_t b[4][2];
#pragma unroll
            for (int p = 0; p < 2; p++) {
                const uint32_t addr = bBase + (bRowOff[p] + (kcB ^ bSwz[p])) * 4u;
                LDSM_X4(b[2 * p][0], b[2 * p][1], b[2 * p + 1][0], b[2 * p + 1][1], addr);
            }
#pragma unroll
            for (int mf = 0; mf < 4; mf++)
#pragma unroll
                for (int nf = 0; nf < 4; nf++)
                    MMA_H(d[mf][nf], a[mf][0], a[mf][1], a[mf][2], a[mf][3],
                          b[nf][0], b[nf][1]);
        }
        stage = stage + 1 >= 3 ? 0 : stage + 1;
    }

#pragma unroll
    for (int nf = 0; nf < 4; nf++) {
        const int gcol = n0 + wn + nf * 8 + 2 * lk;
        const float2 bv = *(const float2*)&bias[gcol];
#pragma unroll
        for (int mf = 0; mf < 4; mf++) {
            const long long row = m0 + wm + mf * 16 + lm;
            float2 v0, v1;
            v0.x = d[mf][nf][0] + bv.x;
            v0.y = d[mf][nf][1] + bv.y;
            v1.x = d[mf][nf][2] + bv.x;
            v1.y = d[mf][nf][3] + bv.y;
            if (EPI == 3) {
                float2 r0 = *(const float2*)&R[row * (long long)N + gcol];
                float2 r1 = *(const float2*)&R[(row + 8) * (long long)N + gcol];
                v0.x += r0.x; v0.y += r0.y;
                v1.x += r1.x; v1.y += r1.y;
                const int n_ = (int)(row >> 6);
                const int t_ = (int)(row & 63);
                const int bb = n_ >> 8, wy = (n_ >> 4) & 15, wx = n_ & 15;
                const int hh = wy * 8 + (t_ >> 3), ww = wx * 8 + (t_ & 7);
                float* Out = (float*)OutV;
                const long long base0 =
                    ((long long)(bb * 256 + gcol) << 14) + hh * 128 + ww;
                Out[base0] = v0.x;
                Out[base0 + 16384] = v0.y;
                Out[base0 + 128] = v1.x;
                Out[base0 + 16384 + 128] = v1.y;
            } else {
                if (EPI == 2) {
                    v0.x = gelu_exact(v0.x); v0.y = gelu_exact(v0.y);
                    v1.x = gelu_exact(v1.x); v1.y = gelu_exact(v1.y);
                }
                __half* Out = (__half*)OutV;
                *(__half2*)&Out[row * (long long)N + gcol] = __floats2half2_rn(v0.x, v0.y);
                *(__half2*)&Out[(row + 8) * (long long)N + gcol] = __floats2half2_rn(v1.x, v1.y);
            }
        }
    }
}

// ===========================================================================
// Fused proj GEMM + residual + LN2 (unchanged from R13)
// ===========================================================================
#define PROJ_SMEM (147456 + 4096 + 1024)

__global__ void __launch_bounds__(512) proj_ln(const __half* __restrict__ A,
                                               const __half* __restrict__ Wm,
                                               const float* __restrict__ bias,
                                               float* __restrict__ tok,
                                               const float* __restrict__ g2,
                                               const float* __restrict__ b2,
                                               __half* __restrict__ yh) {
    extern __shared__ uint32_t sm[];
    uint32_t* As = sm;
    uint32_t* Bs = sm + 12288;
    float* spart = (float*)(sm + 36864);
    float* smr   = spart + 1024;

    const int tid = threadIdx.x;
    const int wid = tid >> 5;
    const int lane = tid & 31;
    const long long m0 = (long long)blockIdx.x * 128;

    const int wr = wid >> 2;
    const int wc = wid & 3;
    const int lm = lane >> 2;
    const int lk = lane & 3;

    const uint32_t as_b = (uint32_t)__cvta_generic_to_shared(As);
    const uint32_t bs_b = (uint32_t)__cvta_generic_to_shared(Bs);

    uint32_t aoff[2];
    const __half* aptr[2];
#pragma unroll
    for (int j = 0; j < 2; j++) {
        const int id = tid + 512 * j;
        const int row = id >> 3;
        const int seg = id & 7;
        aoff[j] = (uint32_t)(row * 32 + ((seg * 4) ^ ((row & 7) * 4))) * 4u;
        aptr[j] = A + (m0 + row) * 256LL + seg * 8;
    }
    uint32_t boff[4];
    const __half* bptr[4];
#pragma unroll
    for (int j = 0; j < 4; j++) {
        const int id = tid + 512 * j;
        const int row = id >> 3;
        const int seg = id & 7;
        boff[j] = (uint32_t)(row * 32 + ((seg * 4) ^ ((row & 7) * 4))) * 4u;
        bptr[j] = Wm + (long long)row * 256 + seg * 8;
    }

#pragma unroll
    for (int s = 0; s < 2; s++) {
        const uint32_t sbA = s * 16384u;
        const uint32_t sbB = s * 32768u;
#pragma unroll
        for (int j = 0; j < 2; j++) cpa16(as_b + sbA + aoff[j], aptr[j] + s * 64);
#pragma unroll
        for (int j = 0; j < 4; j++) cpa16(bs_b + sbB + boff[j], bptr[j] + s * 64);
        CP_COMMIT();
    }

    const int l8 = lane & 7;
    const int subm = (lane >> 3) & 1;
    const int subk = lane >> 4;
    uint32_t aRowOff[2], aSwz[2];
#pragma unroll
    for (int mf = 0; mf < 2; mf++) {
        const int rowA = wr * 32 + mf * 16 + subm * 8 + l8;
        aRowOff[mf] = (uint32_t)rowA * 32;
        aSwz[mf] = (uint32_t)(rowA & 7) * 4;
    }
    uint32_t bRowOff[4], bSwz[4];
#pragma unroll
    for (int p = 0; p < 4; p++) {
        const int rowB = wc * 64 + p * 16 + subk * 8 + l8;
        bRowOff[p] = (uint32_t)rowB * 32;
        bSwz[p] = (uint32_t)(rowB & 7) * 4;
    }

    float d[2][8][4];
#pragma unroll
    for (int i = 0; i < 2; i++)
#pragma unroll
        for (int j = 0; j < 8; j++)
#pragma unroll
            for (int q = 0; q < 4; q++) d[i][j][q] = 0.0f;

    int stage = 0;
    for (int kt = 0; kt < 4; kt++) {
        CP_WAIT1();
        __syncthreads();

        if (kt + 2 < 4) {
            const int s2 = stage + 2 >= 3 ? stage - 1 : stage + 2;
            const int ko = (kt + 2) * 64;
            const uint32_t sbA = s2 * 16384u;
            const uint32_t sbB = s2 * 32768u;
#pragma unroll
            for (int j = 0; j < 2; j++) cpa16(as_b + sbA + aoff[j], aptr[j] + ko);
#pragma unroll
            for (int j = 0; j < 4; j++) cpa16(bs_b + sbB + boff[j], bptr[j] + ko);
        }
        CP_COMMIT();

        const uint32_t aBase = as_b + stage * 16384u;
        const uint32_t bBase = bs_b + stage * 32768u;
#pragma unroll
        for (int ks = 0; ks < 4; ks++) {
            const uint32_t kcA = (uint32_t)(ks * 8 + subk * 4);
            const uint32_t kcB = (uint32_t)(ks * 8 + subm * 4);
            uint32_t a[2][4];
#pragma unroll
            for (int mf = 0; mf < 2; mf++) {
                const uint32_t addr = aBase + (aRowOff[mf] + (kcA ^ aSwz[mf])) * 4u;
                LDSM_X4(a[mf][0], a[mf][1], a[mf][2], a[mf][3], addr);
            }
            uint32_t b[8][2];
#pragma unroll
            for (int p = 0; p < 4; p++) {
                const uint32_t addr = bBase + (bRowOff[p] + (kcB ^ bSwz[p])) * 4u;
                LDSM_X4(b[2 * p][0], b[2 * p][1], b[2 * p + 1][0], b[2 * p + 1][1], addr);
            }
#pragma unroll
            for (int mf = 0; mf < 2; mf++)
#pragma unroll
                for (int nf = 0; nf < 8; nf++)
                    MMA_H(d[mf][nf], a[mf][0], a[mf][1], a[mf][2], a[mf][3],
                          b[nf][0], b[nf][1]);
        }
        stage = stage + 1 >= 3 ? 0 : stage + 1;
    }

    float rsum[2][2], rsq[2][2];
#pragma unroll
    for (int i = 0; i < 2; i++) { rsum[i][0] = rsum[i][1] = 0.0f; rsq[i][0] = rsq[i][1] = 0.0f; }

#pragma unroll
    for (int nf = 0; nf < 8; nf++) {
        const int gcol = wc * 64 + nf * 8 + 2 * lk;
        const float2 bv = *(const float2*)&bias[gcol];
#pragma unroll
        for (int mf = 0; mf < 2; mf++) {
            const long long r0 = m0 + wr * 32 + mf * 16 + lm;
            float2 q0 = *(const float2*)&tok[r0 * 256 + gcol];
            float2 q1 = *(const float2*)&tok[(r0 + 8) * 256 + gcol];
            float2 v0, v1;
            v0.x = d[mf][nf][0] + bv.x + q0.x;
            v0.y = d[mf][nf][1] + bv.y + q0.y;
            v1.x = d[mf][nf][2] + bv.x + q1.x;
            v1.y = d[mf][nf][3] + bv.y + q1.y;
            d[mf][nf][0] = v0.x; d[mf][nf][1] = v0.y;
            d[mf][nf][2] = v1.x; d[mf][nf][3] = v1.y;
            *(float2*)&tok[r0 * 256 + gcol] = v0;
            *(float2*)&tok[(r0 + 8) * 256 + gcol] = v1;
            rsum[mf][0] += v0.x + v0.y;  rsq[mf][0] += v0.x * v0.x + v0.y * v0.y;
            rsum[mf][1] += v1.x + v1.y;  rsq[mf][1] += v1.x * v1.x + v1.y * v1.y;
        }
    }
#pragma unroll
    for (int mf = 0; mf < 2; mf++)
#pragma unroll
        for (int s = 0; s < 2; s++) {
            rsum[mf][s] += __shfl_xor_sync(0xFFFFFFFFu, rsum[mf][s], 1);
            rsum[mf][s] += __shfl_xor_sync(0xFFFFFFFFu, rsum[mf][s], 2);
            rsq[mf][s]  += __shfl_xor_sync(0xFFFFFFFFu, rsq[mf][s], 1);
            rsq[mf][s]  += __shfl_xor_sync(0xFFFFFFFFu, rsq[mf][s], 2);
        }
    if (lk == 0) {
#pragma unroll
        for (int mf = 0; mf < 2; mf++)
#pragma unroll
            for (int s = 0; s < 2; s++) {
                const int r = wr * 32 + mf * 16 + s * 8 + lm;
                spart[(r * 4 + wc) * 2] = rsum[mf][s];
                spart[(r * 4 + wc) * 2 + 1] = rsq[mf][s];
            }
    }
    __syncthreads();
    if (tid < 128) {
        float s = 0.0f, q = 0.0f;
#pragma unroll
        for (int c = 0; c < 4; c++) {
            s += spart[(tid * 4 + c) * 2];
            q += spart[(tid * 4 + c) * 2 + 1];
        }
        const float mu = s * (1.0f / 256.0f);
        const float var = q * (1.0f / 256.0f) - mu * mu;
        smr[tid * 2] = mu;
        smr[tid * 2 + 1] = rsqrtf(var + 1e-5f);
    }
    __syncthreads();

#pragma unroll
    for (int nf = 0; nf < 8; nf++) {
        const int gcol = wc * 64 + nf * 8 + 2 * lk;
        const float2 gv = *(const float2*)&g2[gcol];
        const float2 bv = *(const float2*)&b2[gcol];
#pragma unroll
        for (int mf = 0; mf < 2; mf++) {
            const int rl0 = wr * 32 + mf * 16 + lm;
            const float mu0 = smr[rl0 * 2],       ri0 = smr[rl0 * 2 + 1];
            const float mu1 = smr[(rl0 + 8) * 2], ri1 = smr[(rl0 + 8) * 2 + 1];
            const long long r0 = m0 + rl0;
            __half2 h0 = __floats2half2_rn((d[mf][nf][0] - mu0) * ri0 * gv.x + bv.x,
                                           (d[mf][nf][1] - mu0) * ri0 * gv.y + bv.y);
            __half2 h1 = __floats2half2_rn((d[mf][nf][2] - mu1) * ri1 * gv.x + bv.x,
                                           (d[mf][nf][3] - mu1) * ri1 * gv.y + bv.y);
            *(__half2*)&yh[r0 * 256 + gcol] = h0;
            *(__half2*)&yh[(r0 + 8) * 256 + gcol] = h1;
        }
    }
}

// ===========================================================================
// Fused gather + LN1 (unchanged)
// ===========================================================================
__global__ void __launch_bounds__(256) gather_ln(const float* __restrict__ x,
                                                 const float* __restrict__ g,
                                                 const float* __restrict__ b,
                                                 float* __restrict__ tok,
                                                 __half* __restrict__ yh) {
    extern __shared__ float st[];

    const int tid = threadIdx.x;
    const int n = blockIdx.x;
    const int bb = n >> 8, wy = (n >> 4) & 15, wx = n & 15;

#pragma unroll
    for (int j = 0; j < 8; j++) {
        const int p = tid + 256 * j;
        const int c = p >> 3;
        const int iy = p & 7;
        const float* xp = x + (((long long)(bb * 256 + c)) << 14)
                        + (wy * 8 + iy) * 128 + wx * 8;
        float4 u0 = *(const float4*)xp;
        float4 u1 = *(const float4*)(xp + 4);
        const int cs = c ^ (iy * 4);
        float* row0 = st + (iy * 8) * 256;
        row0[0 * 256 + cs] = u0.x;
        row0[1 * 256 + cs] = u0.y;
        row0[2 * 256 + cs] = u0.z;
        row0[3 * 256 + cs] = u0.w;
        row0[4 * 256 + cs] = u1.x;
        row0[5 * 256 + cs] = u1.y;
        row0[6 * 256 + cs] = u1.z;
        row0[7 * 256 + cs] = u1.w;
    }
    __syncthreads();

    const int w = tid >> 5, lane = tid & 31;
#pragma unroll
    for (int r = 0; r < 8; r++) {
        const int t = w * 8 + r;
        const int xr = ((t >> 3) & 7) * 4;
        const float* row = st + t * 256;
        float4 v0 = *(const float4*)&row[(4 * lane) ^ xr];
        float4 v1 = *(const float4*)&row[(128 + 4 * lane) ^ xr];

        float s = v0.x + v0.y + v0.z + v0.w + v1.x + v1.y + v1.z + v1.w;
#pragma unroll
        for (int o = 16; o; o >>= 1) s += __shfl_xor_sync(0xFFFFFFFFu, s, o);
        const float mu = s * (1.0f / 256.0f);

        float q = (v0.x - mu) * (v0.x - mu) + (v0.y - mu) * (v0.y - mu)
                + (v0.z - mu) * (v0.z - mu) + (v0.w - mu) * (v0.w - mu)
                + (v1.x - mu) * (v1.x - mu) + (v1.y - mu) * (v1.y - mu)
                + (v1.z - mu) * (v1.z - mu) + (v1.w - mu) * (v1.w - mu);
#pragma unroll
        for (int o = 16; o; o >>= 1) q += __shfl_xor_sync(0xFFFFFFFFu, q, o);
        const float rinv = rsqrtf(q * (1.0f / 256.0f) + 1e-5f);

        const long long grow = (long long)n * 64 + t;
        *(float4*)&tok[grow * CDIM + 4 * lane] = v0;
        *(float4*)&tok[grow * CDIM + 128 + 4 * lane] = v1;

        float4 g0 = *(const float4*)&g[4 * lane];
        float4 g1 = *(const float4*)&g[128 + 4 * lane];
        float4 b0 = *(const float4*)&b[4 * lane];
        float4 b1 = *(const float4*)&b[128 + 4 * lane];
        __half* yrow = yh + grow * CDIM;
        *(__half2*)&yrow[4 * lane] = __floats2half2_rn((v0.x - mu) * rinv * g0.x + b0.x,
                                                       (v0.y - mu) * rinv * g0.y + b0.y);
        *(__half2*)&yrow[4 * lane + 2] = __floats2half2_rn((v0.z - mu) * rinv * g0.z + b0.z,
                                                           (v0.w - mu) * rinv * g0.w + b0.w);
        *(__half2*)&yrow[128 + 4 * lane] = __floats2half2_rn((v1.x - mu) * rinv * g1.x + b1.x,
                                                             (v1.y - mu) * rinv * g1.y + b1.y);
        *(__half2*)&yrow[128 + 4 * lane + 2] = __floats2half2_rn((v1.z - mu) * rinv * g1.z + b1.z,
                                                                 (v1.w - mu) * rinv * g1.w + b1.w);
    }
}

// ===========================================================================
// Tensor-core window attention. 2 CTAs per window (4 heads each), 256 thr.
// V staging FIXED: 4096 half2 (was 2048 — heads 2,3 were garbage).
// ===========================================================================
#define SQK2 264
#define SVT2 70
#define SVT2_H 2240
#define ATTN_SMEM ((64 * SQK2 + 4 * SVT2_H) * 2)

__global__ void __launch_bounds__(256) attn_mma(const __half* __restrict__ qkv,
                                                __half* __restrict__ o) {
    extern __shared__ __half sm_h[];
    __half* sqk = sm_h;                   // [64][264]
    __half* svt = sm_h + 64 * SQK2;       // [4][32][70]

    const int tid = threadIdx.x;
    const int n = blockIdx.x >> 1;
    const int hg = blockIdx.x & 1;
    const int cb = hg * 128;
    const long long gbase = (long long)n * 64 * 768;

    // stage q,k for this head group: 2048 uint4 segs
#pragma unroll
    for (int i = 0; i < 8; i++) {
        const int s = tid + 256 * i;
        const int t = s >> 5;
        const int j = s & 31;
        const int srccol = cb + j * 8 + (j >= 16 ? 128 : 0);
        *(uint4*)&sqk[t * SQK2 + j * 8] = *(const uint4*)&qkv[gbase + t * 768 + srccol];
    }
    // stage v transposed: 64 tokens x 128 halves = 4096 half2
#pragma unroll
    for (int i = 0; i < 16; i++) {
        const int p = tid + 256 * i;
        const int t = p >> 6;
        const int d0 = (p & 63) * 2;
        __half2 v = *(const __half2*)&qkv[gbase + t * 768 + 512 + cb + d0];
        const int hl = d0 >> 5, dh = d0 & 31;
        svt[hl * SVT2_H + dh * SVT2 + t] = __low2half(v);
        svt[hl * SVT2_H + (dh + 1) * SVT2 + t] = __high2half(v);
    }
    __syncthreads();

    const int w = tid >> 5, lane = tid & 31;
    const int hl = w >> 1, rh = w & 1;
    const int lm = lane >> 2, lk = lane & 3;

    const __half* qb = sqk + hl * 32 + 2 * lk;
    const __half* kb = sqk + 128 + hl * 32 + 2 * lk;

    float acc[2][8][4];
#pragma unroll
    for (int i = 0; i < 2; i++)
#pragma unroll
        for (int j = 0; j < 8; j++)
#pragma unroll
            for (int q = 0; q < 4; q++) acc[i][j][q] = 0.0f;

#pragma unroll
    for (int kt = 0; kt < 2; kt++) {
        uint32_t a[2][4];
#pragma unroll
        for (int mt = 0; mt < 2; mt++) {
            const int r0 = rh * 32 + mt * 16 + lm;
            const __half* q0 = qb + kt * 16;
            a[mt][0] = *(const uint32_t*)&q0[r0 * SQK2];
            a[mt][1] = *(const uint32_t*)&q0[(r0 + 8) * SQK2];
            a[mt][2] = *(const uint32_t*)&q0[r0 * SQK2 + 8];
            a[mt][3] = *(const uint32_t*)&q0[(r0 + 8) * SQK2 + 8];
        }
#pragma unroll
        for (int nt = 0; nt < 8; nt++) {
            const int kr = nt * 8 + lm;
            const __half* k0 = kb + kt * 16;
            uint32_t b0 = *(const uint32_t*)&k0[kr * SQK2];
            uint32_t b1 = *(const uint32_t*)&k0[kr * SQK2 + 8];
#pragma unroll
            for (int mt = 0; mt < 2; mt++)
                MMA_H(acc[mt][nt], a[mt][0], a[mt][1], a[mt][2], a[mt][3], b0, b1);
        }
    }

    const float cs = 0.17677669529663689f * 1.4426950408889634f;
    float rs[2][2];
#pragma unroll
    for (int mt = 0; mt < 2; mt++) {
        float m0 = -1e30f, m1 = -1e30f;
#pragma unroll
        for (int nt = 0; nt < 8; nt++) {
            m0 = fmaxf(m0, fmaxf(acc[mt][nt][0], acc[mt][nt][1]));
            m1 = fmaxf(m1, fmaxf(acc[mt][nt][2], acc[mt][nt][3]));
        }
        m0 = fmaxf(m0, __shfl_xor_sync(0xFFFFFFFFu, m0, 1));
        m0 = fmaxf(m0, __shfl_xor_sync(0xFFFFFFFFu, m0, 2));
        m1 = fmaxf(m1, __shfl_xor_sync(0xFFFFFFFFu, m1, 1));
        m1 = fmaxf(m1, __shfl_xor_sync(0xFFFFFFFFu, m1, 2));
        float s0 = 0.0f, s1 = 0.0f;
#pragma unroll
        for (int nt = 0; nt < 8; nt++) {
            float e0 = exp2f((acc[mt][nt][0] - m0) * cs);
            float e1 = exp2f((acc[mt][nt][1] - m0) * cs);
            float e2 = exp2f((acc[mt][nt][2] - m1) * cs);
            float e3 = exp2f((acc[mt][nt][3] - m1) * cs);
            acc[mt][nt][0] = e0; acc[mt][nt][1] = e1;
            acc[mt][nt][2] = e2; acc[mt][nt][3] = e3;
            s0 += e0 + e1; s1 += e2 + e3;
        }
        s0 += __shfl_xor_sync(0xFFFFFFFFu, s0, 1);
        s0 += __shfl_xor_sync(0xFFFFFFFFu, s0, 2);
        s1 += __shfl_xor_sync(0xFFFFFFFFu, s1, 1);
        s1 += __shfl_xor_sync(0xFFFFFFFFu, s1, 2);
        rs[mt][0] = 1.0f / s0;
        rs[mt][1] = 1.0f / s1;
    }

    float oacc[2][4][4];
#pragma unroll
    for (int i = 0; i < 2; i++)
#pragma unroll
        for (int j = 0; j < 4; j++)
#pragma unroll
            for (int q = 0; q < 4; q++) oacc[i][j][q] = 0.0f;

    const __half* vb0 = svt + hl * SVT2_H + 2 * lk;
#pragma unroll
    for (int kt4 = 0; kt4 < 4; kt4++) {
        uint32_t pa[2][4];
#pragma unroll
        for (int mt = 0; mt < 2; mt++) {
            pa[mt][0] = h2_u32(__floats2half2_rn(acc[mt][2 * kt4][0], acc[mt][2 * kt4][1]));
            pa[mt][1] = h2_u32(__floats2half2_rn(acc[mt][2 * kt4][2], acc[mt][2 * kt4][3]));
            pa[mt][2] = h2_u32(__floats2half2_rn(acc[mt][2 * kt4 + 1][0], acc[mt][2 * kt4 + 1][1]));
            pa[mt][3] = h2_u32(__floats2half2_rn(acc[mt][2 * kt4 + 1][2], acc[mt][2 * kt4 + 1][3]));
        }
#pragma unroll
        for (int dn = 0; dn < 4; dn++) {
            const __half* vb = vb0 + (dn * 8 + lm) * SVT2 + kt4 * 16;
            uint32_t b0 = *(const uint32_t*)&vb[0];
            uint32_t b1 = *(const uint32_t*)&vb[8];
#pragma unroll
            for (int mt = 0; mt < 2; mt++)
                MMA_H(oacc[mt][dn], pa[mt][0], pa[mt][1], pa[mt][2], pa[mt][3], b0, b1);
        }
    }

#pragma unroll
    for (int mt = 0; mt < 2; mt++) {
        const int r0 = rh * 32 + mt * 16 + lm;
#pragma unroll
        for (int dn = 0; dn < 4; dn++) {
            const int col = (hg * 4 + hl) * 32 + dn * 8 + 2 * lk;
            __half* o0 = o + ((long long)n * 64 + r0) * CDIM + col;
            __half* o1 = o + ((long long)n * 64 + r0 + 8) * CDIM + col;
            *(__half2*)o0 = __floats2half2_rn(oacc[mt][dn][0] * rs[mt][0],
                                              oacc[mt][dn][1] * rs[mt][0]);
            *(__half2*)o1 = __floats2half2_rn(oacc[mt][dn][2] * rs[mt][1],
                                              oacc[mt][dn][3] * rs[mt][1]);
        }
    }
}

// ===========================================================================
// Launch
// ===========================================================================
extern "C" void kernel_launch(void* const* d_in, const int* in_sizes, int n_in,
                              void* d_out, int out_size) {
    const float* x      = (const float*)d_in[0];
    const float* qkv_w  = (const float*)d_in[1];
    const float* qkv_b  = (const float*)d_in[2];
    const float* proj_w = (const float*)d_in[3];
    const float* proj_b = (const float*)d_in[4];
    const float* n1_g   = (const float*)d_in[5];
    const float* n1_b   = (const float*)d_in[6];
    const float* n2_g   = (const float*)d_in[7];
    const float* n2_b   = (const float*)d_in[8];
    const float* fc1_w  = (const float*)d_in[9];
    const float* fc1_b  = (const float*)d_in[10];
    const float* fc2_w  = (const float*)d_in[11];
    const float* fc2_b  = (const float*)d_in[12];
    float* out = (float*)d_out;

    float *tok;
    __half *yh, *qkvh, *oh, *hidh, *wh;
    cudaGetSymbolAddress((void**)&tok, g_tok);
    cudaGetSymbolAddress((void**)&yh, g_yh);
    cudaGetSymbolAddress((void**)&qkvh, g_qkvh);
    cudaGetSymbolAddress((void**)&oh, g_oh);
    cudaGetSymbolAddress((void**)&hidh, g_hidh);
    cudaGetSymbolAddress((void**)&wh, g_wh);

    cudaFuncSetAttribute(attn_mma, cudaFuncAttributeMaxDynamicSharedMemorySize, ATTN_SMEM);
    const int GLN_SMEM = 64 * 256 * 4;
    cudaFuncSetAttribute(gather_ln, cudaFuncAttributeMaxDynamicSharedMemorySize, GLN_SMEM);
    const int GEMM_SMEM = 98304;
    cudaFuncSetAttribute(mma_gemm_h<0>, cudaFuncAttributeMaxDynamicSharedMemorySize, GEMM_SMEM);
    cudaFuncSetAttribute(mma_gemm_h<2>, cudaFuncAttributeMaxDynamicSharedMemorySize, GEMM_SMEM);
    cudaFuncSetAttribute(mma_gemm_h<3>, cudaFuncAttributeMaxDynamicSharedMemorySize, GEMM_SMEM);
    cudaFuncSetAttribute(proj_ln, cudaFuncAttributeMaxDynamicSharedMemorySize, PROJ_SMEM);

    const int MT = NTOK / 128;  // 2048 M-tiles

    // 0. weights -> fp16
    cvt_weights<<<512, 256>>>(qkv_w, proj_w, fc1_w, fc2_w);
    // 1+2. window partition + LN1 (fused)
    gather_ln<<<4096, 256, GLN_SMEM>>>(x, n1_g, n1_b, tok, yh);
    // 3. QKV gemm
    mma_gemm_h<0><<<dim3(6, MT), 256, GEMM_SMEM>>>(yh, wh + WOFF_QKV, qkv_b, nullptr, qkvh, 768, 256);
    // 4. windowed attention (2 CTAs/window)
    attn_mma<<<8192, 256, ATTN_SMEM>>>(qkvh, oh);
    // 5+6. proj gemm + residual + LN2 (fused)
    proj_ln<<<MT, 512, PROJ_SMEM>>>(oh, wh + WOFF_PROJ, proj_b, tok, n2_g, n2_b, yh);
    // 7. fc1 gemm + GELU
    mma_gemm_h<2><<<dim3(8, MT), 256, GEMM_SMEM>>>(yh, wh + WOFF_FC1, fc1_b, nullptr, hidh, 1024, 256);
    // 8. fc2 gemm + residual + scatter -> out
    mma_gemm_h<3><<<dim3(2, MT), 256, GEMM_SMEM>>>(hidh, wh + WOFF_FC2, fc2_b, tok, out, 256, 1024);
}